// round 10
// baseline (speedup 1.0000x reference)
#include <cuda_runtime.h>
#include <cstdint>
#include <math.h>

// Problem constants
#define NTOK 8192
#define CDIM 1024
#define HDIM 4096
#define EXPN 8
#define KSEL 2
#define CAPN 2048
#define NFLAT (NTOK*KSEL)

// GEMM tiling: CTA 128x128, BK=32, 256 threads, warp tile 64x32 (2x4 warps)
#define BK2 32
#define RP 36                 // floats per smem row (32 + 4 pad; 144B, 16B-aligned)
#define NST 3                 // cp.async stages
#define TILEF (128*RP)        // floats per tile

// ---------------- scratch ----------------------------------------------------
__device__ float g_xh[(size_t)NTOK * CDIM];
__device__ float g_xl[(size_t)NTOK * CDIM];
__device__ float g_h1h[(size_t)NTOK * HDIM];
__device__ float g_h1l[(size_t)NTOK * HDIM];
__device__ float g_h2[(size_t)NTOK * HDIM];
__device__ int   g_eid[NFLAT];
__device__ float g_prob[NFLAT];
__device__ int   g_pos[NFLAT];
__device__ float g_disp[(size_t)EXPN * CAPN * CDIM];
__device__ float g_eh[(size_t)EXPN * CAPN * HDIM];
__device__ float g_eo[(size_t)EXPN * CAPN * CDIM];
__device__ float g_rw1th[(size_t)HDIM * CDIM];
__device__ float g_rw1tl[(size_t)HDIM * CDIM];
__device__ float g_rw2th[(size_t)HDIM * HDIM];
__device__ float g_rw2tl[(size_t)HDIM * HDIM];
__device__ float g_ew1t[(size_t)EXPN * HDIM * CDIM];
__device__ float g_ew2t[(size_t)EXPN * CDIM * HDIM];

// ---------------- helpers ------------------------------------------------
__device__ __forceinline__ uint32_t f2tf32_rna(float x) {
    uint32_t u;
    asm("cvt.rna.tf32.f32 %0, %1;" : "=r"(u) : "f"(x));
    return u;
}
__device__ __forceinline__ uint32_t smem_u32(const void* p) {
    uint32_t a;
    asm("{ .reg .u64 t; cvta.to.shared.u64 t, %1; cvt.u32.u64 %0, t; }" : "=r"(a) : "l"(p));
    return a;
}
__device__ __forceinline__ void cp16(uint32_t s, const float* g) {
    asm volatile("cp.async.cg.shared.global [%0], [%1], 16;" :: "r"(s), "l"(g));
}
__device__ __forceinline__ void cp_commit() {
    asm volatile("cp.async.commit_group;" ::: "memory");
}
template <int N> __device__ __forceinline__ void cp_wait() {
    asm volatile("cp.async.wait_group %0;" :: "n"(N) : "memory");
}

#define MMA_TF32(d, a, b) \
    asm volatile( \
        "mma.sync.aligned.m16n8k8.row.col.f32.tf32.tf32.f32 " \
        "{%0,%1,%2,%3}, {%4,%5,%6,%7}, {%8,%9}, {%0,%1,%2,%3};" \
        : "+f"((d)[0]), "+f"((d)[1]), "+f"((d)[2]), "+f"((d)[3]) \
        : "r"((a)[0]), "r"((a)[1]), "r"((a)[2]), "r"((a)[3]), \
          "r"((b)[0]), "r"((b)[1]))

// ---------------- TF32 mma.sync GEMM (pre-converted operands) ----------------
// Ah/Al: [M,K] row-major (Al used iff PASS3). Bh/Bl: [N,K] row-major.
// C = op(A@B^T + bias). WMODE: 0 plain fp32, 1 write (hi,lo) split, 2 write rna.
template <int PASS3, int RELU, int WMODE>
__global__ __launch_bounds__(256, 1)
void mma_gemm(const float* __restrict__ Ah, const float* __restrict__ Al,
              const float* __restrict__ Bh, const float* __restrict__ Bl,
              const float* __restrict__ bias, float* __restrict__ C,
              float* __restrict__ Cl,
              int Kd, int Nn,
              long long aB, long long bB, long long biasB, long long cB)
{
    extern __shared__ float sm[];
    constexpr int AHo = 0;
    constexpr int BHo = TILEF;
    constexpr int ALo = 2 * TILEF;
    constexpr int BLo = 3 * TILEF;
    constexpr int STG = (PASS3 ? 4 : 2) * TILEF;

    const int tid = threadIdx.x;
    const int z = blockIdx.z;
    Ah += (size_t)z * aB;
    Bh += (size_t)z * bB;
    if (PASS3) { Al += (size_t)z * aB; Bl += (size_t)z * bB; }
    bias += (size_t)z * biasB;
    C    += (size_t)z * cB;
    if (WMODE == 1) Cl += (size_t)z * cB;
    const int m0 = blockIdx.y * 128;
    const int n0 = blockIdx.x * 128;

    const int warp = tid >> 5;
    const int lane = tid & 31;
    const int wm = warp >> 2;
    const int wn = warp & 3;
    const int g4 = lane >> 2;
    const int t4 = lane & 3;

    const uint32_t smb = smem_u32(sm);
    const int nk = Kd / BK2;

    // loader mapping: 4 chunks of 16B per tile per thread
    int lrow[4], lc4[4];
#pragma unroll
    for (int t = 0; t < 4; t++) {
        int id = tid + 256 * t;
        lrow[t] = id >> 3;
        lc4[t] = (id & 7) * 4;
    }

    auto ISSUE = [&](int s) {
        const int buf = s % NST;
        const uint32_t sb = smb + (uint32_t)buf * STG * 4;
        const size_t ko = (size_t)s * BK2;
#pragma unroll
        for (int t = 0; t < 4; t++) {
            const size_t go = (size_t)lrow[t] * Kd + ko + lc4[t];
            const uint32_t so = (uint32_t)(lrow[t] * RP + lc4[t]) * 4;
            cp16(sb + AHo * 4 + so, Ah + (size_t)m0 * Kd + go);
            cp16(sb + BHo * 4 + so, Bh + (size_t)n0 * Kd + go);
            if (PASS3) {
                cp16(sb + ALo * 4 + so, Al + (size_t)m0 * Kd + go);
                cp16(sb + BLo * 4 + so, Bl + (size_t)n0 * Kd + go);
            }
        }
    };

    float d[4][4][4];
#pragma unroll
    for (int i = 0; i < 4; i++)
#pragma unroll
        for (int j = 0; j < 4; j++)
#pragma unroll
            for (int q = 0; q < 4; q++) d[i][j][q] = 0.f;

    // prologue: 2 stages in flight
    ISSUE(0); cp_commit();
    if (nk > 1) ISSUE(1);
    cp_commit();

    for (int s = 0; s < nk; s++) {
        cp_wait<NST - 2>();
        __syncthreads();
        if (s + NST - 1 < nk) ISSUE(s + NST - 1);
        cp_commit();

        const float* sb = sm + (s % NST) * STG;
#pragma unroll
        for (int kk = 0; kk < 4; kk++) {
            const int cA = kk * 8 + t4;
            uint32_t ah[4][4], bh[4][2];
#pragma unroll
            for (int i = 0; i < 4; i++) {
                int ro = (wm * 64 + i * 16 + g4) * RP + cA;
                ah[i][0] = __float_as_uint(sb[AHo + ro]);
                ah[i][1] = __float_as_uint(sb[AHo + ro + 8 * RP]);
                ah[i][2] = __float_as_uint(sb[AHo + ro + 4]);
                ah[i][3] = __float_as_uint(sb[AHo + ro + 8 * RP + 4]);
            }
#pragma unroll
            for (int j = 0; j < 4; j++) {
                int no = (wn * 32 + j * 8 + g4) * RP + cA;
                bh[j][0] = __float_as_uint(sb[BHo + no]);
                bh[j][1] = __float_as_uint(sb[BHo + no + 4]);
            }
#pragma unroll
            for (int i = 0; i < 4; i++)
#pragma unroll
                for (int j = 0; j < 4; j++) MMA_TF32(d[i][j], ah[i], bh[j]);

            if (PASS3) {
                uint32_t al[4][4], bl[4][2];
#pragma unroll
                for (int i = 0; i < 4; i++) {
                    int ro = (wm * 64 + i * 16 + g4) * RP + cA;
                    al[i][0] = __float_as_uint(sb[ALo + ro]);
                    al[i][1] = __float_as_uint(sb[ALo + ro + 8 * RP]);
                    al[i][2] = __float_as_uint(sb[ALo + ro + 4]);
                    al[i][3] = __float_as_uint(sb[ALo + ro + 8 * RP + 4]);
                }
#pragma unroll
                for (int j = 0; j < 4; j++) {
                    int no = (wn * 32 + j * 8 + g4) * RP + cA;
                    bl[j][0] = __float_as_uint(sb[BLo + no]);
                    bl[j][1] = __float_as_uint(sb[BLo + no + 4]);
                }
#pragma unroll
                for (int i = 0; i < 4; i++)
#pragma unroll
                    for (int j = 0; j < 4; j++) {
                        MMA_TF32(d[i][j], ah[i], bl[j]);
                        MMA_TF32(d[i][j], al[i], bh[j]);
                    }
            }
        }
    }

    // epilogue
#pragma unroll
    for (int i = 0; i < 4; i++) {
        int r0 = m0 + wm * 64 + i * 16 + g4;
#pragma unroll
        for (int j = 0; j < 4; j++) {
            int col = n0 + wn * 32 + j * 8 + t4 * 2;
            float2 bv = *(const float2*)(bias + col);
            float vv[4];
            vv[0] = d[i][j][0] + bv.x; vv[1] = d[i][j][1] + bv.y;
            vv[2] = d[i][j][2] + bv.x; vv[3] = d[i][j][3] + bv.y;
            if (RELU) {
#pragma unroll
                for (int q = 0; q < 4; q++) vv[q] = fmaxf(vv[q], 0.f);
            }
            size_t o0 = (size_t)r0 * Nn + col;
            size_t o1 = (size_t)(r0 + 8) * Nn + col;
            if (WMODE == 0) {
                *(float2*)(C + o0) = make_float2(vv[0], vv[1]);
                *(float2*)(C + o1) = make_float2(vv[2], vv[3]);
            } else if (WMODE == 2) {
                float2 h0, h1;
                h0.x = __uint_as_float(f2tf32_rna(vv[0]));
                h0.y = __uint_as_float(f2tf32_rna(vv[1]));
                h1.x = __uint_as_float(f2tf32_rna(vv[2]));
                h1.y = __uint_as_float(f2tf32_rna(vv[3]));
                *(float2*)(C + o0) = h0;
                *(float2*)(C + o1) = h1;
            } else {
                float2 h0, h1, l0, l1;
                h0.x = __uint_as_float(f2tf32_rna(vv[0]));
                h0.y = __uint_as_float(f2tf32_rna(vv[1]));
                h1.x = __uint_as_float(f2tf32_rna(vv[2]));
                h1.y = __uint_as_float(f2tf32_rna(vv[3]));
                l0.x = vv[0] - h0.x; l0.y = vv[1] - h0.y;
                l1.x = vv[2] - h1.x; l1.y = vv[3] - h1.y;
                *(float2*)(C + o0)  = h0;
                *(float2*)(C + o1)  = h1;
                *(float2*)(Cl + o0) = l0;
                *(float2*)(Cl + o1) = l1;
            }
        }
    }
}

// ---------------- elementwise split: x -> (rna(x), x - rna(x)) ---------------
__global__ __launch_bounds__(256) void split_kernel(
    const float* __restrict__ src, float* __restrict__ dh, float* __restrict__ dl,
    int n4)
{
    int i = blockIdx.x * blockDim.x + threadIdx.x;
    if (i >= n4) return;
    float4 v = ((const float4*)src)[i];
    float4 h, l;
    h.x = __uint_as_float(f2tf32_rna(v.x)); l.x = v.x - h.x;
    h.y = __uint_as_float(f2tf32_rna(v.y)); l.y = v.y - h.y;
    h.z = __uint_as_float(f2tf32_rna(v.z)); l.z = v.z - h.z;
    h.w = __uint_as_float(f2tf32_rna(v.w)); l.w = v.w - h.w;
    ((float4*)dh)[i] = h;
    ((float4*)dl)[i] = l;
}

// ------------- weight transpose W[R,Cc]->Wt[Cc,R], MODE: 0 split, 1 rna ------
template <int MODE>
__global__ __launch_bounds__(256) void transpose_kernel(
    const float* __restrict__ src, float* __restrict__ dh, float* __restrict__ dl,
    int R, int Cc)
{
    __shared__ float tile[32][33];
    size_t off = (size_t)blockIdx.z * R * Cc;
    int c0 = blockIdx.x * 32, r0 = blockIdx.y * 32;
    int tx = threadIdx.x, ty = threadIdx.y;   // 32 x 8
#pragma unroll
    for (int i = 0; i < 4; i++)
        tile[ty + i * 8][tx] = src[off + (size_t)(r0 + ty + i * 8) * Cc + c0 + tx];
    __syncthreads();
#pragma unroll
    for (int i = 0; i < 4; i++) {
        float v = tile[tx][ty + i * 8];
        float h = __uint_as_float(f2tf32_rna(v));
        size_t o = off + (size_t)(c0 + ty + i * 8) * R + r0 + tx;
        dh[o] = h;
        if (MODE == 0) dl[o] = v - h;
    }
}

// ---------------- router head ------------------------------------------------
__global__ __launch_bounds__(256) void router_topk_kernel(
    const float* __restrict__ h2, const float* __restrict__ rw3,
    const float* __restrict__ rb3, int* __restrict__ eid,
    float* __restrict__ prob)
{
    __shared__ __align__(16) float sh[HDIM];
    __shared__ float slog[EXPN];
    const int t = blockIdx.x;

    const float4* src = (const float4*)(h2 + (size_t)t * HDIM);
    float4* dst4 = (float4*)sh;
    for (int i = threadIdx.x; i < HDIM / 4; i += 256) dst4[i] = src[i];
    __syncthreads();

    const int w = threadIdx.x >> 5;
    const int lane = threadIdx.x & 31;
    if (w < EXPN) {
        float s = 0.f;
        for (int j = lane; j < HDIM; j += 32) s += sh[j] * rw3[(size_t)j * EXPN + w];
#pragma unroll
        for (int o = 16; o > 0; o >>= 1) s += __shfl_down_sync(0xffffffffu, s, o);
        if (lane == 0) slog[w] = s + rb3[w];
    }
    __syncthreads();

    if (threadIdx.x == 0) {
        float l[EXPN], p[EXPN];
        float mx = -1e30f;
#pragma unroll
        for (int e = 0; e < EXPN; e++) { l[e] = slog[e]; mx = fmaxf(mx, l[e]); }
        float se = 0.f;
#pragma unroll
        for (int e = 0; e < EXPN; e++) { p[e] = expf(l[e] - mx); se += p[e]; }
        float inv = 1.f / se;
#pragma unroll
        for (int e = 0; e < EXPN; e++) p[e] *= inv;
        int b1 = 0;
#pragma unroll
        for (int e = 1; e < EXPN; e++) if (p[e] > p[b1]) b1 = e;
        int b2 = (b1 == 0) ? 1 : 0;
#pragma unroll
        for (int e = 0; e < EXPN; e++)
            if (e != b1 && p[e] > p[b2]) b2 = e;
        eid[t * 2 + 0] = b1; prob[t * 2 + 0] = p[b1];
        eid[t * 2 + 1] = b2; prob[t * 2 + 1] = p[b2];
    }
}

// ---- exact flattened-order per-expert ranks ---------------------------------
__global__ __launch_bounds__(1024) void positions_kernel(
    const int* __restrict__ eid, int* __restrict__ pos)
{
    __shared__ int base[EXPN];
    __shared__ int wcnt[32][EXPN];
    const int tid = threadIdx.x;
    const int lane = tid & 31;
    const int w = tid >> 5;

    if (tid < EXPN) base[tid] = 0;
    __syncthreads();

    for (int c = 0; c < NFLAT; c += 1024) {
        if (tid < 32 * EXPN) ((int*)wcnt)[tid] = 0;
        __syncthreads();

        int e = eid[c + tid];
        unsigned m = __match_any_sync(0xffffffffu, e);
        int rank = __popc(m & ((1u << lane) - 1u));
        int leader = __ffs(m) - 1;
        if (lane == leader) wcnt[w][e] = __popc(m);
        __syncthreads();

        int off = base[e] + rank;
        for (int w2 = 0; w2 < 32; w2++)
            if (w2 < w) off += wcnt[w2][e];
        pos[c + tid] = off;
        __syncthreads();

        if (tid < EXPN) {
            int s = 0;
#pragma unroll
            for (int w2 = 0; w2 < 32; w2++) s += wcnt[w2][tid];
            base[tid] += s;
        }
        __syncthreads();
    }
}

__global__ void zero_kernel(float4* __restrict__ p, int n4)
{
    int i = blockIdx.x * blockDim.x + threadIdx.x;
    if (i < n4) p[i] = make_float4(0.f, 0.f, 0.f, 0.f);
}

// dispatch: scatter rna(x) rows into expert buffers
__global__ __launch_bounds__(256) void dispatch_kernel(
    const float* __restrict__ x, const int* __restrict__ eid,
    const int* __restrict__ pos, float* __restrict__ disp)
{
    const int i = blockIdx.x;
    const int p = pos[i];
    if (p >= CAPN) return;
    const int e = eid[i];
    const int token = i >> 1;
    const float4* src = (const float4*)(x + (size_t)token * CDIM);
    float4* dst = (float4*)(disp + ((size_t)e * CAPN + p) * CDIM);
    float4 v = src[threadIdx.x];
    v.x = __uint_as_float(f2tf32_rna(v.x));
    v.y = __uint_as_float(f2tf32_rna(v.y));
    v.z = __uint_as_float(f2tf32_rna(v.z));
    v.w = __uint_as_float(f2tf32_rna(v.w));
    dst[threadIdx.x] = v;
}

__global__ __launch_bounds__(256) void combine_kernel(
    const float* __restrict__ eo, const int* __restrict__ eid,
    const float* __restrict__ prob, const int* __restrict__ pos,
    float* __restrict__ out)
{
    const int t = blockIdx.x;
    const int e1 = eid[t * 2 + 0], e2 = eid[t * 2 + 1];
    const int p1 = pos[t * 2 + 0], p2 = pos[t * 2 + 1];
    const float w1 = prob[t * 2 + 0] * (p1 < CAPN ? 1.f : 0.f);
    const float w2 = prob[t * 2 + 1] * (p2 < CAPN ? 1.f : 0.f);
    const int g1 = min(p1, CAPN - 1), g2 = min(p2, CAPN - 1);

    const float4* r1 = (const float4*)(eo + ((size_t)e1 * CAPN + g1) * CDIM);
    const float4* r2 = (const float4*)(eo + ((size_t)e2 * CAPN + g2) * CDIM);
    float4 a = r1[threadIdx.x];
    float4 b = r2[threadIdx.x];
    float4 v;
    v.x = w1 * a.x + w2 * b.x;
    v.y = w1 * a.y + w2 * b.y;
    v.z = w1 * a.z + w2 * b.z;
    v.w = w1 * a.w + w2 * b.w;
    ((float4*)(out + (size_t)t * CDIM))[threadIdx.x] = v;
}

// ---------------- launch -----------------------------------------------------
extern "C" void kernel_launch(void* const* d_in, const int* in_sizes, int n_in,
                              void* d_out, int out_size)
{
    const float* x   = (const float*)d_in[0];
    const float* rw1 = (const float*)d_in[1];
    const float* rb1 = (const float*)d_in[2];
    const float* rw2 = (const float*)d_in[3];
    const float* rb2 = (const float*)d_in[4];
    const float* rw3 = (const float*)d_in[5];
    const float* rb3 = (const float*)d_in[6];
    const float* ew1 = (const float*)d_in[7];
    const float* eb1 = (const float*)d_in[8];
    const float* ew2 = (const float*)d_in[9];
    const float* eb2 = (const float*)d_in[10];
    float* out = (float*)d_out;
    (void)in_sizes; (void)n_in; (void)out_size;

    float *xh, *xl, *h1h, *h1l, *h2, *disp, *eh, *eo, *prob;
    float *rw1th, *rw1tl, *rw2th, *rw2tl, *ew1t, *ew2t;
    int *eid, *pos;
    cudaGetSymbolAddress((void**)&xh,    g_xh);
    cudaGetSymbolAddress((void**)&xl,    g_xl);
    cudaGetSymbolAddress((void**)&h1h,   g_h1h);
    cudaGetSymbolAddress((void**)&h1l,   g_h1l);
    cudaGetSymbolAddress((void**)&h2,    g_h2);
    cudaGetSymbolAddress((void**)&disp,  g_disp);
    cudaGetSymbolAddress((void**)&eh,    g_eh);
    cudaGetSymbolAddress((void**)&eo,    g_eo);
    cudaGetSymbolAddress((void**)&eid,   g_eid);
    cudaGetSymbolAddress((void**)&prob,  g_prob);
    cudaGetSymbolAddress((void**)&pos,   g_pos);
    cudaGetSymbolAddress((void**)&rw1th, g_rw1th);
    cudaGetSymbolAddress((void**)&rw1tl, g_rw1tl);
    cudaGetSymbolAddress((void**)&rw2th, g_rw2th);
    cudaGetSymbolAddress((void**)&rw2tl, g_rw2tl);
    cudaGetSymbolAddress((void**)&ew1t,  g_ew1t);
    cudaGetSymbolAddress((void**)&ew2t,  g_ew2t);

    const int DS3 = 4 * TILEF * NST * 4;   // 3-pass: AH,BH,AL,BL per stage
    const int DS1 = 2 * TILEF * NST * 4;   // 1-pass: AH,BH per stage
    cudaFuncSetAttribute(mma_gemm<1,1,1>, cudaFuncAttributeMaxDynamicSharedMemorySize, DS3);
    cudaFuncSetAttribute(mma_gemm<1,1,0>, cudaFuncAttributeMaxDynamicSharedMemorySize, DS3);
    cudaFuncSetAttribute(mma_gemm<0,1,2>, cudaFuncAttributeMaxDynamicSharedMemorySize, DS1);
    cudaFuncSetAttribute(mma_gemm<0,0,0>, cudaFuncAttributeMaxDynamicSharedMemorySize, DS1);

    // operand preparation
    split_kernel<<<(NTOK * CDIM / 4 + 255) / 256, 256>>>(x, xh, xl, NTOK * CDIM / 4);
    transpose_kernel<0><<<dim3(HDIM/32, CDIM/32, 1), dim3(32, 8)>>>(rw1, rw1th, rw1tl, CDIM, HDIM);
    transpose_kernel<0><<<dim3(HDIM/32, HDIM/32, 1), dim3(32, 8)>>>(rw2, rw2th, rw2tl, HDIM, HDIM);
    transpose_kernel<1><<<dim3(HDIM/32, CDIM/32, EXPN), dim3(32, 8)>>>(ew1, ew1t, nullptr, CDIM, HDIM);
    transpose_kernel<1><<<dim3(CDIM/32, HDIM/32, EXPN), dim3(32, 8)>>>(ew2, ew2t, nullptr, HDIM, CDIM);

    // router MLP (3xTF32, fp32-exact class); GEMM1 writes h1 pre-split
    mma_gemm<1,1,1><<<dim3(HDIM/128, NTOK/128, 1), 256, DS3>>>(
        xh, xl, rw1th, rw1tl, rb1, h1h, h1l, CDIM, HDIM, 0, 0, 0, 0);
    mma_gemm<1,1,0><<<dim3(HDIM/128, NTOK/128, 1), 256, DS3>>>(
        h1h, h1l, rw2th, rw2tl, rb2, h2, nullptr, HDIM, HDIM, 0, 0, 0, 0);
    router_topk_kernel<<<NTOK, 256>>>(h2, rw3, rb3, eid, prob);
    positions_kernel<<<1, 1024>>>(eid, pos);

    // dispatch (pre-rna'd for expert GEMM1)
    {
        int n4 = (int)((size_t)EXPN * CAPN * CDIM / 4);
        zero_kernel<<<(n4 + 255) / 256, 256>>>((float4*)disp, n4);
    }
    dispatch_kernel<<<NFLAT, 256>>>(x, eid, pos, disp);

    // expert FFNs (1xTF32), batched over experts; GEMM1 writes eh pre-rna'd
    mma_gemm<0,1,2><<<dim3(HDIM/128, CAPN/128, EXPN), 256, DS1>>>(
        disp, nullptr, ew1t, nullptr, eb1, eh, nullptr, CDIM, HDIM,
        (long long)CAPN * CDIM, (long long)HDIM * CDIM, HDIM, (long long)CAPN * HDIM);
    mma_gemm<0,0,0><<<dim3(CDIM/128, CAPN/128, EXPN), 256, DS1>>>(
        eh, nullptr, ew2t, nullptr, eb2, eo, nullptr, HDIM, CDIM,
        (long long)CAPN * HDIM, (long long)CDIM * HDIM, CDIM, (long long)CAPN * CDIM);

    // combine
    combine_kernel<<<NTOK, 256>>>(eo, eid, prob, pos, out);
}

// round 11
// speedup vs baseline: 1.5252x; 1.5252x over previous
#include <cuda_runtime.h>
#include <cstdint>
#include <math.h>

// Problem constants
#define NTOK 8192
#define CDIM 1024
#define HDIM 4096
#define EXPN 8
#define KSEL 2
#define CAPN 2048
#define NFLAT (NTOK*KSEL)
#define RCAP 2048               // recheck batch capacity (rows)
#define MARGIN 0.008f           // logit-gap threshold for exact recheck

// GEMM tiling: CTA 128x128, BK=32, 256 threads, warp tile 64x32 (2x4 warps)
#define BK2 32
#define RP 36
#define NST 3
#define TILEF (128*RP)

// ---------------- scratch ----------------------------------------------------
__device__ float g_xh[(size_t)NTOK * CDIM];
__device__ float g_xl[(size_t)NTOK * CDIM];
__device__ float g_h1r[(size_t)NTOK * HDIM];          // rna(h1) for 1x router
__device__ float g_h2[(size_t)NTOK * HDIM];
__device__ int   g_eid[NFLAT];
__device__ float g_prob[NFLAT];
__device__ int   g_pos[NFLAT];
__device__ float g_disp[(size_t)EXPN * CAPN * CDIM];
__device__ float g_eh[(size_t)EXPN * CAPN * HDIM];
__device__ float g_eo[(size_t)EXPN * CAPN * CDIM];
__device__ float g_rw1th[(size_t)HDIM * CDIM];
__device__ float g_rw1tl[(size_t)HDIM * CDIM];
__device__ float g_rw2th[(size_t)HDIM * HDIM];
__device__ float g_rw2tl[(size_t)HDIM * HDIM];
__device__ float g_ew1t[(size_t)EXPN * HDIM * CDIM];
__device__ float g_ew2t[(size_t)EXPN * CDIM * HDIM];
// recheck scratch
__device__ int   g_list[RCAP];
__device__ int   g_cnt;
__device__ float g_gxh[(size_t)RCAP * CDIM];
__device__ float g_gxl[(size_t)RCAP * CDIM];
__device__ float g_grh1h[(size_t)RCAP * HDIM];
__device__ float g_grh1l[(size_t)RCAP * HDIM];
__device__ float g_grh2[(size_t)RCAP * HDIM];

// ---------------- helpers ------------------------------------------------
__device__ __forceinline__ uint32_t f2tf32_rna(float x) {
    uint32_t u;
    asm("cvt.rna.tf32.f32 %0, %1;" : "=r"(u) : "f"(x));
    return u;
}
__device__ __forceinline__ uint32_t smem_u32(const void* p) {
    uint32_t a;
    asm("{ .reg .u64 t; cvta.to.shared.u64 t, %1; cvt.u32.u64 %0, t; }" : "=r"(a) : "l"(p));
    return a;
}
__device__ __forceinline__ void cp16(uint32_t s, const float* g) {
    asm volatile("cp.async.cg.shared.global [%0], [%1], 16;" :: "r"(s), "l"(g));
}
__device__ __forceinline__ void cp_commit() {
    asm volatile("cp.async.commit_group;" ::: "memory");
}
template <int N> __device__ __forceinline__ void cp_wait() {
    asm volatile("cp.async.wait_group %0;" :: "n"(N) : "memory");
}

#define MMA_TF32(d, a, b) \
    asm volatile( \
        "mma.sync.aligned.m16n8k8.row.col.f32.tf32.tf32.f32 " \
        "{%0,%1,%2,%3}, {%4,%5,%6,%7}, {%8,%9}, {%0,%1,%2,%3};" \
        : "+f"((d)[0]), "+f"((d)[1]), "+f"((d)[2]), "+f"((d)[3]) \
        : "r"((a)[0]), "r"((a)[1]), "r"((a)[2]), "r"((a)[3]), \
          "r"((b)[0]), "r"((b)[1]))

// ---------------- TF32 mma.sync GEMM (pre-converted operands) ----------------
// mrows: optional device row count -> tiles with m0 >= *mrows exit early.
template <int PASS3, int RELU, int WMODE>
__global__ __launch_bounds__(256, 1)
void mma_gemm(const float* __restrict__ Ah, const float* __restrict__ Al,
              const float* __restrict__ Bh, const float* __restrict__ Bl,
              const float* __restrict__ bias, float* __restrict__ C,
              float* __restrict__ Cl, const int* __restrict__ mrows,
              int Kd, int Nn,
              long long aB, long long bB, long long biasB, long long cB)
{
    if (mrows && (int)(blockIdx.y * 128) >= *mrows) return;

    extern __shared__ float sm[];
    constexpr int AHo = 0;
    constexpr int BHo = TILEF;
    constexpr int ALo = 2 * TILEF;
    constexpr int BLo = 3 * TILEF;
    constexpr int STG = (PASS3 ? 4 : 2) * TILEF;

    const int tid = threadIdx.x;
    const int z = blockIdx.z;
    Ah += (size_t)z * aB;
    Bh += (size_t)z * bB;
    if (PASS3) { Al += (size_t)z * aB; Bl += (size_t)z * bB; }
    bias += (size_t)z * biasB;
    C    += (size_t)z * cB;
    if (WMODE == 1) Cl += (size_t)z * cB;
    const int m0 = blockIdx.y * 128;
    const int n0 = blockIdx.x * 128;

    const int warp = tid >> 5;
    const int lane = tid & 31;
    const int wm = warp >> 2;
    const int wn = warp & 3;
    const int g4 = lane >> 2;
    const int t4 = lane & 3;

    const uint32_t smb = smem_u32(sm);
    const int nk = Kd / BK2;

    int lrow[4], lc4[4];
#pragma unroll
    for (int t = 0; t < 4; t++) {
        int id = tid + 256 * t;
        lrow[t] = id >> 3;
        lc4[t] = (id & 7) * 4;
    }

    auto ISSUE = [&](int s) {
        const int buf = s % NST;
        const uint32_t sb = smb + (uint32_t)buf * STG * 4;
        const size_t ko = (size_t)s * BK2;
#pragma unroll
        for (int t = 0; t < 4; t++) {
            const size_t go = (size_t)lrow[t] * Kd + ko + lc4[t];
            const uint32_t so = (uint32_t)(lrow[t] * RP + lc4[t]) * 4;
            cp16(sb + AHo * 4 + so, Ah + (size_t)m0 * Kd + go);
            cp16(sb + BHo * 4 + so, Bh + (size_t)n0 * Kd + go);
            if (PASS3) {
                cp16(sb + ALo * 4 + so, Al + (size_t)m0 * Kd + go);
                cp16(sb + BLo * 4 + so, Bl + (size_t)n0 * Kd + go);
            }
        }
    };

    float d[4][4][4];
#pragma unroll
    for (int i = 0; i < 4; i++)
#pragma unroll
        for (int j = 0; j < 4; j++)
#pragma unroll
            for (int q = 0; q < 4; q++) d[i][j][q] = 0.f;

    ISSUE(0); cp_commit();
    if (nk > 1) ISSUE(1);
    cp_commit();

    for (int s = 0; s < nk; s++) {
        cp_wait<NST - 2>();
        __syncthreads();
        if (s + NST - 1 < nk) ISSUE(s + NST - 1);
        cp_commit();

        const float* sb = sm + (s % NST) * STG;
#pragma unroll
        for (int kk = 0; kk < 4; kk++) {
            const int cA = kk * 8 + t4;
            uint32_t ah[4][4], bh[4][2];
#pragma unroll
            for (int i = 0; i < 4; i++) {
                int ro = (wm * 64 + i * 16 + g4) * RP + cA;
                ah[i][0] = __float_as_uint(sb[AHo + ro]);
                ah[i][1] = __float_as_uint(sb[AHo + ro + 8 * RP]);
                ah[i][2] = __float_as_uint(sb[AHo + ro + 4]);
                ah[i][3] = __float_as_uint(sb[AHo + ro + 8 * RP + 4]);
            }
#pragma unroll
            for (int j = 0; j < 4; j++) {
                int no = (wn * 32 + j * 8 + g4) * RP + cA;
                bh[j][0] = __float_as_uint(sb[BHo + no]);
                bh[j][1] = __float_as_uint(sb[BHo + no + 4]);
            }
#pragma unroll
            for (int i = 0; i < 4; i++)
#pragma unroll
                for (int j = 0; j < 4; j++) MMA_TF32(d[i][j], ah[i], bh[j]);

            if (PASS3) {
                uint32_t al[4][4], bl[4][2];
#pragma unroll
                for (int i = 0; i < 4; i++) {
                    int ro = (wm * 64 + i * 16 + g4) * RP + cA;
                    al[i][0] = __float_as_uint(sb[ALo + ro]);
                    al[i][1] = __float_as_uint(sb[ALo + ro + 8 * RP]);
                    al[i][2] = __float_as_uint(sb[ALo + ro + 4]);
                    al[i][3] = __float_as_uint(sb[ALo + ro + 8 * RP + 4]);
                }
#pragma unroll
                for (int j = 0; j < 4; j++) {
                    int no = (wn * 32 + j * 8 + g4) * RP + cA;
                    bl[j][0] = __float_as_uint(sb[BLo + no]);
                    bl[j][1] = __float_as_uint(sb[BLo + no + 4]);
                }
#pragma unroll
                for (int i = 0; i < 4; i++)
#pragma unroll
                    for (int j = 0; j < 4; j++) {
                        MMA_TF32(d[i][j], ah[i], bl[j]);
                        MMA_TF32(d[i][j], al[i], bh[j]);
                    }
            }
        }
    }

    // epilogue
#pragma unroll
    for (int i = 0; i < 4; i++) {
        int r0 = m0 + wm * 64 + i * 16 + g4;
#pragma unroll
        for (int j = 0; j < 4; j++) {
            int col = n0 + wn * 32 + j * 8 + t4 * 2;
            float2 bv = *(const float2*)(bias + col);
            float vv[4];
            vv[0] = d[i][j][0] + bv.x; vv[1] = d[i][j][1] + bv.y;
            vv[2] = d[i][j][2] + bv.x; vv[3] = d[i][j][3] + bv.y;
            if (RELU) {
#pragma unroll
                for (int q = 0; q < 4; q++) vv[q] = fmaxf(vv[q], 0.f);
            }
            size_t o0 = (size_t)r0 * Nn + col;
            size_t o1 = (size_t)(r0 + 8) * Nn + col;
            if (WMODE == 0) {
                *(float2*)(C + o0) = make_float2(vv[0], vv[1]);
                *(float2*)(C + o1) = make_float2(vv[2], vv[3]);
            } else if (WMODE == 2) {
                float2 h0, h1;
                h0.x = __uint_as_float(f2tf32_rna(vv[0]));
                h0.y = __uint_as_float(f2tf32_rna(vv[1]));
                h1.x = __uint_as_float(f2tf32_rna(vv[2]));
                h1.y = __uint_as_float(f2tf32_rna(vv[3]));
                *(float2*)(C + o0) = h0;
                *(float2*)(C + o1) = h1;
            } else {
                float2 h0, h1, l0, l1;
                h0.x = __uint_as_float(f2tf32_rna(vv[0]));
                h0.y = __uint_as_float(f2tf32_rna(vv[1]));
                h1.x = __uint_as_float(f2tf32_rna(vv[2]));
                h1.y = __uint_as_float(f2tf32_rna(vv[3]));
                l0.x = vv[0] - h0.x; l0.y = vv[1] - h0.y;
                l1.x = vv[2] - h1.x; l1.y = vv[3] - h1.y;
                *(float2*)(C + o0)  = h0;
                *(float2*)(C + o1)  = h1;
                *(float2*)(Cl + o0) = l0;
                *(float2*)(Cl + o1) = l1;
            }
        }
    }
}

// ---------------- elementwise split ------------------------------------------
__global__ __launch_bounds__(256) void split_kernel(
    const float* __restrict__ src, float* __restrict__ dh, float* __restrict__ dl,
    int n4)
{
    int i = blockIdx.x * blockDim.x + threadIdx.x;
    if (i >= n4) return;
    float4 v = ((const float4*)src)[i];
    float4 h, l;
    h.x = __uint_as_float(f2tf32_rna(v.x)); l.x = v.x - h.x;
    h.y = __uint_as_float(f2tf32_rna(v.y)); l.y = v.y - h.y;
    h.z = __uint_as_float(f2tf32_rna(v.z)); l.z = v.z - h.z;
    h.w = __uint_as_float(f2tf32_rna(v.w)); l.w = v.w - h.w;
    ((float4*)dh)[i] = h;
    ((float4*)dl)[i] = l;
}

// ------------- weight transpose, MODE: 0 split, 1 rna ------------------------
template <int MODE>
__global__ __launch_bounds__(256) void transpose_kernel(
    const float* __restrict__ src, float* __restrict__ dh, float* __restrict__ dl,
    int R, int Cc)
{
    __shared__ float tile[32][33];
    size_t off = (size_t)blockIdx.z * R * Cc;
    int c0 = blockIdx.x * 32, r0 = blockIdx.y * 32;
    int tx = threadIdx.x, ty = threadIdx.y;
#pragma unroll
    for (int i = 0; i < 4; i++)
        tile[ty + i * 8][tx] = src[off + (size_t)(r0 + ty + i * 8) * Cc + c0 + tx];
    __syncthreads();
#pragma unroll
    for (int i = 0; i < 4; i++) {
        float v = tile[tx][ty + i * 8];
        float h = __uint_as_float(f2tf32_rna(v));
        size_t o = off + (size_t)(c0 + ty + i * 8) * R + r0 + tx;
        dh[o] = h;
        if (MODE == 0) dl[o] = v - h;
    }
}

// ---------------- router head: logits + softmax + top-2 + margin flag --------
__global__ __launch_bounds__(256) void router_topk_kernel(
    const float* __restrict__ h2, const float* __restrict__ rw3,
    const float* __restrict__ rb3, int* __restrict__ eid,
    float* __restrict__ prob, int* __restrict__ list, int* __restrict__ cnt)
{
    __shared__ __align__(16) float sh[HDIM];
    __shared__ float slog[EXPN];
    const int t = blockIdx.x;

    const float4* src = (const float4*)(h2 + (size_t)t * HDIM);
    float4* dst4 = (float4*)sh;
    for (int i = threadIdx.x; i < HDIM / 4; i += 256) dst4[i] = src[i];
    __syncthreads();

    const int w = threadIdx.x >> 5;
    const int lane = threadIdx.x & 31;
    if (w < EXPN) {
        float s = 0.f;
        for (int j = lane; j < HDIM; j += 32) s += sh[j] * rw3[(size_t)j * EXPN + w];
#pragma unroll
        for (int o = 16; o > 0; o >>= 1) s += __shfl_down_sync(0xffffffffu, s, o);
        if (lane == 0) slog[w] = s + rb3[w];
    }
    __syncthreads();

    if (threadIdx.x == 0) {
        float l[EXPN], p[EXPN];
        float mx = -1e30f;
#pragma unroll
        for (int e = 0; e < EXPN; e++) { l[e] = slog[e]; mx = fmaxf(mx, l[e]); }
        float se = 0.f;
#pragma unroll
        for (int e = 0; e < EXPN; e++) { p[e] = expf(l[e] - mx); se += p[e]; }
        float inv = 1.f / se;
#pragma unroll
        for (int e = 0; e < EXPN; e++) p[e] *= inv;
        int b1 = 0;
#pragma unroll
        for (int e = 1; e < EXPN; e++) if (l[e] > l[b1]) b1 = e;
        int b2 = (b1 == 0) ? 1 : 0;
#pragma unroll
        for (int e = 0; e < EXPN; e++)
            if (e != b1 && l[e] > l[b2]) b2 = e;
        int b3 = -1;
#pragma unroll
        for (int e = 0; e < EXPN; e++)
            if (e != b1 && e != b2 && (b3 < 0 || l[e] > l[b3])) b3 = e;
        eid[t * 2 + 0] = b1; prob[t * 2 + 0] = p[b1];
        eid[t * 2 + 1] = b2; prob[t * 2 + 1] = p[b2];
        if (l[b2] - l[b3] < MARGIN) {
            int idx = atomicAdd(cnt, 1);
            if (idx < RCAP) list[idx] = t;
        }
    }
}

__global__ void reset_cnt_kernel(int* c) { *c = 0; }

// ------------- gather marginal tokens' split x into compact batch ------------
__global__ __launch_bounds__(256) void gather_kernel(
    const float* __restrict__ xh, const float* __restrict__ xl,
    const int* __restrict__ list, const int* __restrict__ cnt,
    float* __restrict__ gxh, float* __restrict__ gxl)
{
    const int i = blockIdx.x;
    const int n = min(*cnt, RCAP);
    float4* dh = (float4*)(gxh + (size_t)i * CDIM);
    float4* dl = (float4*)(gxl + (size_t)i * CDIM);
    if (i < n) {
        const int t = list[i];
        dh[threadIdx.x] = ((const float4*)(xh + (size_t)t * CDIM))[threadIdx.x];
        dl[threadIdx.x] = ((const float4*)(xl + (size_t)t * CDIM))[threadIdx.x];
    } else {
        float4 z = make_float4(0.f, 0.f, 0.f, 0.f);
        dh[threadIdx.x] = z;
        dl[threadIdx.x] = z;
    }
}

// ------------- exact top-2 fix for marginal tokens ----------------------------
__global__ __launch_bounds__(256) void fix_topk_kernel(
    const float* __restrict__ grh2, const float* __restrict__ rw3,
    const float* __restrict__ rb3, const int* __restrict__ list,
    const int* __restrict__ cnt, int* __restrict__ eid, float* __restrict__ prob)
{
    const int i = blockIdx.x;
    if (i >= min(*cnt, RCAP)) return;
    __shared__ __align__(16) float sh[HDIM];
    __shared__ float slog[EXPN];

    const float4* src = (const float4*)(grh2 + (size_t)i * HDIM);
    float4* dst4 = (float4*)sh;
    for (int k = threadIdx.x; k < HDIM / 4; k += 256) dst4[k] = src[k];
    __syncthreads();

    const int w = threadIdx.x >> 5;
    const int lane = threadIdx.x & 31;
    if (w < EXPN) {
        float s = 0.f;
        for (int j = lane; j < HDIM; j += 32) s += sh[j] * rw3[(size_t)j * EXPN + w];
#pragma unroll
        for (int o = 16; o > 0; o >>= 1) s += __shfl_down_sync(0xffffffffu, s, o);
        if (lane == 0) slog[w] = s + rb3[w];
    }
    __syncthreads();

    if (threadIdx.x == 0) {
        const int t = list[i];
        float l[EXPN], p[EXPN];
        float mx = -1e30f;
#pragma unroll
        for (int e = 0; e < EXPN; e++) { l[e] = slog[e]; mx = fmaxf(mx, l[e]); }
        float se = 0.f;
#pragma unroll
        for (int e = 0; e < EXPN; e++) { p[e] = expf(l[e] - mx); se += p[e]; }
        float inv = 1.f / se;
#pragma unroll
        for (int e = 0; e < EXPN; e++) p[e] *= inv;
        int b1 = 0;
#pragma unroll
        for (int e = 1; e < EXPN; e++) if (l[e] > l[b1]) b1 = e;
        int b2 = (b1 == 0) ? 1 : 0;
#pragma unroll
        for (int e = 0; e < EXPN; e++)
            if (e != b1 && l[e] > l[b2]) b2 = e;
        eid[t * 2 + 0] = b1; prob[t * 2 + 0] = p[b1];
        eid[t * 2 + 1] = b2; prob[t * 2 + 1] = p[b2];
    }
}

// ---- exact flattened-order per-expert ranks ---------------------------------
__global__ __launch_bounds__(1024) void positions_kernel(
    const int* __restrict__ eid, int* __restrict__ pos)
{
    __shared__ int base[EXPN];
    __shared__ int wcnt[32][EXPN];
    const int tid = threadIdx.x;
    const int lane = tid & 31;
    const int w = tid >> 5;

    if (tid < EXPN) base[tid] = 0;
    __syncthreads();

    for (int c = 0; c < NFLAT; c += 1024) {
        if (tid < 32 * EXPN) ((int*)wcnt)[tid] = 0;
        __syncthreads();

        int e = eid[c + tid];
        unsigned m = __match_any_sync(0xffffffffu, e);
        int rank = __popc(m & ((1u << lane) - 1u));
        int leader = __ffs(m) - 1;
        if (lane == leader) wcnt[w][e] = __popc(m);
        __syncthreads();

        int off = base[e] + rank;
        for (int w2 = 0; w2 < 32; w2++)
            if (w2 < w) off += wcnt[w2][e];
        pos[c + tid] = off;
        __syncthreads();

        if (tid < EXPN) {
            int s = 0;
#pragma unroll
            for (int w2 = 0; w2 < 32; w2++) s += wcnt[w2][tid];
            base[tid] += s;
        }
        __syncthreads();
    }
}

// dispatch: scatter rna(x) rows into expert buffers
__global__ __launch_bounds__(256) void dispatch_kernel(
    const float* __restrict__ x, const int* __restrict__ eid,
    const int* __restrict__ pos, float* __restrict__ disp)
{
    const int i = blockIdx.x;
    const int p = pos[i];
    if (p >= CAPN) return;
    const int e = eid[i];
    const int token = i >> 1;
    const float4* src = (const float4*)(x + (size_t)token * CDIM);
    float4* dst = (float4*)(disp + ((size_t)e * CAPN + p) * CDIM);
    float4 v = src[threadIdx.x];
    v.x = __uint_as_float(f2tf32_rna(v.x));
    v.y = __uint_as_float(f2tf32_rna(v.y));
    v.z = __uint_as_float(f2tf32_rna(v.z));
    v.w = __uint_as_float(f2tf32_rna(v.w));
    dst[threadIdx.x] = v;
}

__global__ __launch_bounds__(256) void combine_kernel(
    const float* __restrict__ eo, const int* __restrict__ eid,
    const float* __restrict__ prob, const int* __restrict__ pos,
    float* __restrict__ out)
{
    const int t = blockIdx.x;
    const int e1 = eid[t * 2 + 0], e2 = eid[t * 2 + 1];
    const int p1 = pos[t * 2 + 0], p2 = pos[t * 2 + 1];
    const float w1 = prob[t * 2 + 0] * (p1 < CAPN ? 1.f : 0.f);
    const float w2 = prob[t * 2 + 1] * (p2 < CAPN ? 1.f : 0.f);
    const int g1 = min(p1, CAPN - 1), g2 = min(p2, CAPN - 1);

    const float4* r1 = (const float4*)(eo + ((size_t)e1 * CAPN + g1) * CDIM);
    const float4* r2 = (const float4*)(eo + ((size_t)e2 * CAPN + g2) * CDIM);
    float4 a = r1[threadIdx.x];
    float4 b = r2[threadIdx.x];
    float4 v;
    v.x = w1 * a.x + w2 * b.x;
    v.y = w1 * a.y + w2 * b.y;
    v.z = w1 * a.z + w2 * b.z;
    v.w = w1 * a.w + w2 * b.w;
    ((float4*)(out + (size_t)t * CDIM))[threadIdx.x] = v;
}

// ---------------- launch -----------------------------------------------------
extern "C" void kernel_launch(void* const* d_in, const int* in_sizes, int n_in,
                              void* d_out, int out_size)
{
    const float* x   = (const float*)d_in[0];
    const float* rw1 = (const float*)d_in[1];
    const float* rb1 = (const float*)d_in[2];
    const float* rw2 = (const float*)d_in[3];
    const float* rb2 = (const float*)d_in[4];
    const float* rw3 = (const float*)d_in[5];
    const float* rb3 = (const float*)d_in[6];
    const float* ew1 = (const float*)d_in[7];
    const float* eb1 = (const float*)d_in[8];
    const float* ew2 = (const float*)d_in[9];
    const float* eb2 = (const float*)d_in[10];
    float* out = (float*)d_out;
    (void)in_sizes; (void)n_in; (void)out_size;

    float *xh, *xl, *h1r, *h2, *disp, *eh, *eo, *prob;
    float *rw1th, *rw1tl, *rw2th, *rw2tl, *ew1t, *ew2t;
    float *gxh, *gxl, *grh1h, *grh1l, *grh2;
    int *eid, *pos, *list, *cnt;
    cudaGetSymbolAddress((void**)&xh,    g_xh);
    cudaGetSymbolAddress((void**)&xl,    g_xl);
    cudaGetSymbolAddress((void**)&h1r,   g_h1r);
    cudaGetSymbolAddress((void**)&h2,    g_h2);
    cudaGetSymbolAddress((void**)&disp,  g_disp);
    cudaGetSymbolAddress((void**)&eh,    g_eh);
    cudaGetSymbolAddress((void**)&eo,    g_eo);
    cudaGetSymbolAddress((void**)&eid,   g_eid);
    cudaGetSymbolAddress((void**)&prob,  g_prob);
    cudaGetSymbolAddress((void**)&pos,   g_pos);
    cudaGetSymbolAddress((void**)&rw1th, g_rw1th);
    cudaGetSymbolAddress((void**)&rw1tl, g_rw1tl);
    cudaGetSymbolAddress((void**)&rw2th, g_rw2th);
    cudaGetSymbolAddress((void**)&rw2tl, g_rw2tl);
    cudaGetSymbolAddress((void**)&ew1t,  g_ew1t);
    cudaGetSymbolAddress((void**)&ew2t,  g_ew2t);
    cudaGetSymbolAddress((void**)&gxh,   g_gxh);
    cudaGetSymbolAddress((void**)&gxl,   g_gxl);
    cudaGetSymbolAddress((void**)&grh1h, g_grh1h);
    cudaGetSymbolAddress((void**)&grh1l, g_grh1l);
    cudaGetSymbolAddress((void**)&grh2,  g_grh2);
    cudaGetSymbolAddress((void**)&list,  g_list);
    cudaGetSymbolAddress((void**)&cnt,   g_cnt);

    const int DS3 = 4 * TILEF * NST * 4;
    const int DS1 = 2 * TILEF * NST * 4;
    cudaFuncSetAttribute(mma_gemm<1,1,1>, cudaFuncAttributeMaxDynamicSharedMemorySize, DS3);
    cudaFuncSetAttribute(mma_gemm<1,1,0>, cudaFuncAttributeMaxDynamicSharedMemorySize, DS3);
    cudaFuncSetAttribute(mma_gemm<0,1,2>, cudaFuncAttributeMaxDynamicSharedMemorySize, DS1);
    cudaFuncSetAttribute(mma_gemm<0,1,0>, cudaFuncAttributeMaxDynamicSharedMemorySize, DS1);
    cudaFuncSetAttribute(mma_gemm<0,0,0>, cudaFuncAttributeMaxDynamicSharedMemorySize, DS1);

    // operand preparation
    split_kernel<<<(NTOK * CDIM / 4 + 255) / 256, 256>>>(x, xh, xl, NTOK * CDIM / 4);
    transpose_kernel<0><<<dim3(HDIM/32, CDIM/32, 1), dim3(32, 8)>>>(rw1, rw1th, rw1tl, CDIM, HDIM);
    transpose_kernel<0><<<dim3(HDIM/32, HDIM/32, 1), dim3(32, 8)>>>(rw2, rw2th, rw2tl, HDIM, HDIM);
    transpose_kernel<1><<<dim3(HDIM/32, CDIM/32, EXPN), dim3(32, 8)>>>(ew1, ew1t, nullptr, CDIM, HDIM);
    transpose_kernel<1><<<dim3(CDIM/32, HDIM/32, EXPN), dim3(32, 8)>>>(ew2, ew2t, nullptr, HDIM, CDIM);

    // router MLP in 1xTF32 (fast approx; decisions fixed below)
    mma_gemm<0,1,2><<<dim3(HDIM/128, NTOK/128, 1), 256, DS1>>>(
        xh, nullptr, rw1th, nullptr, rb1, h1r, nullptr, nullptr, CDIM, HDIM, 0, 0, 0, 0);
    mma_gemm<0,1,0><<<dim3(HDIM/128, NTOK/128, 1), 256, DS1>>>(
        h1r, nullptr, rw2th, nullptr, rb2, h2, nullptr, nullptr, HDIM, HDIM, 0, 0, 0, 0);

    reset_cnt_kernel<<<1, 1>>>(cnt);
    router_topk_kernel<<<NTOK, 256>>>(h2, rw3, rb3, eid, prob, list, cnt);

    // exact (3xTF32) recheck of marginal tokens, early-exit on count
    gather_kernel<<<RCAP, 256>>>(xh, xl, list, cnt, gxh, gxl);
    mma_gemm<1,1,1><<<dim3(HDIM/128, RCAP/128, 1), 256, DS3>>>(
        gxh, gxl, rw1th, rw1tl, rb1, grh1h, grh1l, cnt, CDIM, HDIM, 0, 0, 0, 0);
    mma_gemm<1,1,0><<<dim3(HDIM/128, RCAP/128, 1), 256, DS3>>>(
        grh1h, grh1l, rw2th, rw2tl, rb2, grh2, nullptr, cnt, HDIM, HDIM, 0, 0, 0, 0);
    fix_topk_kernel<<<RCAP, 256>>>(grh2, rw3, rb3, list, cnt, eid, prob);

    positions_kernel<<<1, 1024>>>(eid, pos);
    dispatch_kernel<<<NFLAT, 256>>>(x, eid, pos, disp);

    // expert FFNs (1xTF32)
    mma_gemm<0,1,2><<<dim3(HDIM/128, CAPN/128, EXPN), 256, DS1>>>(
        disp, nullptr, ew1t, nullptr, eb1, eh, nullptr, nullptr, CDIM, HDIM,
        (long long)CAPN * CDIM, (long long)HDIM * CDIM, HDIM, (long long)CAPN * HDIM);
    mma_gemm<0,0,0><<<dim3(CDIM/128, CAPN/128, EXPN), 256, DS1>>>(
        eh, nullptr, ew2t, nullptr, eb2, eo, nullptr, nullptr, HDIM, CDIM,
        (long long)CAPN * HDIM, (long long)CDIM * HDIM, CDIM, (long long)CAPN * CDIM);

    // combine
    combine_kernel<<<NTOK, 256>>>(eo, eid, prob, pos, out);
}

// round 12
// speedup vs baseline: 1.6513x; 1.0827x over previous
#include <cuda_runtime.h>
#include <cstdint>
#include <math.h>

// Problem constants
#define NTOK 8192
#define CDIM 1024
#define HDIM 4096
#define EXPN 8
#define KSEL 2
#define CAPN 2048
#define NFLAT (NTOK*KSEL)
#define RCAP 2048               // recheck batch capacity (rows)
#define MARGIN 0.008f           // logit-gap threshold for exact recheck

// GEMM tiling: CTA 128x128, BK=32, 256 threads, warp tile 64x32 (2x4 warps)
#define BK2 32
#define RP 36
#define NST 3
#define TILEF (128*RP)

// ---------------- scratch ----------------------------------------------------
__device__ float g_xh[(size_t)NTOK * CDIM];
__device__ float g_xl[(size_t)NTOK * CDIM];
__device__ float g_h1r[(size_t)NTOK * HDIM];
__device__ float g_h2[(size_t)NTOK * HDIM];
__device__ int   g_eid[NFLAT];
__device__ float g_prob[NFLAT];
__device__ int   g_pos[NFLAT];
__device__ float g_disp[(size_t)EXPN * CAPN * CDIM];
__device__ float g_eh[(size_t)EXPN * CAPN * HDIM];
__device__ float g_eo[(size_t)EXPN * CAPN * CDIM];
__device__ float g_rw1th[(size_t)HDIM * CDIM];
__device__ float g_rw1tl[(size_t)HDIM * CDIM];
__device__ float g_rw2th[(size_t)HDIM * HDIM];
__device__ float g_rw2tl[(size_t)HDIM * HDIM];
__device__ float g_ew1t[(size_t)EXPN * HDIM * CDIM];
__device__ float g_ew2t[(size_t)EXPN * CDIM * HDIM];
// recheck scratch
__device__ int   g_list[RCAP];
__device__ int   g_cnt;
__device__ float g_gxh[(size_t)RCAP * CDIM];
__device__ float g_gxl[(size_t)RCAP * CDIM];
__device__ float g_grh1h[(size_t)RCAP * HDIM];
__device__ float g_grh1l[(size_t)RCAP * HDIM];
__device__ float g_grh2[(size_t)RCAP * HDIM];

// ---------------- helpers ------------------------------------------------
__device__ __forceinline__ uint32_t f2tf32_rna(float x) {
    uint32_t u;
    asm("cvt.rna.tf32.f32 %0, %1;" : "=r"(u) : "f"(x));
    return u;
}
__device__ __forceinline__ uint32_t smem_u32(const void* p) {
    uint32_t a;
    asm("{ .reg .u64 t; cvta.to.shared.u64 t, %1; cvt.u32.u64 %0, t; }" : "=r"(a) : "l"(p));
    return a;
}
__device__ __forceinline__ void cp16(uint32_t s, const float* g) {
    asm volatile("cp.async.cg.shared.global [%0], [%1], 16;" :: "r"(s), "l"(g));
}
__device__ __forceinline__ void cp_commit() {
    asm volatile("cp.async.commit_group;" ::: "memory");
}
template <int N> __device__ __forceinline__ void cp_wait() {
    asm volatile("cp.async.wait_group %0;" :: "n"(N) : "memory");
}

#define MMA_TF32(d, a, b) \
    asm volatile( \
        "mma.sync.aligned.m16n8k8.row.col.f32.tf32.tf32.f32 " \
        "{%0,%1,%2,%3}, {%4,%5,%6,%7}, {%8,%9}, {%0,%1,%2,%3};" \
        : "+f"((d)[0]), "+f"((d)[1]), "+f"((d)[2]), "+f"((d)[3]) \
        : "r"((a)[0]), "r"((a)[1]), "r"((a)[2]), "r"((a)[3]), \
          "r"((b)[0]), "r"((b)[1]))

// ldmatrix x4 of b16 == four 8x8 b32 quadrants (tf32 bit-moves)
#define LDSM_X4(r, a) \
    asm volatile("ldmatrix.sync.aligned.m8n8.x4.shared.b16 {%0,%1,%2,%3}, [%4];" \
        : "=r"((r)[0]), "=r"((r)[1]), "=r"((r)[2]), "=r"((r)[3]) : "r"(a))

// ---------------- TF32 mma.sync GEMM (pre-converted operands) ----------------
template <int PASS3, int RELU, int WMODE>
__global__ __launch_bounds__(256, 1)
void mma_gemm(const float* __restrict__ Ah, const float* __restrict__ Al,
              const float* __restrict__ Bh, const float* __restrict__ Bl,
              const float* __restrict__ bias, float* __restrict__ C,
              float* __restrict__ Cl, const int* __restrict__ mrows,
              int Kd, int Nn,
              long long aB, long long bB, long long biasB, long long cB)
{
    if (mrows && (int)(blockIdx.y * 128) >= *mrows) return;

    extern __shared__ float sm[];
    constexpr int AHo = 0;
    constexpr int BHo = TILEF;
    constexpr int ALo = 2 * TILEF;
    constexpr int BLo = 3 * TILEF;
    constexpr int STG = (PASS3 ? 4 : 2) * TILEF;

    const int tid = threadIdx.x;
    const int z = blockIdx.z;
    Ah += (size_t)z * aB;
    Bh += (size_t)z * bB;
    if (PASS3) { Al += (size_t)z * aB; Bl += (size_t)z * bB; }
    bias += (size_t)z * biasB;
    C    += (size_t)z * cB;
    if (WMODE == 1) Cl += (size_t)z * cB;
    const int m0 = blockIdx.y * 128;
    const int n0 = blockIdx.x * 128;

    const int warp = tid >> 5;
    const int lane = tid & 31;
    const int wm = warp >> 2;
    const int wn = warp & 3;
    const int g4 = lane >> 2;
    const int t4 = lane & 3;

    const uint32_t smb = smem_u32(sm);
    const int nk = Kd / BK2;

    // ldmatrix lane-address bases (bytes within a stage, before tile offset)
    // A x4: lanes 0-15 -> rows (wm*64 + lane), col 0; lanes 16-31 -> rows, col+4
    const uint32_t aFrag = (uint32_t)(((wm * 64 + (lane & 15)) * RP + ((lane >> 4) << 2)) * 4);
    // B x4 (covers 16 n-rows = 2 j-blocks): rows wn*32 + (lane&7) + ((lane>>3)&1)*8, col (lane>>4)*4
    const uint32_t bFrag = (uint32_t)(((wn * 32 + (lane & 7) + ((lane >> 3) & 1) * 8) * RP
                                      + ((lane >> 4) << 2)) * 4);

    int lrow[4], lc4[4];
#pragma unroll
    for (int t = 0; t < 4; t++) {
        int id = tid + 256 * t;
        lrow[t] = id >> 3;
        lc4[t] = (id & 7) * 4;
    }

    auto ISSUE = [&](int s) {
        const int buf = s % NST;
        const uint32_t sb = smb + (uint32_t)buf * STG * 4;
        const size_t ko = (size_t)s * BK2;
#pragma unroll
        for (int t = 0; t < 4; t++) {
            const size_t go = (size_t)lrow[t] * Kd + ko + lc4[t];
            const uint32_t so = (uint32_t)(lrow[t] * RP + lc4[t]) * 4;
            cp16(sb + AHo * 4 + so, Ah + (size_t)m0 * Kd + go);
            cp16(sb + BHo * 4 + so, Bh + (size_t)n0 * Kd + go);
            if (PASS3) {
                cp16(sb + ALo * 4 + so, Al + (size_t)m0 * Kd + go);
                cp16(sb + BLo * 4 + so, Bl + (size_t)n0 * Kd + go);
            }
        }
    };

    float d[4][4][4];
#pragma unroll
    for (int i = 0; i < 4; i++)
#pragma unroll
        for (int j = 0; j < 4; j++)
#pragma unroll
            for (int q = 0; q < 4; q++) d[i][j][q] = 0.f;

    ISSUE(0); cp_commit();
    if (nk > 1) ISSUE(1);
    cp_commit();

    for (int s = 0; s < nk; s++) {
        cp_wait<NST - 2>();
        __syncthreads();
        if (s + NST - 1 < nk) ISSUE(s + NST - 1);
        cp_commit();

        const uint32_t sb32 = smb + (uint32_t)(s % NST) * STG * 4;
#pragma unroll
        for (int kk = 0; kk < 4; kk++) {
            const uint32_t cOff = (uint32_t)kk * 32;   // kk*8 floats
            uint32_t ah[4][4], bh[4][2];
#pragma unroll
            for (int i = 0; i < 4; i++)
                LDSM_X4(ah[i], sb32 + AHo * 4 + aFrag + (uint32_t)(i * 16 * RP * 4) + cOff);
#pragma unroll
            for (int j2 = 0; j2 < 2; j2++) {
                uint32_t t[4];
                LDSM_X4(t, sb32 + BHo * 4 + bFrag + (uint32_t)(j2 * 16 * RP * 4) + cOff);
                bh[j2 * 2][0] = t[0]; bh[j2 * 2 + 1][0] = t[1];
                bh[j2 * 2][1] = t[2]; bh[j2 * 2 + 1][1] = t[3];
            }
#pragma unroll
            for (int i = 0; i < 4; i++)
#pragma unroll
                for (int j = 0; j < 4; j++) MMA_TF32(d[i][j], ah[i], bh[j]);

            if (PASS3) {
                uint32_t al[4][4], bl[4][2];
#pragma unroll
                for (int i = 0; i < 4; i++)
                    LDSM_X4(al[i], sb32 + ALo * 4 + aFrag + (uint32_t)(i * 16 * RP * 4) + cOff);
#pragma unroll
                for (int j2 = 0; j2 < 2; j2++) {
                    uint32_t t[4];
                    LDSM_X4(t, sb32 + BLo * 4 + bFrag + (uint32_t)(j2 * 16 * RP * 4) + cOff);
                    bl[j2 * 2][0] = t[0]; bl[j2 * 2 + 1][0] = t[1];
                    bl[j2 * 2][1] = t[2]; bl[j2 * 2 + 1][1] = t[3];
                }
#pragma unroll
                for (int i = 0; i < 4; i++)
#pragma unroll
                    for (int j = 0; j < 4; j++) {
                        MMA_TF32(d[i][j], ah[i], bl[j]);
                        MMA_TF32(d[i][j], al[i], bh[j]);
                    }
            }
        }
    }

    // epilogue
#pragma unroll
    for (int i = 0; i < 4; i++) {
        int r0 = m0 + wm * 64 + i * 16 + g4;
#pragma unroll
        for (int j = 0; j < 4; j++) {
            int col = n0 + wn * 32 + j * 8 + t4 * 2;
            float2 bv = *(const float2*)(bias + col);
            float vv[4];
            vv[0] = d[i][j][0] + bv.x; vv[1] = d[i][j][1] + bv.y;
            vv[2] = d[i][j][2] + bv.x; vv[3] = d[i][j][3] + bv.y;
            if (RELU) {
#pragma unroll
                for (int q = 0; q < 4; q++) vv[q] = fmaxf(vv[q], 0.f);
            }
            size_t o0 = (size_t)r0 * Nn + col;
            size_t o1 = (size_t)(r0 + 8) * Nn + col;
            if (WMODE == 0) {
                *(float2*)(C + o0) = make_float2(vv[0], vv[1]);
                *(float2*)(C + o1) = make_float2(vv[2], vv[3]);
            } else if (WMODE == 2) {
                float2 h0, h1;
                h0.x = __uint_as_float(f2tf32_rna(vv[0]));
                h0.y = __uint_as_float(f2tf32_rna(vv[1]));
                h1.x = __uint_as_float(f2tf32_rna(vv[2]));
                h1.y = __uint_as_float(f2tf32_rna(vv[3]));
                *(float2*)(C + o0) = h0;
                *(float2*)(C + o1) = h1;
            } else {
                float2 h0, h1, l0, l1;
                h0.x = __uint_as_float(f2tf32_rna(vv[0]));
                h0.y = __uint_as_float(f2tf32_rna(vv[1]));
                h1.x = __uint_as_float(f2tf32_rna(vv[2]));
                h1.y = __uint_as_float(f2tf32_rna(vv[3]));
                l0.x = vv[0] - h0.x; l0.y = vv[1] - h0.y;
                l1.x = vv[2] - h1.x; l1.y = vv[3] - h1.y;
                *(float2*)(C + o0)  = h0;
                *(float2*)(C + o1)  = h1;
                *(float2*)(Cl + o0) = l0;
                *(float2*)(Cl + o1) = l1;
            }
        }
    }
}

// ---------------- elementwise split ------------------------------------------
__global__ __launch_bounds__(256) void split_kernel(
    const float* __restrict__ src, float* __restrict__ dh, float* __restrict__ dl,
    int n4)
{
    int i = blockIdx.x * blockDim.x + threadIdx.x;
    if (i >= n4) return;
    float4 v = ((const float4*)src)[i];
    float4 h, l;
    h.x = __uint_as_float(f2tf32_rna(v.x)); l.x = v.x - h.x;
    h.y = __uint_as_float(f2tf32_rna(v.y)); l.y = v.y - h.y;
    h.z = __uint_as_float(f2tf32_rna(v.z)); l.z = v.z - h.z;
    h.w = __uint_as_float(f2tf32_rna(v.w)); l.w = v.w - h.w;
    ((float4*)dh)[i] = h;
    ((float4*)dl)[i] = l;
}

// ------------- weight transpose, MODE: 0 split, 1 rna ------------------------
template <int MODE>
__global__ __launch_bounds__(256) void transpose_kernel(
    const float* __restrict__ src, float* __restrict__ dh, float* __restrict__ dl,
    int R, int Cc)
{
    __shared__ float tile[32][33];
    size_t off = (size_t)blockIdx.z * R * Cc;
    int c0 = blockIdx.x * 32, r0 = blockIdx.y * 32;
    int tx = threadIdx.x, ty = threadIdx.y;
#pragma unroll
    for (int i = 0; i < 4; i++)
        tile[ty + i * 8][tx] = src[off + (size_t)(r0 + ty + i * 8) * Cc + c0 + tx];
    __syncthreads();
#pragma unroll
    for (int i = 0; i < 4; i++) {
        float v = tile[tx][ty + i * 8];
        float h = __uint_as_float(f2tf32_rna(v));
        size_t o = off + (size_t)(c0 + ty + i * 8) * R + r0 + tx;
        dh[o] = h;
        if (MODE == 0) dl[o] = v - h;
    }
}

// ---------------- router head: logits + softmax + top-2 + margin flag --------
__global__ __launch_bounds__(256) void router_topk_kernel(
    const float* __restrict__ h2, const float* __restrict__ rw3,
    const float* __restrict__ rb3, int* __restrict__ eid,
    float* __restrict__ prob, int* __restrict__ list, int* __restrict__ cnt)
{
    __shared__ __align__(16) float sh[HDIM];
    __shared__ float slog[EXPN];
    const int t = blockIdx.x;

    const float4* src = (const float4*)(h2 + (size_t)t * HDIM);
    float4* dst4 = (float4*)sh;
    for (int i = threadIdx.x; i < HDIM / 4; i += 256) dst4[i] = src[i];
    __syncthreads();

    const int w = threadIdx.x >> 5;
    const int lane = threadIdx.x & 31;
    if (w < EXPN) {
        float s = 0.f;
        for (int j = lane; j < HDIM; j += 32) s += sh[j] * rw3[(size_t)j * EXPN + w];
#pragma unroll
        for (int o = 16; o > 0; o >>= 1) s += __shfl_down_sync(0xffffffffu, s, o);
        if (lane == 0) slog[w] = s + rb3[w];
    }
    __syncthreads();

    if (threadIdx.x == 0) {
        float l[EXPN], p[EXPN];
        float mx = -1e30f;
#pragma unroll
        for (int e = 0; e < EXPN; e++) { l[e] = slog[e]; mx = fmaxf(mx, l[e]); }
        float se = 0.f;
#pragma unroll
        for (int e = 0; e < EXPN; e++) { p[e] = expf(l[e] - mx); se += p[e]; }
        float inv = 1.f / se;
#pragma unroll
        for (int e = 0; e < EXPN; e++) p[e] *= inv;
        int b1 = 0;
#pragma unroll
        for (int e = 1; e < EXPN; e++) if (l[e] > l[b1]) b1 = e;
        int b2 = (b1 == 0) ? 1 : 0;
#pragma unroll
        for (int e = 0; e < EXPN; e++)
            if (e != b1 && l[e] > l[b2]) b2 = e;
        int b3 = -1;
#pragma unroll
        for (int e = 0; e < EXPN; e++)
            if (e != b1 && e != b2 && (b3 < 0 || l[e] > l[b3])) b3 = e;
        eid[t * 2 + 0] = b1; prob[t * 2 + 0] = p[b1];
        eid[t * 2 + 1] = b2; prob[t * 2 + 1] = p[b2];
        if (l[b2] - l[b3] < MARGIN) {
            int idx = atomicAdd(cnt, 1);
            if (idx < RCAP) list[idx] = t;
        }
    }
}

__global__ void reset_cnt_kernel(int* c) { *c = 0; }

// ------------- gather marginal tokens' split x into compact batch ------------
__global__ __launch_bounds__(256) void gather_kernel(
    const float* __restrict__ xh, const float* __restrict__ xl,
    const int* __restrict__ list, const int* __restrict__ cnt,
    float* __restrict__ gxh, float* __restrict__ gxl)
{
    const int i = blockIdx.x;
    const int n = min(*cnt, RCAP);
    float4* dh = (float4*)(gxh + (size_t)i * CDIM);
    float4* dl = (float4*)(gxl + (size_t)i * CDIM);
    if (i < n) {
        const int t = list[i];
        dh[threadIdx.x] = ((const float4*)(xh + (size_t)t * CDIM))[threadIdx.x];
        dl[threadIdx.x] = ((const float4*)(xl + (size_t)t * CDIM))[threadIdx.x];
    } else {
        float4 z = make_float4(0.f, 0.f, 0.f, 0.f);
        dh[threadIdx.x] = z;
        dl[threadIdx.x] = z;
    }
}

// ------------- exact top-2 fix for marginal tokens ----------------------------
__global__ __launch_bounds__(256) void fix_topk_kernel(
    const float* __restrict__ grh2, const float* __restrict__ rw3,
    const float* __restrict__ rb3, const int* __restrict__ list,
    const int* __restrict__ cnt, int* __restrict__ eid, float* __restrict__ prob)
{
    const int i = blockIdx.x;
    if (i >= min(*cnt, RCAP)) return;
    __shared__ __align__(16) float sh[HDIM];
    __shared__ float slog[EXPN];

    const float4* src = (const float4*)(grh2 + (size_t)i * HDIM);
    float4* dst4 = (float4*)sh;
    for (int k = threadIdx.x; k < HDIM / 4; k += 256) dst4[k] = src[k];
    __syncthreads();

    const int w = threadIdx.x >> 5;
    const int lane = threadIdx.x & 31;
    if (w < EXPN) {
        float s = 0.f;
        for (int j = lane; j < HDIM; j += 32) s += sh[j] * rw3[(size_t)j * EXPN + w];
#pragma unroll
        for (int o = 16; o > 0; o >>= 1) s += __shfl_down_sync(0xffffffffu, s, o);
        if (lane == 0) slog[w] = s + rb3[w];
    }
    __syncthreads();

    if (threadIdx.x == 0) {
        const int t = list[i];
        float l[EXPN], p[EXPN];
        float mx = -1e30f;
#pragma unroll
        for (int e = 0; e < EXPN; e++) { l[e] = slog[e]; mx = fmaxf(mx, l[e]); }
        float se = 0.f;
#pragma unroll
        for (int e = 0; e < EXPN; e++) { p[e] = expf(l[e] - mx); se += p[e]; }
        float inv = 1.f / se;
#pragma unroll
        for (int e = 0; e < EXPN; e++) p[e] *= inv;
        int b1 = 0;
#pragma unroll
        for (int e = 1; e < EXPN; e++) if (l[e] > l[b1]) b1 = e;
        int b2 = (b1 == 0) ? 1 : 0;
#pragma unroll
        for (int e = 0; e < EXPN; e++)
            if (e != b1 && l[e] > l[b2]) b2 = e;
        eid[t * 2 + 0] = b1; prob[t * 2 + 0] = p[b1];
        eid[t * 2 + 1] = b2; prob[t * 2 + 1] = p[b2];
    }
}

// ---- exact flattened-order per-expert ranks ---------------------------------
__global__ __launch_bounds__(1024) void positions_kernel(
    const int* __restrict__ eid, int* __restrict__ pos)
{
    __shared__ int base[EXPN];
    __shared__ int wcnt[32][EXPN];
    const int tid = threadIdx.x;
    const int lane = tid & 31;
    const int w = tid >> 5;

    if (tid < EXPN) base[tid] = 0;
    __syncthreads();

    for (int c = 0; c < NFLAT; c += 1024) {
        if (tid < 32 * EXPN) ((int*)wcnt)[tid] = 0;
        __syncthreads();

        int e = eid[c + tid];
        unsigned m = __match_any_sync(0xffffffffu, e);
        int rank = __popc(m & ((1u << lane) - 1u));
        int leader = __ffs(m) - 1;
        if (lane == leader) wcnt[w][e] = __popc(m);
        __syncthreads();

        int off = base[e] + rank;
        for (int w2 = 0; w2 < 32; w2++)
            if (w2 < w) off += wcnt[w2][e];
        pos[c + tid] = off;
        __syncthreads();

        if (tid < EXPN) {
            int s = 0;
#pragma unroll
            for (int w2 = 0; w2 < 32; w2++) s += wcnt[w2][tid];
            base[tid] += s;
        }
        __syncthreads();
    }
}

// dispatch: scatter rna(x) rows into expert buffers
__global__ __launch_bounds__(256) void dispatch_kernel(
    const float* __restrict__ x, const int* __restrict__ eid,
    const int* __restrict__ pos, float* __restrict__ disp)
{
    const int i = blockIdx.x;
    const int p = pos[i];
    if (p >= CAPN) return;
    const int e = eid[i];
    const int token = i >> 1;
    const float4* src = (const float4*)(x + (size_t)token * CDIM);
    float4* dst = (float4*)(disp + ((size_t)e * CAPN + p) * CDIM);
    float4 v = src[threadIdx.x];
    v.x = __uint_as_float(f2tf32_rna(v.x));
    v.y = __uint_as_float(f2tf32_rna(v.y));
    v.z = __uint_as_float(f2tf32_rna(v.z));
    v.w = __uint_as_float(f2tf32_rna(v.w));
    dst[threadIdx.x] = v;
}

__global__ __launch_bounds__(256) void combine_kernel(
    const float* __restrict__ eo, const int* __restrict__ eid,
    const float* __restrict__ prob, const int* __restrict__ pos,
    float* __restrict__ out)
{
    const int t = blockIdx.x;
    const int e1 = eid[t * 2 + 0], e2 = eid[t * 2 + 1];
    const int p1 = pos[t * 2 + 0], p2 = pos[t * 2 + 1];
    const float w1 = prob[t * 2 + 0] * (p1 < CAPN ? 1.f : 0.f);
    const float w2 = prob[t * 2 + 1] * (p2 < CAPN ? 1.f : 0.f);
    const int g1 = min(p1, CAPN - 1), g2 = min(p2, CAPN - 1);

    const float4* r1 = (const float4*)(eo + ((size_t)e1 * CAPN + g1) * CDIM);
    const float4* r2 = (const float4*)(eo + ((size_t)e2 * CAPN + g2) * CDIM);
    float4 a = r1[threadIdx.x];
    float4 b = r2[threadIdx.x];
    float4 v;
    v.x = w1 * a.x + w2 * b.x;
    v.y = w1 * a.y + w2 * b.y;
    v.z = w1 * a.z + w2 * b.z;
    v.w = w1 * a.w + w2 * b.w;
    ((float4*)(out + (size_t)t * CDIM))[threadIdx.x] = v;
}

// ---------------- launch -----------------------------------------------------
extern "C" void kernel_launch(void* const* d_in, const int* in_sizes, int n_in,
                              void* d_out, int out_size)
{
    const float* x   = (const float*)d_in[0];
    const float* rw1 = (const float*)d_in[1];
    const float* rb1 = (const float*)d_in[2];
    const float* rw2 = (const float*)d_in[3];
    const float* rb2 = (const float*)d_in[4];
    const float* rw3 = (const float*)d_in[5];
    const float* rb3 = (const float*)d_in[6];
    const float* ew1 = (const float*)d_in[7];
    const float* eb1 = (const float*)d_in[8];
    const float* ew2 = (const float*)d_in[9];
    const float* eb2 = (const float*)d_in[10];
    float* out = (float*)d_out;
    (void)in_sizes; (void)n_in; (void)out_size;

    float *xh, *xl, *h1r, *h2, *disp, *eh, *eo, *prob;
    float *rw1th, *rw1tl, *rw2th, *rw2tl, *ew1t, *ew2t;
    float *gxh, *gxl, *grh1h, *grh1l, *grh2;
    int *eid, *pos, *list, *cnt;
    cudaGetSymbolAddress((void**)&xh,    g_xh);
    cudaGetSymbolAddress((void**)&xl,    g_xl);
    cudaGetSymbolAddress((void**)&h1r,   g_h1r);
    cudaGetSymbolAddress((void**)&h2,    g_h2);
    cudaGetSymbolAddress((void**)&disp,  g_disp);
    cudaGetSymbolAddress((void**)&eh,    g_eh);
    cudaGetSymbolAddress((void**)&eo,    g_eo);
    cudaGetSymbolAddress((void**)&eid,   g_eid);
    cudaGetSymbolAddress((void**)&prob,  g_prob);
    cudaGetSymbolAddress((void**)&pos,   g_pos);
    cudaGetSymbolAddress((void**)&rw1th, g_rw1th);
    cudaGetSymbolAddress((void**)&rw1tl, g_rw1tl);
    cudaGetSymbolAddress((void**)&rw2th, g_rw2th);
    cudaGetSymbolAddress((void**)&rw2tl, g_rw2tl);
    cudaGetSymbolAddress((void**)&ew1t,  g_ew1t);
    cudaGetSymbolAddress((void**)&ew2t,  g_ew2t);
    cudaGetSymbolAddress((void**)&gxh,   g_gxh);
    cudaGetSymbolAddress((void**)&gxl,   g_gxl);
    cudaGetSymbolAddress((void**)&grh1h, g_grh1h);
    cudaGetSymbolAddress((void**)&grh1l, g_grh1l);
    cudaGetSymbolAddress((void**)&grh2,  g_grh2);
    cudaGetSymbolAddress((void**)&list,  g_list);
    cudaGetSymbolAddress((void**)&cnt,   g_cnt);

    const int DS3 = 4 * TILEF * NST * 4;
    const int DS1 = 2 * TILEF * NST * 4;
    cudaFuncSetAttribute(mma_gemm<1,1,1>, cudaFuncAttributeMaxDynamicSharedMemorySize, DS3);
    cudaFuncSetAttribute(mma_gemm<1,1,0>, cudaFuncAttributeMaxDynamicSharedMemorySize, DS3);
    cudaFuncSetAttribute(mma_gemm<0,1,2>, cudaFuncAttributeMaxDynamicSharedMemorySize, DS1);
    cudaFuncSetAttribute(mma_gemm<0,1,0>, cudaFuncAttributeMaxDynamicSharedMemorySize, DS1);
    cudaFuncSetAttribute(mma_gemm<0,0,0>, cudaFuncAttributeMaxDynamicSharedMemorySize, DS1);

    // operand preparation
    split_kernel<<<(NTOK * CDIM / 4 + 255) / 256, 256>>>(x, xh, xl, NTOK * CDIM / 4);
    transpose_kernel<0><<<dim3(HDIM/32, CDIM/32, 1), dim3(32, 8)>>>(rw1, rw1th, rw1tl, CDIM, HDIM);
    transpose_kernel<0><<<dim3(HDIM/32, HDIM/32, 1), dim3(32, 8)>>>(rw2, rw2th, rw2tl, HDIM, HDIM);
    transpose_kernel<1><<<dim3(HDIM/32, CDIM/32, EXPN), dim3(32, 8)>>>(ew1, ew1t, nullptr, CDIM, HDIM);
    transpose_kernel<1><<<dim3(CDIM/32, HDIM/32, EXPN), dim3(32, 8)>>>(ew2, ew2t, nullptr, HDIM, CDIM);

    // router MLP in 1xTF32 (fast approx; decisions fixed below)
    mma_gemm<0,1,2><<<dim3(HDIM/128, NTOK/128, 1), 256, DS1>>>(
        xh, nullptr, rw1th, nullptr, rb1, h1r, nullptr, nullptr, CDIM, HDIM, 0, 0, 0, 0);
    mma_gemm<0,1,0><<<dim3(HDIM/128, NTOK/128, 1), 256, DS1>>>(
        h1r, nullptr, rw2th, nullptr, rb2, h2, nullptr, nullptr, HDIM, HDIM, 0, 0, 0, 0);

    reset_cnt_kernel<<<1, 1>>>(cnt);
    router_topk_kernel<<<NTOK, 256>>>(h2, rw3, rb3, eid, prob, list, cnt);

    // exact (3xTF32) recheck of marginal tokens, early-exit on count
    gather_kernel<<<RCAP, 256>>>(xh, xl, list, cnt, gxh, gxl);
    mma_gemm<1,1,1><<<dim3(HDIM/128, RCAP/128, 1), 256, DS3>>>(
        gxh, gxl, rw1th, rw1tl, rb1, grh1h, grh1l, cnt, CDIM, HDIM, 0, 0, 0, 0);
    mma_gemm<1,1,0><<<dim3(HDIM/128, RCAP/128, 1), 256, DS3>>>(
        grh1h, grh1l, rw2th, rw2tl, rb2, grh2, nullptr, cnt, HDIM, HDIM, 0, 0, 0, 0);
    fix_topk_kernel<<<RCAP, 256>>>(grh2, rw3, rb3, list, cnt, eid, prob);

    positions_kernel<<<1, 1024>>>(eid, pos);
    dispatch_kernel<<<NFLAT, 256>>>(x, eid, pos, disp);

    // expert FFNs (1xTF32)
    mma_gemm<0,1,2><<<dim3(HDIM/128, CAPN/128, EXPN), 256, DS1>>>(
        disp, nullptr, ew1t, nullptr, eb1, eh, nullptr, nullptr, CDIM, HDIM,
        (long long)CAPN * CDIM, (long long)HDIM * CDIM, HDIM, (long long)CAPN * HDIM);
    mma_gemm<0,0,0><<<dim3(CDIM/128, CAPN/128, EXPN), 256, DS1>>>(
        eh, nullptr, ew2t, nullptr, eb2, eo, nullptr, nullptr, HDIM, CDIM,
        (long long)CAPN * HDIM, (long long)CDIM * HDIM, CDIM, (long long)CAPN * CDIM);

    // combine
    combine_kernel<<<NTOK, 256>>>(eo, eid, prob, pos, out);
}

// round 13
// speedup vs baseline: 1.6848x; 1.0203x over previous
#include <cuda_runtime.h>
#include <cstdint>
#include <math.h>

// Problem constants
#define NTOK 8192
#define CDIM 1024
#define HDIM 4096
#define EXPN 8
#define KSEL 2
#define CAPN 2048
#define NFLAT (NTOK*KSEL)
#define RCAP 2048               // recheck batch capacity (rows)
#define MARGIN 0.008f           // logit-gap threshold for exact recheck

// GEMM tiling: CTA 128x128, BK=32, 256 threads, warp tile 64x32 (2x4 warps)
#define BK2 32
#define RP 36
#define TILEF (128*RP)

// ---------------- scratch ----------------------------------------------------
__device__ float g_xh[(size_t)NTOK * CDIM];
__device__ float g_xl[(size_t)NTOK * CDIM];
__device__ float g_h1r[(size_t)NTOK * HDIM];
__device__ float g_h2[(size_t)NTOK * HDIM];
__device__ int   g_eid[NFLAT];
__device__ float g_prob[NFLAT];
__device__ int   g_pos[NFLAT];
__device__ float g_disp[(size_t)EXPN * CAPN * CDIM];
__device__ float g_eh[(size_t)EXPN * CAPN * HDIM];
__device__ float g_eo[(size_t)EXPN * CAPN * CDIM];
__device__ float g_rw1th[(size_t)HDIM * CDIM];
__device__ float g_rw1tl[(size_t)HDIM * CDIM];
__device__ float g_rw2th[(size_t)HDIM * HDIM];
__device__ float g_rw2tl[(size_t)HDIM * HDIM];
__device__ float g_ew1t[(size_t)EXPN * HDIM * CDIM];
__device__ float g_ew2t[(size_t)EXPN * CDIM * HDIM];
// recheck scratch
__device__ int   g_list[RCAP];
__device__ int   g_cnt;
__device__ float g_gxh[(size_t)RCAP * CDIM];
__device__ float g_gxl[(size_t)RCAP * CDIM];
__device__ float g_grh1h[(size_t)RCAP * HDIM];
__device__ float g_grh1l[(size_t)RCAP * HDIM];
__device__ float g_grh2[(size_t)RCAP * HDIM];

// ---------------- helpers ------------------------------------------------
__device__ __forceinline__ uint32_t f2tf32_rna(float x) {
    uint32_t u;
    asm("cvt.rna.tf32.f32 %0, %1;" : "=r"(u) : "f"(x));
    return u;
}
__device__ __forceinline__ uint32_t smem_u32(const void* p) {
    uint32_t a;
    asm("{ .reg .u64 t; cvta.to.shared.u64 t, %1; cvt.u32.u64 %0, t; }" : "=r"(a) : "l"(p));
    return a;
}
__device__ __forceinline__ void cp16(uint32_t s, const float* g) {
    asm volatile("cp.async.cg.shared.global [%0], [%1], 16;" :: "r"(s), "l"(g));
}
__device__ __forceinline__ void cp_commit() {
    asm volatile("cp.async.commit_group;" ::: "memory");
}
template <int N> __device__ __forceinline__ void cp_wait() {
    asm volatile("cp.async.wait_group %0;" :: "n"(N) : "memory");
}

#define MMA_TF32(d, a, b) \
    asm volatile( \
        "mma.sync.aligned.m16n8k8.row.col.f32.tf32.tf32.f32 " \
        "{%0,%1,%2,%3}, {%4,%5,%6,%7}, {%8,%9}, {%0,%1,%2,%3};" \
        : "+f"((d)[0]), "+f"((d)[1]), "+f"((d)[2]), "+f"((d)[3]) \
        : "r"((a)[0]), "r"((a)[1]), "r"((a)[2]), "r"((a)[3]), \
          "r"((b)[0]), "r"((b)[1]))

// ldmatrix x4 of b16 == four 8x8 b32 quadrants (tf32 bit-moves)
#define LDSM_X4(r, a) \
    asm volatile("ldmatrix.sync.aligned.m8n8.x4.shared.b16 {%0,%1,%2,%3}, [%4];" \
        : "=r"((r)[0]), "=r"((r)[1]), "=r"((r)[2]), "=r"((r)[3]) : "r"(a))

// ---------------- TF32 mma.sync GEMM (pre-converted operands) ----------------
// NSTT: cp.async stages. MINB: min blocks/SM (occupancy hint / reg cap).
template <int PASS3, int RELU, int WMODE, int NSTT, int MINB>
__global__ __launch_bounds__(256, MINB)
void mma_gemm(const float* __restrict__ Ah, const float* __restrict__ Al,
              const float* __restrict__ Bh, const float* __restrict__ Bl,
              const float* __restrict__ bias, float* __restrict__ C,
              float* __restrict__ Cl, const int* __restrict__ mrows,
              int Kd, int Nn,
              long long aB, long long bB, long long biasB, long long cB)
{
    if (mrows && (int)(blockIdx.y * 128) >= *mrows) return;

    extern __shared__ float sm[];
    constexpr int AHo = 0;
    constexpr int BHo = TILEF;
    constexpr int ALo = 2 * TILEF;
    constexpr int BLo = 3 * TILEF;
    constexpr int STG = (PASS3 ? 4 : 2) * TILEF;

    const int tid = threadIdx.x;
    const int z = blockIdx.z;
    Ah += (size_t)z * aB;
    Bh += (size_t)z * bB;
    if (PASS3) { Al += (size_t)z * aB; Bl += (size_t)z * bB; }
    bias += (size_t)z * biasB;
    C    += (size_t)z * cB;
    if (WMODE == 1) Cl += (size_t)z * cB;
    const int m0 = blockIdx.y * 128;
    const int n0 = blockIdx.x * 128;

    const int warp = tid >> 5;
    const int lane = tid & 31;
    const int wm = warp >> 2;
    const int wn = warp & 3;
    const int g4 = lane >> 2;
    const int t4 = lane & 3;

    const uint32_t smb = smem_u32(sm);
    const int nk = Kd / BK2;

    const uint32_t aFrag = (uint32_t)(((wm * 64 + (lane & 15)) * RP + ((lane >> 4) << 2)) * 4);
    const uint32_t bFrag = (uint32_t)(((wn * 32 + (lane & 7) + ((lane >> 3) & 1) * 8) * RP
                                      + ((lane >> 4) << 2)) * 4);

    int lrow[4], lc4[4];
#pragma unroll
    for (int t = 0; t < 4; t++) {
        int id = tid + 256 * t;
        lrow[t] = id >> 3;
        lc4[t] = (id & 7) * 4;
    }

    auto ISSUE = [&](int s) {
        const int buf = s % NSTT;
        const uint32_t sb = smb + (uint32_t)buf * STG * 4;
        const size_t ko = (size_t)s * BK2;
#pragma unroll
        for (int t = 0; t < 4; t++) {
            const size_t go = (size_t)lrow[t] * Kd + ko + lc4[t];
            const uint32_t so = (uint32_t)(lrow[t] * RP + lc4[t]) * 4;
            cp16(sb + AHo * 4 + so, Ah + (size_t)m0 * Kd + go);
            cp16(sb + BHo * 4 + so, Bh + (size_t)n0 * Kd + go);
            if (PASS3) {
                cp16(sb + ALo * 4 + so, Al + (size_t)m0 * Kd + go);
                cp16(sb + BLo * 4 + so, Bl + (size_t)n0 * Kd + go);
            }
        }
    };

    float d[4][4][4];
#pragma unroll
    for (int i = 0; i < 4; i++)
#pragma unroll
        for (int j = 0; j < 4; j++)
#pragma unroll
            for (int q = 0; q < 4; q++) d[i][j][q] = 0.f;

    // prologue
    ISSUE(0); cp_commit();
    if (NSTT >= 3) {
        if (nk > 1) ISSUE(1);
        cp_commit();
    }

    for (int s = 0; s < nk; s++) {
        if (NSTT >= 3) {
            cp_wait<1>();
            __syncthreads();
            if (s + 2 < nk) ISSUE(s + 2);
            cp_commit();
        } else {
            cp_wait<0>();
            __syncthreads();
            if (s + 1 < nk) ISSUE(s + 1);
            cp_commit();
        }

        const uint32_t sb32 = smb + (uint32_t)(s % NSTT) * STG * 4;
#pragma unroll
        for (int kk = 0; kk < 4; kk++) {
            const uint32_t cOff = (uint32_t)kk * 32;   // kk*8 floats
            uint32_t ah[4][4], bh[4][2];
#pragma unroll
            for (int i = 0; i < 4; i++)
                LDSM_X4(ah[i], sb32 + AHo * 4 + aFrag + (uint32_t)(i * 16 * RP * 4) + cOff);
#pragma unroll
            for (int j2 = 0; j2 < 2; j2++) {
                uint32_t t[4];
                LDSM_X4(t, sb32 + BHo * 4 + bFrag + (uint32_t)(j2 * 16 * RP * 4) + cOff);
                bh[j2 * 2][0] = t[0]; bh[j2 * 2 + 1][0] = t[1];
                bh[j2 * 2][1] = t[2]; bh[j2 * 2 + 1][1] = t[3];
            }
#pragma unroll
            for (int i = 0; i < 4; i++)
#pragma unroll
                for (int j = 0; j < 4; j++) MMA_TF32(d[i][j], ah[i], bh[j]);

            if (PASS3) {
                uint32_t al[4][4], bl[4][2];
#pragma unroll
                for (int i = 0; i < 4; i++)
                    LDSM_X4(al[i], sb32 + ALo * 4 + aFrag + (uint32_t)(i * 16 * RP * 4) + cOff);
#pragma unroll
                for (int j2 = 0; j2 < 2; j2++) {
                    uint32_t t[4];
                    LDSM_X4(t, sb32 + BLo * 4 + bFrag + (uint32_t)(j2 * 16 * RP * 4) + cOff);
                    bl[j2 * 2][0] = t[0]; bl[j2 * 2 + 1][0] = t[1];
                    bl[j2 * 2][1] = t[2]; bl[j2 * 2 + 1][1] = t[3];
                }
#pragma unroll
                for (int i = 0; i < 4; i++)
#pragma unroll
                    for (int j = 0; j < 4; j++) {
                        MMA_TF32(d[i][j], ah[i], bl[j]);
                        MMA_TF32(d[i][j], al[i], bh[j]);
                    }
            }
        }
    }

    // epilogue
#pragma unroll
    for (int i = 0; i < 4; i++) {
        int r0 = m0 + wm * 64 + i * 16 + g4;
#pragma unroll
        for (int j = 0; j < 4; j++) {
            int col = n0 + wn * 32 + j * 8 + t4 * 2;
            float2 bv = *(const float2*)(bias + col);
            float vv[4];
            vv[0] = d[i][j][0] + bv.x; vv[1] = d[i][j][1] + bv.y;
            vv[2] = d[i][j][2] + bv.x; vv[3] = d[i][j][3] + bv.y;
            if (RELU) {
#pragma unroll
                for (int q = 0; q < 4; q++) vv[q] = fmaxf(vv[q], 0.f);
            }
            size_t o0 = (size_t)r0 * Nn + col;
            size_t o1 = (size_t)(r0 + 8) * Nn + col;
            if (WMODE == 0) {
                *(float2*)(C + o0) = make_float2(vv[0], vv[1]);
                *(float2*)(C + o1) = make_float2(vv[2], vv[3]);
            } else if (WMODE == 2) {
                float2 h0, h1;
                h0.x = __uint_as_float(f2tf32_rna(vv[0]));
                h0.y = __uint_as_float(f2tf32_rna(vv[1]));
                h1.x = __uint_as_float(f2tf32_rna(vv[2]));
                h1.y = __uint_as_float(f2tf32_rna(vv[3]));
                *(float2*)(C + o0) = h0;
                *(float2*)(C + o1) = h1;
            } else {
                float2 h0, h1, l0, l1;
                h0.x = __uint_as_float(f2tf32_rna(vv[0]));
                h0.y = __uint_as_float(f2tf32_rna(vv[1]));
                h1.x = __uint_as_float(f2tf32_rna(vv[2]));
                h1.y = __uint_as_float(f2tf32_rna(vv[3]));
                l0.x = vv[0] - h0.x; l0.y = vv[1] - h0.y;
                l1.x = vv[2] - h1.x; l1.y = vv[3] - h1.y;
                *(float2*)(C + o0)  = h0;
                *(float2*)(C + o1)  = h1;
                *(float2*)(Cl + o0) = l0;
                *(float2*)(Cl + o1) = l1;
            }
        }
    }
}

// ---------------- elementwise split ------------------------------------------
__global__ __launch_bounds__(256) void split_kernel(
    const float* __restrict__ src, float* __restrict__ dh, float* __restrict__ dl,
    int n4)
{
    int i = blockIdx.x * blockDim.x + threadIdx.x;
    if (i >= n4) return;
    float4 v = ((const float4*)src)[i];
    float4 h, l;
    h.x = __uint_as_float(f2tf32_rna(v.x)); l.x = v.x - h.x;
    h.y = __uint_as_float(f2tf32_rna(v.y)); l.y = v.y - h.y;
    h.z = __uint_as_float(f2tf32_rna(v.z)); l.z = v.z - h.z;
    h.w = __uint_as_float(f2tf32_rna(v.w)); l.w = v.w - h.w;
    ((float4*)dh)[i] = h;
    ((float4*)dl)[i] = l;
}

// ------------- weight transpose, MODE: 0 split, 1 rna ------------------------
template <int MODE>
__global__ __launch_bounds__(256) void transpose_kernel(
    const float* __restrict__ src, float* __restrict__ dh, float* __restrict__ dl,
    int R, int Cc)
{
    __shared__ float tile[32][33];
    size_t off = (size_t)blockIdx.z * R * Cc;
    int c0 = blockIdx.x * 32, r0 = blockIdx.y * 32;
    int tx = threadIdx.x, ty = threadIdx.y;
#pragma unroll
    for (int i = 0; i < 4; i++)
        tile[ty + i * 8][tx] = src[off + (size_t)(r0 + ty + i * 8) * Cc + c0 + tx];
    __syncthreads();
#pragma unroll
    for (int i = 0; i < 4; i++) {
        float v = tile[tx][ty + i * 8];
        float h = __uint_as_float(f2tf32_rna(v));
        size_t o = off + (size_t)(c0 + ty + i * 8) * R + r0 + tx;
        dh[o] = h;
        if (MODE == 0) dl[o] = v - h;
    }
}

// ---------------- router head: logits + softmax + top-2 + margin flag --------
__global__ __launch_bounds__(256) void router_topk_kernel(
    const float* __restrict__ h2, const float* __restrict__ rw3,
    const float* __restrict__ rb3, int* __restrict__ eid,
    float* __restrict__ prob, int* __restrict__ list, int* __restrict__ cnt)
{
    __shared__ __align__(16) float sh[HDIM];
    __shared__ float slog[EXPN];
    const int t = blockIdx.x;

    const float4* src = (const float4*)(h2 + (size_t)t * HDIM);
    float4* dst4 = (float4*)sh;
    for (int i = threadIdx.x; i < HDIM / 4; i += 256) dst4[i] = src[i];
    __syncthreads();

    const int w = threadIdx.x >> 5;
    const int lane = threadIdx.x & 31;
    if (w < EXPN) {
        float s = 0.f;
        for (int j = lane; j < HDIM; j += 32) s += sh[j] * rw3[(size_t)j * EXPN + w];
#pragma unroll
        for (int o = 16; o > 0; o >>= 1) s += __shfl_down_sync(0xffffffffu, s, o);
        if (lane == 0) slog[w] = s + rb3[w];
    }
    __syncthreads();

    if (threadIdx.x == 0) {
        float l[EXPN], p[EXPN];
        float mx = -1e30f;
#pragma unroll
        for (int e = 0; e < EXPN; e++) { l[e] = slog[e]; mx = fmaxf(mx, l[e]); }
        float se = 0.f;
#pragma unroll
        for (int e = 0; e < EXPN; e++) { p[e] = expf(l[e] - mx); se += p[e]; }
        float inv = 1.f / se;
#pragma unroll
        for (int e = 0; e < EXPN; e++) p[e] *= inv;
        int b1 = 0;
#pragma unroll
        for (int e = 1; e < EXPN; e++) if (l[e] > l[b1]) b1 = e;
        int b2 = (b1 == 0) ? 1 : 0;
#pragma unroll
        for (int e = 0; e < EXPN; e++)
            if (e != b1 && l[e] > l[b2]) b2 = e;
        int b3 = -1;
#pragma unroll
        for (int e = 0; e < EXPN; e++)
            if (e != b1 && e != b2 && (b3 < 0 || l[e] > l[b3])) b3 = e;
        eid[t * 2 + 0] = b1; prob[t * 2 + 0] = p[b1];
        eid[t * 2 + 1] = b2; prob[t * 2 + 1] = p[b2];
        if (l[b2] - l[b3] < MARGIN) {
            int idx = atomicAdd(cnt, 1);
            if (idx < RCAP) list[idx] = t;
        }
    }
}

__global__ void reset_cnt_kernel(int* c) { *c = 0; }

// ------------- gather marginal tokens' split x into compact batch ------------
__global__ __launch_bounds__(256) void gather_kernel(
    const float* __restrict__ xh, const float* __restrict__ xl,
    const int* __restrict__ list, const int* __restrict__ cnt,
    float* __restrict__ gxh, float* __restrict__ gxl)
{
    const int i = blockIdx.x;
    const int n = min(*cnt, RCAP);
    float4* dh = (float4*)(gxh + (size_t)i * CDIM);
    float4* dl = (float4*)(gxl + (size_t)i * CDIM);
    if (i < n) {
        const int t = list[i];
        dh[threadIdx.x] = ((const float4*)(xh + (size_t)t * CDIM))[threadIdx.x];
        dl[threadIdx.x] = ((const float4*)(xl + (size_t)t * CDIM))[threadIdx.x];
    } else {
        float4 z = make_float4(0.f, 0.f, 0.f, 0.f);
        dh[threadIdx.x] = z;
        dl[threadIdx.x] = z;
    }
}

// ------------- exact top-2 fix for marginal tokens ----------------------------
__global__ __launch_bounds__(256) void fix_topk_kernel(
    const float* __restrict__ grh2, const float* __restrict__ rw3,
    const float* __restrict__ rb3, const int* __restrict__ list,
    const int* __restrict__ cnt, int* __restrict__ eid, float* __restrict__ prob)
{
    const int i = blockIdx.x;
    if (i >= min(*cnt, RCAP)) return;
    __shared__ __align__(16) float sh[HDIM];
    __shared__ float slog[EXPN];

    const float4* src = (const float4*)(grh2 + (size_t)i * HDIM);
    float4* dst4 = (float4*)sh;
    for (int k = threadIdx.x; k < HDIM / 4; k += 256) dst4[k] = src[k];
    __syncthreads();

    const int w = threadIdx.x >> 5;
    const int lane = threadIdx.x & 31;
    if (w < EXPN) {
        float s = 0.f;
        for (int j = lane; j < HDIM; j += 32) s += sh[j] * rw3[(size_t)j * EXPN + w];
#pragma unroll
        for (int o = 16; o > 0; o >>= 1) s += __shfl_down_sync(0xffffffffu, s, o);
        if (lane == 0) slog[w] = s + rb3[w];
    }
    __syncthreads();

    if (threadIdx.x == 0) {
        const int t = list[i];
        float l[EXPN], p[EXPN];
        float mx = -1e30f;
#pragma unroll
        for (int e = 0; e < EXPN; e++) { l[e] = slog[e]; mx = fmaxf(mx, l[e]); }
        float se = 0.f;
#pragma unroll
        for (int e = 0; e < EXPN; e++) { p[e] = expf(l[e] - mx); se += p[e]; }
        float inv = 1.f / se;
#pragma unroll
        for (int e = 0; e < EXPN; e++) p[e] *= inv;
        int b1 = 0;
#pragma unroll
        for (int e = 1; e < EXPN; e++) if (l[e] > l[b1]) b1 = e;
        int b2 = (b1 == 0) ? 1 : 0;
#pragma unroll
        for (int e = 0; e < EXPN; e++)
            if (e != b1 && l[e] > l[b2]) b2 = e;
        eid[t * 2 + 0] = b1; prob[t * 2 + 0] = p[b1];
        eid[t * 2 + 1] = b2; prob[t * 2 + 1] = p[b2];
    }
}

// ---- exact flattened-order per-expert ranks ---------------------------------
__global__ __launch_bounds__(1024) void positions_kernel(
    const int* __restrict__ eid, int* __restrict__ pos)
{
    __shared__ int base[EXPN];
    __shared__ int wcnt[32][EXPN];
    const int tid = threadIdx.x;
    const int lane = tid & 31;
    const int w = tid >> 5;

    if (tid < EXPN) base[tid] = 0;
    __syncthreads();

    for (int c = 0; c < NFLAT; c += 1024) {
        if (tid < 32 * EXPN) ((int*)wcnt)[tid] = 0;
        __syncthreads();

        int e = eid[c + tid];
        unsigned m = __match_any_sync(0xffffffffu, e);
        int rank = __popc(m & ((1u << lane) - 1u));
        int leader = __ffs(m) - 1;
        if (lane == leader) wcnt[w][e] = __popc(m);
        __syncthreads();

        int off = base[e] + rank;
        for (int w2 = 0; w2 < 32; w2++)
            if (w2 < w) off += wcnt[w2][e];
        pos[c + tid] = off;
        __syncthreads();

        if (tid < EXPN) {
            int s = 0;
#pragma unroll
            for (int w2 = 0; w2 < 32; w2++) s += wcnt[w2][tid];
            base[tid] += s;
        }
        __syncthreads();
    }
}

// dispatch: scatter rna(x) rows into expert buffers
__global__ __launch_bounds__(256) void dispatch_kernel(
    const float* __restrict__ x, const int* __restrict__ eid,
    const int* __restrict__ pos, float* __restrict__ disp)
{
    const int i = blockIdx.x;
    const int p = pos[i];
    if (p >= CAPN) return;
    const int e = eid[i];
    const int token = i >> 1;
    const float4* src = (const float4*)(x + (size_t)token * CDIM);
    float4* dst = (float4*)(disp + ((size_t)e * CAPN + p) * CDIM);
    float4 v = src[threadIdx.x];
    v.x = __uint_as_float(f2tf32_rna(v.x));
    v.y = __uint_as_float(f2tf32_rna(v.y));
    v.z = __uint_as_float(f2tf32_rna(v.z));
    v.w = __uint_as_float(f2tf32_rna(v.w));
    dst[threadIdx.x] = v;
}

__global__ __launch_bounds__(256) void combine_kernel(
    const float* __restrict__ eo, const int* __restrict__ eid,
    const float* __restrict__ prob, const int* __restrict__ pos,
    float* __restrict__ out)
{
    const int t = blockIdx.x;
    const int e1 = eid[t * 2 + 0], e2 = eid[t * 2 + 1];
    const int p1 = pos[t * 2 + 0], p2 = pos[t * 2 + 1];
    const float w1 = prob[t * 2 + 0] * (p1 < CAPN ? 1.f : 0.f);
    const float w2 = prob[t * 2 + 1] * (p2 < CAPN ? 1.f : 0.f);
    const int g1 = min(p1, CAPN - 1), g2 = min(p2, CAPN - 1);

    const float4* r1 = (const float4*)(eo + ((size_t)e1 * CAPN + g1) * CDIM);
    const float4* r2 = (const float4*)(eo + ((size_t)e2 * CAPN + g2) * CDIM);
    float4 a = r1[threadIdx.x];
    float4 b = r2[threadIdx.x];
    float4 v;
    v.x = w1 * a.x + w2 * b.x;
    v.y = w1 * a.y + w2 * b.y;
    v.z = w1 * a.z + w2 * b.z;
    v.w = w1 * a.w + w2 * b.w;
    ((float4*)(out + (size_t)t * CDIM))[threadIdx.x] = v;
}

// ---------------- launch -----------------------------------------------------
extern "C" void kernel_launch(void* const* d_in, const int* in_sizes, int n_in,
                              void* d_out, int out_size)
{
    const float* x   = (const float*)d_in[0];
    const float* rw1 = (const float*)d_in[1];
    const float* rb1 = (const float*)d_in[2];
    const float* rw2 = (const float*)d_in[3];
    const float* rb2 = (const float*)d_in[4];
    const float* rw3 = (const float*)d_in[5];
    const float* rb3 = (const float*)d_in[6];
    const float* ew1 = (const float*)d_in[7];
    const float* eb1 = (const float*)d_in[8];
    const float* ew2 = (const float*)d_in[9];
    const float* eb2 = (const float*)d_in[10];
    float* out = (float*)d_out;
    (void)in_sizes; (void)n_in; (void)out_size;

    float *xh, *xl, *h1r, *h2, *disp, *eh, *eo, *prob;
    float *rw1th, *rw1tl, *rw2th, *rw2tl, *ew1t, *ew2t;
    float *gxh, *gxl, *grh1h, *grh1l, *grh2;
    int *eid, *pos, *list, *cnt;
    cudaGetSymbolAddress((void**)&xh,    g_xh);
    cudaGetSymbolAddress((void**)&xl,    g_xl);
    cudaGetSymbolAddress((void**)&h1r,   g_h1r);
    cudaGetSymbolAddress((void**)&h2,    g_h2);
    cudaGetSymbolAddress((void**)&disp,  g_disp);
    cudaGetSymbolAddress((void**)&eh,    g_eh);
    cudaGetSymbolAddress((void**)&eo,    g_eo);
    cudaGetSymbolAddress((void**)&eid,   g_eid);
    cudaGetSymbolAddress((void**)&prob,  g_prob);
    cudaGetSymbolAddress((void**)&pos,   g_pos);
    cudaGetSymbolAddress((void**)&rw1th, g_rw1th);
    cudaGetSymbolAddress((void**)&rw1tl, g_rw1tl);
    cudaGetSymbolAddress((void**)&rw2th, g_rw2th);
    cudaGetSymbolAddress((void**)&rw2tl, g_rw2tl);
    cudaGetSymbolAddress((void**)&ew1t,  g_ew1t);
    cudaGetSymbolAddress((void**)&ew2t,  g_ew2t);
    cudaGetSymbolAddress((void**)&gxh,   g_gxh);
    cudaGetSymbolAddress((void**)&gxl,   g_gxl);
    cudaGetSymbolAddress((void**)&grh1h, g_grh1h);
    cudaGetSymbolAddress((void**)&grh1l, g_grh1l);
    cudaGetSymbolAddress((void**)&grh2,  g_grh2);
    cudaGetSymbolAddress((void**)&list,  g_list);
    cudaGetSymbolAddress((void**)&cnt,   g_cnt);

    const int DS3 = 4 * TILEF * 3 * 4;   // 3-pass: 3 stages of (AH,BH,AL,BL)
    const int DS1 = 2 * TILEF * 2 * 4;   // 1-pass: 2 stages of (AH,BH) -> occ 2
    cudaFuncSetAttribute((const void*)mma_gemm<1,1,1,3,1>, cudaFuncAttributeMaxDynamicSharedMemorySize, DS3);
    cudaFuncSetAttribute((const void*)mma_gemm<1,1,0,3,1>, cudaFuncAttributeMaxDynamicSharedMemorySize, DS3);
    cudaFuncSetAttribute((const void*)mma_gemm<0,1,2,2,2>, cudaFuncAttributeMaxDynamicSharedMemorySize, DS1);
    cudaFuncSetAttribute((const void*)mma_gemm<0,1,0,2,2>, cudaFuncAttributeMaxDynamicSharedMemorySize, DS1);
    cudaFuncSetAttribute((const void*)mma_gemm<0,0,0,2,2>, cudaFuncAttributeMaxDynamicSharedMemorySize, DS1);

    // operand preparation
    split_kernel<<<(NTOK * CDIM / 4 + 255) / 256, 256>>>(x, xh, xl, NTOK * CDIM / 4);
    transpose_kernel<0><<<dim3(HDIM/32, CDIM/32, 1), dim3(32, 8)>>>(rw1, rw1th, rw1tl, CDIM, HDIM);
    transpose_kernel<0><<<dim3(HDIM/32, HDIM/32, 1), dim3(32, 8)>>>(rw2, rw2th, rw2tl, HDIM, HDIM);
    transpose_kernel<1><<<dim3(HDIM/32, CDIM/32, EXPN), dim3(32, 8)>>>(ew1, ew1t, nullptr, CDIM, HDIM);
    transpose_kernel<1><<<dim3(CDIM/32, HDIM/32, EXPN), dim3(32, 8)>>>(ew2, ew2t, nullptr, HDIM, CDIM);

    // router MLP in 1xTF32 (fast approx; decisions fixed below)
    mma_gemm<0,1,2,2,2><<<dim3(HDIM/128, NTOK/128, 1), 256, DS1>>>(
        xh, nullptr, rw1th, nullptr, rb1, h1r, nullptr, nullptr, CDIM, HDIM, 0, 0, 0, 0);
    mma_gemm<0,1,0,2,2><<<dim3(HDIM/128, NTOK/128, 1), 256, DS1>>>(
        h1r, nullptr, rw2th, nullptr, rb2, h2, nullptr, nullptr, HDIM, HDIM, 0, 0, 0, 0);

    reset_cnt_kernel<<<1, 1>>>(cnt);
    router_topk_kernel<<<NTOK, 256>>>(h2, rw3, rb3, eid, prob, list, cnt);

    // exact (3xTF32) recheck of marginal tokens, early-exit on count
    gather_kernel<<<RCAP, 256>>>(xh, xl, list, cnt, gxh, gxl);
    mma_gemm<1,1,1,3,1><<<dim3(HDIM/128, RCAP/128, 1), 256, DS3>>>(
        gxh, gxl, rw1th, rw1tl, rb1, grh1h, grh1l, cnt, CDIM, HDIM, 0, 0, 0, 0);
    mma_gemm<1,1,0,3,1><<<dim3(HDIM/128, RCAP/128, 1), 256, DS3>>>(
        grh1h, grh1l, rw2th, rw2tl, rb2, grh2, nullptr, cnt, HDIM, HDIM, 0, 0, 0, 0);
    fix_topk_kernel<<<RCAP, 256>>>(grh2, rw3, rb3, list, cnt, eid, prob);

    positions_kernel<<<1, 1024>>>(eid, pos);
    dispatch_kernel<<<NFLAT, 256>>>(x, eid, pos, disp);

    // expert FFNs (1xTF32)
    mma_gemm<0,1,2,2,2><<<dim3(HDIM/128, CAPN/128, EXPN), 256, DS1>>>(
        disp, nullptr, ew1t, nullptr, eb1, eh, nullptr, nullptr, CDIM, HDIM,
        (long long)CAPN * CDIM, (long long)HDIM * CDIM, HDIM, (long long)CAPN * HDIM);
    mma_gemm<0,0,0,2,2><<<dim3(CDIM/128, CAPN/128, EXPN), 256, DS1>>>(
        eh, nullptr, ew2t, nullptr, eb2, eo, nullptr, nullptr, HDIM, CDIM,
        (long long)CAPN * HDIM, (long long)CDIM * HDIM, CDIM, (long long)CAPN * CDIM);

    // combine
    combine_kernel<<<NTOK, 256>>>(eo, eid, prob, pos, out);
}

// round 14
// speedup vs baseline: 2.5720x; 1.5266x over previous
#include <cuda_runtime.h>
#include <cuda_fp16.h>
#include <cstdint>
#include <math.h>

// Problem constants
#define NTOK 8192
#define CDIM 1024
#define HDIM 4096
#define EXPN 8
#define KSEL 2
#define CAPN 2048
#define NFLAT (NTOK*KSEL)
#define RCAP 2048               // recheck batch capacity (rows)
#define MARGIN 0.008f           // logit-gap threshold for exact recheck

// tf32 recheck GEMM tiling
#define BK2 32
#define RP 36
#define TILEF (128*RP)

// fp16 GEMM tiling: CTA 128x128, BK=32 halves, pitch 40 halves (80B)
#define RPH 40
#define TILEH (128*RPH)         // halves per tile

// ---------------- scratch ----------------------------------------------------
__device__ float g_xh[(size_t)NTOK * CDIM];
__device__ float g_xl[(size_t)NTOK * CDIM];
__device__ __align__(16) __half g_xhf[(size_t)NTOK * CDIM];
__device__ __align__(16) __half g_h1hf[(size_t)NTOK * HDIM];
__device__ float g_h2[(size_t)NTOK * HDIM];
__device__ int   g_eid[NFLAT];
__device__ float g_prob[NFLAT];
__device__ int   g_pos[NFLAT];
__device__ __align__(16) __half g_disph[(size_t)EXPN * CAPN * CDIM];
__device__ __align__(16) __half g_ehh[(size_t)EXPN * CAPN * HDIM];
__device__ float g_eo[(size_t)EXPN * CAPN * CDIM];
__device__ float g_rw1th[(size_t)HDIM * CDIM];
__device__ float g_rw1tl[(size_t)HDIM * CDIM];
__device__ __align__(16) __half g_rw1hf[(size_t)HDIM * CDIM];
__device__ float g_rw2th[(size_t)HDIM * HDIM];
__device__ float g_rw2tl[(size_t)HDIM * HDIM];
__device__ __align__(16) __half g_rw2hf[(size_t)HDIM * HDIM];
__device__ __align__(16) __half g_ew1hf[(size_t)EXPN * HDIM * CDIM];
__device__ __align__(16) __half g_ew2hf[(size_t)EXPN * CDIM * HDIM];
// recheck scratch
__device__ int   g_list[RCAP];
__device__ int   g_cnt;
__device__ float g_gxh[(size_t)RCAP * CDIM];
__device__ float g_gxl[(size_t)RCAP * CDIM];
__device__ float g_grh1h[(size_t)RCAP * HDIM];
__device__ float g_grh1l[(size_t)RCAP * HDIM];
__device__ float g_grh2[(size_t)RCAP * HDIM];

// ---------------- helpers ------------------------------------------------
__device__ __forceinline__ uint32_t f2tf32_rna(float x) {
    uint32_t u;
    asm("cvt.rna.tf32.f32 %0, %1;" : "=r"(u) : "f"(x));
    return u;
}
__device__ __forceinline__ uint32_t smem_u32(const void* p) {
    uint32_t a;
    asm("{ .reg .u64 t; cvta.to.shared.u64 t, %1; cvt.u32.u64 %0, t; }" : "=r"(a) : "l"(p));
    return a;
}
__device__ __forceinline__ void cp16(uint32_t s, const void* g) {
    asm volatile("cp.async.cg.shared.global [%0], [%1], 16;" :: "r"(s), "l"(g));
}
__device__ __forceinline__ void cp_commit() {
    asm volatile("cp.async.commit_group;" ::: "memory");
}
template <int N> __device__ __forceinline__ void cp_wait() {
    asm volatile("cp.async.wait_group %0;" :: "n"(N) : "memory");
}

#define MMA_TF32(d, a, b) \
    asm volatile( \
        "mma.sync.aligned.m16n8k8.row.col.f32.tf32.tf32.f32 " \
        "{%0,%1,%2,%3}, {%4,%5,%6,%7}, {%8,%9}, {%0,%1,%2,%3};" \
        : "+f"((d)[0]), "+f"((d)[1]), "+f"((d)[2]), "+f"((d)[3]) \
        : "r"((a)[0]), "r"((a)[1]), "r"((a)[2]), "r"((a)[3]), \
          "r"((b)[0]), "r"((b)[1]))

#define MMA_F16(d, a, b) \
    asm volatile( \
        "mma.sync.aligned.m16n8k16.row.col.f32.f16.f16.f32 " \
        "{%0,%1,%2,%3}, {%4,%5,%6,%7}, {%8,%9}, {%0,%1,%2,%3};" \
        : "+f"((d)[0]), "+f"((d)[1]), "+f"((d)[2]), "+f"((d)[3]) \
        : "r"((a)[0]), "r"((a)[1]), "r"((a)[2]), "r"((a)[3]), \
          "r"((b)[0]), "r"((b)[1]))

#define LDSM_X4(r, a) \
    asm volatile("ldmatrix.sync.aligned.m8n8.x4.shared.b16 {%0,%1,%2,%3}, [%4];" \
        : "=r"((r)[0]), "=r"((r)[1]), "=r"((r)[2]), "=r"((r)[3]) : "r"(a))

// ---------------- FP16 mma.sync GEMM (1x precision class == tf32-rna) --------
// A: [M,K] row-major halves. B: [N,K] row-major halves. C = op(A@B^T + bias).
// HOUT: 0 -> fp32 C, 1 -> fp16 C. 2-stage cp.async, occ 2.
template <int RELU, int HOUT>
__global__ __launch_bounds__(256, 2)
void hmma_gemm(const __half* __restrict__ A, const __half* __restrict__ B,
               const float* __restrict__ bias, void* __restrict__ Cv,
               int Kd, int Nn,
               long long aB, long long bB, long long biasB, long long cB)
{
    extern __shared__ __half smh[];
    constexpr int AOf = 0;
    constexpr int BOf = TILEH;
    constexpr int STG = 2 * TILEH;   // halves per stage

    const int tid = threadIdx.x;
    const int z = blockIdx.z;
    A += (size_t)z * aB;
    B += (size_t)z * bB;
    bias += (size_t)z * biasB;
    const int m0 = blockIdx.y * 128;
    const int n0 = blockIdx.x * 128;

    const int warp = tid >> 5;
    const int lane = tid & 31;
    const int wm = warp >> 2;
    const int wn = warp & 3;
    const int g4 = lane >> 2;
    const int t4 = lane & 3;

    const uint32_t smb = smem_u32(smh);
    const int nk = Kd / 32;

    // fragment lane addresses (bytes within stage)
    const uint32_t fRow = (uint32_t)((lane & 7) + ((lane >> 3) & 1) * 8);
    const uint32_t fCol = (uint32_t)(lane >> 4) * 8;   // halves
    const uint32_t aFrag = ((wm * 64 + fRow) * RPH + fCol) * 2;
    const uint32_t bFrag = ((wn * 32 + fRow) * RPH + fCol) * 2;

    // loader: 1024 cp16 per stage (A 512 + B 512), 4 per thread
    int lrow[2], lc[2];
#pragma unroll
    for (int t = 0; t < 2; t++) {
        int id = tid + 256 * t;        // 0..511
        lrow[t] = id >> 2;             // 0..127
        lc[t] = (id & 3) * 8;          // halves within 32-half chunk
    }

    auto ISSUE = [&](int s) {
        const uint32_t sb = smb + (uint32_t)(s & 1) * STG * 2;
        const size_t ko = (size_t)s * 32;
#pragma unroll
        for (int t = 0; t < 2; t++) {
            const size_t go = (size_t)lrow[t] * Kd + ko + lc[t];
            const uint32_t so = (uint32_t)(lrow[t] * RPH + lc[t]) * 2;
            cp16(sb + AOf * 2 + so, A + (size_t)m0 * Kd + go);
            cp16(sb + BOf * 2 + so, B + (size_t)n0 * Kd + go);
        }
    };

    float d[4][4][4];
#pragma unroll
    for (int i = 0; i < 4; i++)
#pragma unroll
        for (int j = 0; j < 4; j++)
#pragma unroll
            for (int q = 0; q < 4; q++) d[i][j][q] = 0.f;

    ISSUE(0); cp_commit();

    for (int s = 0; s < nk; s++) {
        cp_wait<0>();
        __syncthreads();
        if (s + 1 < nk) ISSUE(s + 1);
        cp_commit();

        const uint32_t sb = smb + (uint32_t)(s & 1) * STG * 2;
#pragma unroll
        for (int kk = 0; kk < 2; kk++) {
            const uint32_t cOff = (uint32_t)kk * 32;   // 16 halves
            uint32_t a[4][4], b[4][2];
#pragma unroll
            for (int i = 0; i < 4; i++)
                LDSM_X4(a[i], sb + AOf * 2 + aFrag + (uint32_t)(i * 16 * RPH * 2) + cOff);
#pragma unroll
            for (int j2 = 0; j2 < 2; j2++) {
                uint32_t t[4];
                LDSM_X4(t, sb + BOf * 2 + bFrag + (uint32_t)(j2 * 16 * RPH * 2) + cOff);
                b[j2 * 2][0] = t[0]; b[j2 * 2 + 1][0] = t[1];
                b[j2 * 2][1] = t[2]; b[j2 * 2 + 1][1] = t[3];
            }
#pragma unroll
            for (int i = 0; i < 4; i++)
#pragma unroll
                for (int j = 0; j < 4; j++) MMA_F16(d[i][j], a[i], b[j]);
        }
    }

    // epilogue: bias + relu
#pragma unroll
    for (int i = 0; i < 4; i++) {
        int r0 = m0 + wm * 64 + i * 16 + g4;
#pragma unroll
        for (int j = 0; j < 4; j++) {
            int col = n0 + wn * 32 + j * 8 + t4 * 2;
            float2 bv = *(const float2*)(bias + col);
            float vv[4];
            vv[0] = d[i][j][0] + bv.x; vv[1] = d[i][j][1] + bv.y;
            vv[2] = d[i][j][2] + bv.x; vv[3] = d[i][j][3] + bv.y;
            if (RELU) {
#pragma unroll
                for (int q = 0; q < 4; q++) vv[q] = fmaxf(vv[q], 0.f);
            }
            size_t o0 = (size_t)r0 * Nn + col;
            size_t o1 = (size_t)(r0 + 8) * Nn + col;
            if (HOUT) {
                __half* C = (__half*)Cv + (size_t)z * cB;
                *(__half2*)(C + o0) = __floats2half2_rn(vv[0], vv[1]);
                *(__half2*)(C + o1) = __floats2half2_rn(vv[2], vv[3]);
            } else {
                float* C = (float*)Cv + (size_t)z * cB;
                *(float2*)(C + o0) = make_float2(vv[0], vv[1]);
                *(float2*)(C + o1) = make_float2(vv[2], vv[3]);
            }
        }
    }
}

// ---------------- 3xTF32 recheck GEMM (fp32-exact class) ---------------------
// WMODE: 0 plain fp32, 1 write (hi,lo) split.
template <int WMODE>
__global__ __launch_bounds__(256, 1)
void mma_gemm(const float* __restrict__ Ah, const float* __restrict__ Al,
              const float* __restrict__ Bh, const float* __restrict__ Bl,
              const float* __restrict__ bias, float* __restrict__ C,
              float* __restrict__ Cl, const int* __restrict__ mrows,
              int Kd, int Nn)
{
    if (mrows && (int)(blockIdx.y * 128) >= *mrows) return;

    extern __shared__ float sm[];
    constexpr int AHo = 0;
    constexpr int BHo = TILEF;
    constexpr int ALo = 2 * TILEF;
    constexpr int BLo = 3 * TILEF;
    constexpr int STG = 4 * TILEF;
    constexpr int NSTT = 3;

    const int tid = threadIdx.x;
    const int m0 = blockIdx.y * 128;
    const int n0 = blockIdx.x * 128;

    const int warp = tid >> 5;
    const int lane = tid & 31;
    const int wm = warp >> 2;
    const int wn = warp & 3;
    const int g4 = lane >> 2;
    const int t4 = lane & 3;

    const uint32_t smb = smem_u32(sm);
    const int nk = Kd / BK2;

    const uint32_t aFrag = (uint32_t)(((wm * 64 + (lane & 15)) * RP + ((lane >> 4) << 2)) * 4);
    const uint32_t bFrag = (uint32_t)(((wn * 32 + (lane & 7) + ((lane >> 3) & 1) * 8) * RP
                                      + ((lane >> 4) << 2)) * 4);

    int lrow[4], lc4[4];
#pragma unroll
    for (int t = 0; t < 4; t++) {
        int id = tid + 256 * t;
        lrow[t] = id >> 3;
        lc4[t] = (id & 7) * 4;
    }

    auto ISSUE = [&](int s) {
        const int buf = s % NSTT;
        const uint32_t sb = smb + (uint32_t)buf * STG * 4;
        const size_t ko = (size_t)s * BK2;
#pragma unroll
        for (int t = 0; t < 4; t++) {
            const size_t go = (size_t)lrow[t] * Kd + ko + lc4[t];
            const uint32_t so = (uint32_t)(lrow[t] * RP + lc4[t]) * 4;
            cp16(sb + AHo * 4 + so, Ah + (size_t)m0 * Kd + go);
            cp16(sb + BHo * 4 + so, Bh + (size_t)n0 * Kd + go);
            cp16(sb + ALo * 4 + so, Al + (size_t)m0 * Kd + go);
            cp16(sb + BLo * 4 + so, Bl + (size_t)n0 * Kd + go);
        }
    };

    float d[4][4][4];
#pragma unroll
    for (int i = 0; i < 4; i++)
#pragma unroll
        for (int j = 0; j < 4; j++)
#pragma unroll
            for (int q = 0; q < 4; q++) d[i][j][q] = 0.f;

    ISSUE(0); cp_commit();
    if (nk > 1) ISSUE(1);
    cp_commit();

    for (int s = 0; s < nk; s++) {
        cp_wait<1>();
        __syncthreads();
        if (s + 2 < nk) ISSUE(s + 2);
        cp_commit();

        const uint32_t sb32 = smb + (uint32_t)(s % NSTT) * STG * 4;
#pragma unroll
        for (int kk = 0; kk < 4; kk++) {
            const uint32_t cOff = (uint32_t)kk * 32;
            uint32_t ah[4][4], bh[4][2], al[4][4], bl[4][2];
#pragma unroll
            for (int i = 0; i < 4; i++) {
                LDSM_X4(ah[i], sb32 + AHo * 4 + aFrag + (uint32_t)(i * 16 * RP * 4) + cOff);
                LDSM_X4(al[i], sb32 + ALo * 4 + aFrag + (uint32_t)(i * 16 * RP * 4) + cOff);
            }
#pragma unroll
            for (int j2 = 0; j2 < 2; j2++) {
                uint32_t t[4];
                LDSM_X4(t, sb32 + BHo * 4 + bFrag + (uint32_t)(j2 * 16 * RP * 4) + cOff);
                bh[j2 * 2][0] = t[0]; bh[j2 * 2 + 1][0] = t[1];
                bh[j2 * 2][1] = t[2]; bh[j2 * 2 + 1][1] = t[3];
                LDSM_X4(t, sb32 + BLo * 4 + bFrag + (uint32_t)(j2 * 16 * RP * 4) + cOff);
                bl[j2 * 2][0] = t[0]; bl[j2 * 2 + 1][0] = t[1];
                bl[j2 * 2][1] = t[2]; bl[j2 * 2 + 1][1] = t[3];
            }
#pragma unroll
            for (int i = 0; i < 4; i++)
#pragma unroll
                for (int j = 0; j < 4; j++) {
                    MMA_TF32(d[i][j], ah[i], bh[j]);
                    MMA_TF32(d[i][j], ah[i], bl[j]);
                    MMA_TF32(d[i][j], al[i], bh[j]);
                }
        }
    }

    // epilogue: bias + relu
#pragma unroll
    for (int i = 0; i < 4; i++) {
        int r0 = m0 + wm * 64 + i * 16 + g4;
#pragma unroll
        for (int j = 0; j < 4; j++) {
            int col = n0 + wn * 32 + j * 8 + t4 * 2;
            float2 bv = *(const float2*)(bias + col);
            float vv[4];
            vv[0] = fmaxf(d[i][j][0] + bv.x, 0.f);
            vv[1] = fmaxf(d[i][j][1] + bv.y, 0.f);
            vv[2] = fmaxf(d[i][j][2] + bv.x, 0.f);
            vv[3] = fmaxf(d[i][j][3] + bv.y, 0.f);
            size_t o0 = (size_t)r0 * Nn + col;
            size_t o1 = (size_t)(r0 + 8) * Nn + col;
            if (WMODE == 0) {
                *(float2*)(C + o0) = make_float2(vv[0], vv[1]);
                *(float2*)(C + o1) = make_float2(vv[2], vv[3]);
            } else {
                float2 h0, h1, l0, l1;
                h0.x = __uint_as_float(f2tf32_rna(vv[0]));
                h0.y = __uint_as_float(f2tf32_rna(vv[1]));
                h1.x = __uint_as_float(f2tf32_rna(vv[2]));
                h1.y = __uint_as_float(f2tf32_rna(vv[3]));
                l0.x = vv[0] - h0.x; l0.y = vv[1] - h0.y;
                l1.x = vv[2] - h1.x; l1.y = vv[3] - h1.y;
                *(float2*)(C + o0)  = h0;
                *(float2*)(C + o1)  = h1;
                *(float2*)(Cl + o0) = l0;
                *(float2*)(Cl + o1) = l1;
            }
        }
    }
}

// -------- elementwise split: x -> (tf32 hi, lo) fp32 + fp16 copy -------------
__global__ __launch_bounds__(256) void split_kernel(
    const float* __restrict__ src, float* __restrict__ dh, float* __restrict__ dl,
    __half* __restrict__ dhalf, int n4)
{
    int i = blockIdx.x * blockDim.x + threadIdx.x;
    if (i >= n4) return;
    float4 v = ((const float4*)src)[i];
    float4 h, l;
    h.x = __uint_as_float(f2tf32_rna(v.x)); l.x = v.x - h.x;
    h.y = __uint_as_float(f2tf32_rna(v.y)); l.y = v.y - h.y;
    h.z = __uint_as_float(f2tf32_rna(v.z)); l.z = v.z - h.z;
    h.w = __uint_as_float(f2tf32_rna(v.w)); l.w = v.w - h.w;
    ((float4*)dh)[i] = h;
    ((float4*)dl)[i] = l;
    __half2 p0 = __floats2half2_rn(v.x, v.y);
    __half2 p1 = __floats2half2_rn(v.z, v.w);
    ((__half2*)dhalf)[i * 2] = p0;
    ((__half2*)dhalf)[i * 2 + 1] = p1;
}

// ------ weight transpose. MODE 0: split fp32 + fp16; MODE 2: fp16 only -------
template <int MODE>
__global__ __launch_bounds__(256) void transpose_kernel(
    const float* __restrict__ src, float* __restrict__ dh, float* __restrict__ dl,
    __half* __restrict__ dhalf, int R, int Cc)
{
    __shared__ float tile[32][33];
    size_t off = (size_t)blockIdx.z * R * Cc;
    int c0 = blockIdx.x * 32, r0 = blockIdx.y * 32;
    int tx = threadIdx.x, ty = threadIdx.y;
#pragma unroll
    for (int i = 0; i < 4; i++)
        tile[ty + i * 8][tx] = src[off + (size_t)(r0 + ty + i * 8) * Cc + c0 + tx];
    __syncthreads();
#pragma unroll
    for (int i = 0; i < 4; i++) {
        float v = tile[tx][ty + i * 8];
        size_t o = off + (size_t)(c0 + ty + i * 8) * R + r0 + tx;
        dhalf[o] = __float2half_rn(v);
        if (MODE == 0) {
            float h = __uint_as_float(f2tf32_rna(v));
            dh[o] = h;
            dl[o] = v - h;
        }
    }
}

// ---------------- router head: logits + softmax + top-2 + margin flag --------
__global__ __launch_bounds__(256) void router_topk_kernel(
    const float* __restrict__ h2, const float* __restrict__ rw3,
    const float* __restrict__ rb3, int* __restrict__ eid,
    float* __restrict__ prob, int* __restrict__ list, int* __restrict__ cnt)
{
    __shared__ __align__(16) float sh[HDIM];
    __shared__ float slog[EXPN];
    const int t = blockIdx.x;

    const float4* src = (const float4*)(h2 + (size_t)t * HDIM);
    float4* dst4 = (float4*)sh;
    for (int i = threadIdx.x; i < HDIM / 4; i += 256) dst4[i] = src[i];
    __syncthreads();

    const int w = threadIdx.x >> 5;
    const int lane = threadIdx.x & 31;
    if (w < EXPN) {
        float s = 0.f;
        for (int j = lane; j < HDIM; j += 32) s += sh[j] * rw3[(size_t)j * EXPN + w];
#pragma unroll
        for (int o = 16; o > 0; o >>= 1) s += __shfl_down_sync(0xffffffffu, s, o);
        if (lane == 0) slog[w] = s + rb3[w];
    }
    __syncthreads();

    if (threadIdx.x == 0) {
        float l[EXPN], p[EXPN];
        float mx = -1e30f;
#pragma unroll
        for (int e = 0; e < EXPN; e++) { l[e] = slog[e]; mx = fmaxf(mx, l[e]); }
        float se = 0.f;
#pragma unroll
        for (int e = 0; e < EXPN; e++) { p[e] = expf(l[e] - mx); se += p[e]; }
        float inv = 1.f / se;
#pragma unroll
        for (int e = 0; e < EXPN; e++) p[e] *= inv;
        int b1 = 0;
#pragma unroll
        for (int e = 1; e < EXPN; e++) if (l[e] > l[b1]) b1 = e;
        int b2 = (b1 == 0) ? 1 : 0;
#pragma unroll
        for (int e = 0; e < EXPN; e++)
            if (e != b1 && l[e] > l[b2]) b2 = e;
        int b3 = -1;
#pragma unroll
        for (int e = 0; e < EXPN; e++)
            if (e != b1 && e != b2 && (b3 < 0 || l[e] > l[b3])) b3 = e;
        eid[t * 2 + 0] = b1; prob[t * 2 + 0] = p[b1];
        eid[t * 2 + 1] = b2; prob[t * 2 + 1] = p[b2];
        if (l[b2] - l[b3] < MARGIN) {
            int idx = atomicAdd(cnt, 1);
            if (idx < RCAP) list[idx] = t;
        }
    }
}

__global__ void reset_cnt_kernel(int* c) { *c = 0; }

// ------------- gather marginal tokens' split x into compact batch ------------
__global__ __launch_bounds__(256) void gather_kernel(
    const float* __restrict__ xh, const float* __restrict__ xl,
    const int* __restrict__ list, const int* __restrict__ cnt,
    float* __restrict__ gxh, float* __restrict__ gxl)
{
    const int i = blockIdx.x;
    const int n = min(*cnt, RCAP);
    float4* dh = (float4*)(gxh + (size_t)i * CDIM);
    float4* dl = (float4*)(gxl + (size_t)i * CDIM);
    if (i < n) {
        const int t = list[i];
        dh[threadIdx.x] = ((const float4*)(xh + (size_t)t * CDIM))[threadIdx.x];
        dl[threadIdx.x] = ((const float4*)(xl + (size_t)t * CDIM))[threadIdx.x];
    } else {
        float4 z = make_float4(0.f, 0.f, 0.f, 0.f);
        dh[threadIdx.x] = z;
        dl[threadIdx.x] = z;
    }
}

// ------------- exact top-2 fix for marginal tokens ----------------------------
__global__ __launch_bounds__(256) void fix_topk_kernel(
    const float* __restrict__ grh2, const float* __restrict__ rw3,
    const float* __restrict__ rb3, const int* __restrict__ list,
    const int* __restrict__ cnt, int* __restrict__ eid, float* __restrict__ prob)
{
    const int i = blockIdx.x;
    if (i >= min(*cnt, RCAP)) return;
    __shared__ __align__(16) float sh[HDIM];
    __shared__ float slog[EXPN];

    const float4* src = (const float4*)(grh2 + (size_t)i * HDIM);
    float4* dst4 = (float4*)sh;
    for (int k = threadIdx.x; k < HDIM / 4; k += 256) dst4[k] = src[k];
    __syncthreads();

    const int w = threadIdx.x >> 5;
    const int lane = threadIdx.x & 31;
    if (w < EXPN) {
        float s = 0.f;
        for (int j = lane; j < HDIM; j += 32) s += sh[j] * rw3[(size_t)j * EXPN + w];
#pragma unroll
        for (int o = 16; o > 0; o >>= 1) s += __shfl_down_sync(0xffffffffu, s, o);
        if (lane == 0) slog[w] = s + rb3[w];
    }
    __syncthreads();

    if (threadIdx.x == 0) {
        const int t = list[i];
        float l[EXPN], p[EXPN];
        float mx = -1e30f;
#pragma unroll
        for (int e = 0; e < EXPN; e++) { l[e] = slog[e]; mx = fmaxf(mx, l[e]); }
        float se = 0.f;
#pragma unroll
        for (int e = 0; e < EXPN; e++) { p[e] = expf(l[e] - mx); se += p[e]; }
        float inv = 1.f / se;
#pragma unroll
        for (int e = 0; e < EXPN; e++) p[e] *= inv;
        int b1 = 0;
#pragma unroll
        for (int e = 1; e < EXPN; e++) if (l[e] > l[b1]) b1 = e;
        int b2 = (b1 == 0) ? 1 : 0;
#pragma unroll
        for (int e = 0; e < EXPN; e++)
            if (e != b1 && l[e] > l[b2]) b2 = e;
        eid[t * 2 + 0] = b1; prob[t * 2 + 0] = p[b1];
        eid[t * 2 + 1] = b2; prob[t * 2 + 1] = p[b2];
    }
}

// ---- exact flattened-order per-expert ranks ---------------------------------
__global__ __launch_bounds__(1024) void positions_kernel(
    const int* __restrict__ eid, int* __restrict__ pos)
{
    __shared__ int base[EXPN];
    __shared__ int wcnt[32][EXPN];
    const int tid = threadIdx.x;
    const int lane = tid & 31;
    const int w = tid >> 5;

    if (tid < EXPN) base[tid] = 0;
    __syncthreads();

    for (int c = 0; c < NFLAT; c += 1024) {
        if (tid < 32 * EXPN) ((int*)wcnt)[tid] = 0;
        __syncthreads();

        int e = eid[c + tid];
        unsigned m = __match_any_sync(0xffffffffu, e);
        int rank = __popc(m & ((1u << lane) - 1u));
        int leader = __ffs(m) - 1;
        if (lane == leader) wcnt[w][e] = __popc(m);
        __syncthreads();

        int off = base[e] + rank;
        for (int w2 = 0; w2 < 32; w2++)
            if (w2 < w) off += wcnt[w2][e];
        pos[c + tid] = off;
        __syncthreads();

        if (tid < EXPN) {
            int s = 0;
#pragma unroll
            for (int w2 = 0; w2 < 32; w2++) s += wcnt[w2][tid];
            base[tid] += s;
        }
        __syncthreads();
    }
}

// dispatch: scatter fp16(x) rows into expert buffers
__global__ __launch_bounds__(256) void dispatch_kernel(
    const float* __restrict__ x, const int* __restrict__ eid,
    const int* __restrict__ pos, __half* __restrict__ disp)
{
    const int i = blockIdx.x;
    const int p = pos[i];
    if (p >= CAPN) return;
    const int e = eid[i];
    const int token = i >> 1;
    float4 v = ((const float4*)(x + (size_t)token * CDIM))[threadIdx.x];
    __half2* dst = (__half2*)(disp + ((size_t)e * CAPN + p) * CDIM);
    dst[threadIdx.x * 2]     = __floats2half2_rn(v.x, v.y);
    dst[threadIdx.x * 2 + 1] = __floats2half2_rn(v.z, v.w);
}

__global__ __launch_bounds__(256) void combine_kernel(
    const float* __restrict__ eo, const int* __restrict__ eid,
    const float* __restrict__ prob, const int* __restrict__ pos,
    float* __restrict__ out)
{
    const int t = blockIdx.x;
    const int e1 = eid[t * 2 + 0], e2 = eid[t * 2 + 1];
    const int p1 = pos[t * 2 + 0], p2 = pos[t * 2 + 1];
    const float w1 = prob[t * 2 + 0] * (p1 < CAPN ? 1.f : 0.f);
    const float w2 = prob[t * 2 + 1] * (p2 < CAPN ? 1.f : 0.f);
    const int g1 = min(p1, CAPN - 1), g2 = min(p2, CAPN - 1);

    const float4* r1 = (const float4*)(eo + ((size_t)e1 * CAPN + g1) * CDIM);
    const float4* r2 = (const float4*)(eo + ((size_t)e2 * CAPN + g2) * CDIM);
    float4 a = r1[threadIdx.x];
    float4 b = r2[threadIdx.x];
    float4 v;
    v.x = w1 * a.x + w2 * b.x;
    v.y = w1 * a.y + w2 * b.y;
    v.z = w1 * a.z + w2 * b.z;
    v.w = w1 * a.w + w2 * b.w;
    ((float4*)(out + (size_t)t * CDIM))[threadIdx.x] = v;
}

// ---------------- launch -----------------------------------------------------
extern "C" void kernel_launch(void* const* d_in, const int* in_sizes, int n_in,
                              void* d_out, int out_size)
{
    const float* x   = (const float*)d_in[0];
    const float* rw1 = (const float*)d_in[1];
    const float* rb1 = (const float*)d_in[2];
    const float* rw2 = (const float*)d_in[3];
    const float* rb2 = (const float*)d_in[4];
    const float* rw3 = (const float*)d_in[5];
    const float* rb3 = (const float*)d_in[6];
    const float* ew1 = (const float*)d_in[7];
    const float* eb1 = (const float*)d_in[8];
    const float* ew2 = (const float*)d_in[9];
    const float* eb2 = (const float*)d_in[10];
    float* out = (float*)d_out;
    (void)in_sizes; (void)n_in; (void)out_size;

    float *xh, *xl, *h2, *eo, *prob;
    float *rw1th, *rw1tl, *rw2th, *rw2tl;
    float *gxh, *gxl, *grh1h, *grh1l, *grh2;
    __half *xhf, *h1hf, *disph, *ehh, *rw1hf, *rw2hf, *ew1hf, *ew2hf;
    int *eid, *pos, *list, *cnt;
    cudaGetSymbolAddress((void**)&xh,    g_xh);
    cudaGetSymbolAddress((void**)&xl,    g_xl);
    cudaGetSymbolAddress((void**)&xhf,   g_xhf);
    cudaGetSymbolAddress((void**)&h1hf,  g_h1hf);
    cudaGetSymbolAddress((void**)&h2,    g_h2);
    cudaGetSymbolAddress((void**)&disph, g_disph);
    cudaGetSymbolAddress((void**)&ehh,   g_ehh);
    cudaGetSymbolAddress((void**)&eo,    g_eo);
    cudaGetSymbolAddress((void**)&eid,   g_eid);
    cudaGetSymbolAddress((void**)&prob,  g_prob);
    cudaGetSymbolAddress((void**)&pos,   g_pos);
    cudaGetSymbolAddress((void**)&rw1th, g_rw1th);
    cudaGetSymbolAddress((void**)&rw1tl, g_rw1tl);
    cudaGetSymbolAddress((void**)&rw1hf, g_rw1hf);
    cudaGetSymbolAddress((void**)&rw2th, g_rw2th);
    cudaGetSymbolAddress((void**)&rw2tl, g_rw2tl);
    cudaGetSymbolAddress((void**)&rw2hf, g_rw2hf);
    cudaGetSymbolAddress((void**)&ew1hf, g_ew1hf);
    cudaGetSymbolAddress((void**)&ew2hf, g_ew2hf);
    cudaGetSymbolAddress((void**)&gxh,   g_gxh);
    cudaGetSymbolAddress((void**)&gxl,   g_gxl);
    cudaGetSymbolAddress((void**)&grh1h, g_grh1h);
    cudaGetSymbolAddress((void**)&grh1l, g_grh1l);
    cudaGetSymbolAddress((void**)&grh2,  g_grh2);
    cudaGetSymbolAddress((void**)&list,  g_list);
    cudaGetSymbolAddress((void**)&cnt,   g_cnt);

    const int DS3 = 4 * TILEF * 3 * 4;            // tf32 3x recheck: 3 stages
    const int DSH = 2 * TILEH * 2 * 2;            // fp16: 2 stages of (A,B) halves
    cudaFuncSetAttribute((const void*)mma_gemm<1>, cudaFuncAttributeMaxDynamicSharedMemorySize, DS3);
    cudaFuncSetAttribute((const void*)mma_gemm<0>, cudaFuncAttributeMaxDynamicSharedMemorySize, DS3);
    cudaFuncSetAttribute((const void*)hmma_gemm<1,1>, cudaFuncAttributeMaxDynamicSharedMemorySize, DSH);
    cudaFuncSetAttribute((const void*)hmma_gemm<1,0>, cudaFuncAttributeMaxDynamicSharedMemorySize, DSH);
    cudaFuncSetAttribute((const void*)hmma_gemm<0,0>, cudaFuncAttributeMaxDynamicSharedMemorySize, DSH);

    // operand preparation
    split_kernel<<<(NTOK * CDIM / 4 + 255) / 256, 256>>>(x, xh, xl, xhf, NTOK * CDIM / 4);
    transpose_kernel<0><<<dim3(HDIM/32, CDIM/32, 1), dim3(32, 8)>>>(rw1, rw1th, rw1tl, rw1hf, CDIM, HDIM);
    transpose_kernel<0><<<dim3(HDIM/32, HDIM/32, 1), dim3(32, 8)>>>(rw2, rw2th, rw2tl, rw2hf, HDIM, HDIM);
    transpose_kernel<2><<<dim3(HDIM/32, CDIM/32, EXPN), dim3(32, 8)>>>(ew1, nullptr, nullptr, ew1hf, CDIM, HDIM);
    transpose_kernel<2><<<dim3(CDIM/32, HDIM/32, EXPN), dim3(32, 8)>>>(ew2, nullptr, nullptr, ew2hf, HDIM, CDIM);

    // router MLP in fp16 (same 11-bit mantissa class as tf32; decisions fixed below)
    hmma_gemm<1,1><<<dim3(HDIM/128, NTOK/128, 1), 256, DSH>>>(
        xhf, rw1hf, rb1, h1hf, CDIM, HDIM, 0, 0, 0, 0);
    hmma_gemm<1,0><<<dim3(HDIM/128, NTOK/128, 1), 256, DSH>>>(
        h1hf, rw2hf, rb2, h2, HDIM, HDIM, 0, 0, 0, 0);

    reset_cnt_kernel<<<1, 1>>>(cnt);
    router_topk_kernel<<<NTOK, 256>>>(h2, rw3, rb3, eid, prob, list, cnt);

    // exact (3xTF32) recheck of marginal tokens, early-exit on count
    gather_kernel<<<RCAP, 256>>>(xh, xl, list, cnt, gxh, gxl);
    mma_gemm<1><<<dim3(HDIM/128, RCAP/128, 1), 256, DS3>>>(
        gxh, gxl, rw1th, rw1tl, rb1, grh1h, grh1l, cnt, CDIM, HDIM);
    mma_gemm<0><<<dim3(HDIM/128, RCAP/128, 1), 256, DS3>>>(
        grh1h, grh1l, rw2th, rw2tl, rb2, grh2, nullptr, cnt, HDIM, HDIM);
    fix_topk_kernel<<<RCAP, 256>>>(grh2, rw3, rb3, list, cnt, eid, prob);

    positions_kernel<<<1, 1024>>>(eid, pos);
    dispatch_kernel<<<NFLAT, 256>>>(x, eid, pos, disph);

    // expert FFNs in fp16
    hmma_gemm<1,1><<<dim3(HDIM/128, CAPN/128, EXPN), 256, DSH>>>(
        disph, ew1hf, eb1, ehh, CDIM, HDIM,
        (long long)CAPN * CDIM, (long long)HDIM * CDIM, HDIM, (long long)CAPN * HDIM);
    hmma_gemm<0,0><<<dim3(CDIM/128, CAPN/128, EXPN), 256, DSH>>>(
        ehh, ew2hf, eb2, eo, HDIM, CDIM,
        (long long)CAPN * HDIM, (long long)CDIM * HDIM, CDIM, (long long)CAPN * CDIM);

    // combine
    combine_kernel<<<NTOK, 256>>>(eo, eid, prob, pos, out);
}

// round 15
// speedup vs baseline: 2.7627x; 1.0742x over previous
#include <cuda_runtime.h>
#include <cuda_fp16.h>
#include <cstdint>
#include <math.h>

// Problem constants
#define NTOK 8192
#define CDIM 1024
#define HDIM 4096
#define EXPN 8
#define KSEL 2
#define CAPN 2048
#define NFLAT (NTOK*KSEL)
#define RCAP 2048               // recheck batch capacity (rows)
#define MARGIN 0.008f           // logit-gap threshold for exact recheck

// fp16 GEMM tiling: CTA 128x128, BK=32 halves, pitch 40 halves (80B)
#define RPH 40
#define TILEH (128*RPH)         // halves per tile

// ---------------- scratch ----------------------------------------------------
__device__ __align__(16) __half g_xh16[(size_t)NTOK * CDIM];     // hi = fp16(x)
__device__ __align__(16) __half g_xl16[(size_t)NTOK * CDIM];     // lo = fp16(x-hi)
__device__ __align__(16) __half g_h1hf[(size_t)NTOK * HDIM];
__device__ float g_h2[(size_t)NTOK * HDIM];
__device__ int   g_eid[NFLAT];
__device__ float g_prob[NFLAT];
__device__ int   g_pos[NFLAT];
__device__ __align__(16) __half g_disph[(size_t)EXPN * CAPN * CDIM];
__device__ __align__(16) __half g_ehh[(size_t)EXPN * CAPN * HDIM];
__device__ float g_eo[(size_t)EXPN * CAPN * CDIM];
__device__ __align__(16) __half g_rw1h16[(size_t)HDIM * CDIM];
__device__ __align__(16) __half g_rw1l16[(size_t)HDIM * CDIM];
__device__ __align__(16) __half g_rw2h16[(size_t)HDIM * HDIM];
__device__ __align__(16) __half g_rw2l16[(size_t)HDIM * HDIM];
__device__ __align__(16) __half g_ew1hf[(size_t)EXPN * HDIM * CDIM];
__device__ __align__(16) __half g_ew2hf[(size_t)EXPN * CDIM * HDIM];
// recheck scratch
__device__ int   g_list[RCAP];
__device__ int   g_cnt;
__device__ __align__(16) __half g_gxh[(size_t)RCAP * CDIM];
__device__ __align__(16) __half g_gxl[(size_t)RCAP * CDIM];
__device__ __align__(16) __half g_grh1h[(size_t)RCAP * HDIM];
__device__ __align__(16) __half g_grh1l[(size_t)RCAP * HDIM];
__device__ float g_grh2[(size_t)RCAP * HDIM];

// ---------------- helpers ------------------------------------------------
__device__ __forceinline__ uint32_t smem_u32(const void* p) {
    uint32_t a;
    asm("{ .reg .u64 t; cvta.to.shared.u64 t, %1; cvt.u32.u64 %0, t; }" : "=r"(a) : "l"(p));
    return a;
}
__device__ __forceinline__ void cp16(uint32_t s, const void* g) {
    asm volatile("cp.async.cg.shared.global [%0], [%1], 16;" :: "r"(s), "l"(g));
}
__device__ __forceinline__ void cp_commit() {
    asm volatile("cp.async.commit_group;" ::: "memory");
}
template <int N> __device__ __forceinline__ void cp_wait() {
    asm volatile("cp.async.wait_group %0;" :: "n"(N) : "memory");
}

#define MMA_F16(d, a, b) \
    asm volatile( \
        "mma.sync.aligned.m16n8k16.row.col.f32.f16.f16.f32 " \
        "{%0,%1,%2,%3}, {%4,%5,%6,%7}, {%8,%9}, {%0,%1,%2,%3};" \
        : "+f"((d)[0]), "+f"((d)[1]), "+f"((d)[2]), "+f"((d)[3]) \
        : "r"((a)[0]), "r"((a)[1]), "r"((a)[2]), "r"((a)[3]), \
          "r"((b)[0]), "r"((b)[1]))

#define LDSM_X4(r, a) \
    asm volatile("ldmatrix.sync.aligned.m8n8.x4.shared.b16 {%0,%1,%2,%3}, [%4];" \
        : "=r"((r)[0]), "=r"((r)[1]), "=r"((r)[2]), "=r"((r)[3]) : "r"(a))

__device__ __forceinline__ void split16(float v, __half& h, __half& l) {
    h = __float2half_rn(v);
    l = __float2half_rn(v - __half2float(h));
}

// ---------------- FP16 mma.sync GEMM (1x precision class == tf32-rna) --------
// A: [M,K] row-major halves. B: [N,K] row-major halves. C = op(A@B^T + bias).
// HOUT: 0 -> fp32 C, 1 -> fp16 C. 2-stage cp.async, occ 2.
template <int RELU, int HOUT>
__global__ __launch_bounds__(256, 2)
void hmma_gemm(const __half* __restrict__ A, const __half* __restrict__ B,
               const float* __restrict__ bias, void* __restrict__ Cv,
               int Kd, int Nn,
               long long aB, long long bB, long long biasB, long long cB)
{
    extern __shared__ __half smh[];
    constexpr int AOf = 0;
    constexpr int BOf = TILEH;
    constexpr int STG = 2 * TILEH;   // halves per stage

    const int tid = threadIdx.x;
    const int z = blockIdx.z;
    A += (size_t)z * aB;
    B += (size_t)z * bB;
    bias += (size_t)z * biasB;
    const int m0 = blockIdx.y * 128;
    const int n0 = blockIdx.x * 128;

    const int warp = tid >> 5;
    const int lane = tid & 31;
    const int wm = warp >> 2;
    const int wn = warp & 3;
    const int g4 = lane >> 2;
    const int t4 = lane & 3;

    const uint32_t smb = smem_u32(smh);
    const int nk = Kd / 32;

    const uint32_t fRow = (uint32_t)((lane & 7) + ((lane >> 3) & 1) * 8);
    const uint32_t fCol = (uint32_t)(lane >> 4) * 8;
    const uint32_t aFrag = ((wm * 64 + fRow) * RPH + fCol) * 2;
    const uint32_t bFrag = ((wn * 32 + fRow) * RPH + fCol) * 2;

    int lrow[2], lc[2];
#pragma unroll
    for (int t = 0; t < 2; t++) {
        int id = tid + 256 * t;
        lrow[t] = id >> 2;
        lc[t] = (id & 3) * 8;
    }

    auto ISSUE = [&](int s) {
        const uint32_t sb = smb + (uint32_t)(s & 1) * STG * 2;
        const size_t ko = (size_t)s * 32;
#pragma unroll
        for (int t = 0; t < 2; t++) {
            const size_t go = (size_t)lrow[t] * Kd + ko + lc[t];
            const uint32_t so = (uint32_t)(lrow[t] * RPH + lc[t]) * 2;
            cp16(sb + AOf * 2 + so, A + (size_t)m0 * Kd + go);
            cp16(sb + BOf * 2 + so, B + (size_t)n0 * Kd + go);
        }
    };

    float d[4][4][4];
#pragma unroll
    for (int i = 0; i < 4; i++)
#pragma unroll
        for (int j = 0; j < 4; j++)
#pragma unroll
            for (int q = 0; q < 4; q++) d[i][j][q] = 0.f;

    ISSUE(0); cp_commit();

    for (int s = 0; s < nk; s++) {
        cp_wait<0>();
        __syncthreads();
        if (s + 1 < nk) ISSUE(s + 1);
        cp_commit();

        const uint32_t sb = smb + (uint32_t)(s & 1) * STG * 2;
#pragma unroll
        for (int kk = 0; kk < 2; kk++) {
            const uint32_t cOff = (uint32_t)kk * 32;
            uint32_t a[4][4], b[4][2];
#pragma unroll
            for (int i = 0; i < 4; i++)
                LDSM_X4(a[i], sb + AOf * 2 + aFrag + (uint32_t)(i * 16 * RPH * 2) + cOff);
#pragma unroll
            for (int j2 = 0; j2 < 2; j2++) {
                uint32_t t[4];
                LDSM_X4(t, sb + BOf * 2 + bFrag + (uint32_t)(j2 * 16 * RPH * 2) + cOff);
                b[j2 * 2][0] = t[0]; b[j2 * 2 + 1][0] = t[1];
                b[j2 * 2][1] = t[2]; b[j2 * 2 + 1][1] = t[3];
            }
#pragma unroll
            for (int i = 0; i < 4; i++)
#pragma unroll
                for (int j = 0; j < 4; j++) MMA_F16(d[i][j], a[i], b[j]);
        }
    }

    // epilogue: bias + relu
#pragma unroll
    for (int i = 0; i < 4; i++) {
        int r0 = m0 + wm * 64 + i * 16 + g4;
#pragma unroll
        for (int j = 0; j < 4; j++) {
            int col = n0 + wn * 32 + j * 8 + t4 * 2;
            float2 bv = *(const float2*)(bias + col);
            float vv[4];
            vv[0] = d[i][j][0] + bv.x; vv[1] = d[i][j][1] + bv.y;
            vv[2] = d[i][j][2] + bv.x; vv[3] = d[i][j][3] + bv.y;
            if (RELU) {
#pragma unroll
                for (int q = 0; q < 4; q++) vv[q] = fmaxf(vv[q], 0.f);
            }
            size_t o0 = (size_t)r0 * Nn + col;
            size_t o1 = (size_t)(r0 + 8) * Nn + col;
            if (HOUT) {
                __half* C = (__half*)Cv + (size_t)z * cB;
                *(__half2*)(C + o0) = __floats2half2_rn(vv[0], vv[1]);
                *(__half2*)(C + o1) = __floats2half2_rn(vv[2], vv[3]);
            } else {
                float* C = (float*)Cv + (size_t)z * cB;
                *(float2*)(C + o0) = make_float2(vv[0], vv[1]);
                *(float2*)(C + o1) = make_float2(vv[2], vv[3]);
            }
        }
    }
}

// ------- FP16 hi/lo split GEMM: 3 products (hh + hl + lh), fp32-exact class --
// A,B given as (hi, lo) fp16 [rows,K]. WSPLIT: 1 -> write fp16 (hi,lo) to C/Cl;
// 0 -> write fp32 to C. mrows: device row count for early tile exit.
template <int RELU, int WSPLIT>
__global__ __launch_bounds__(256, 2)
void hsplit_gemm(const __half* __restrict__ Ah, const __half* __restrict__ Al,
                 const __half* __restrict__ Bh, const __half* __restrict__ Bl,
                 const float* __restrict__ bias, void* __restrict__ Cv,
                 __half* __restrict__ Cl, const int* __restrict__ mrows,
                 int Kd, int Nn)
{
    if (mrows && (int)(blockIdx.y * 128) >= *mrows) return;

    extern __shared__ __half smh[];
    constexpr int AHo = 0;
    constexpr int BHo = TILEH;
    constexpr int ALo = 2 * TILEH;
    constexpr int BLo = 3 * TILEH;
    constexpr int STG = 4 * TILEH;   // halves per stage

    const int tid = threadIdx.x;
    const int m0 = blockIdx.y * 128;
    const int n0 = blockIdx.x * 128;

    const int warp = tid >> 5;
    const int lane = tid & 31;
    const int wm = warp >> 2;
    const int wn = warp & 3;
    const int g4 = lane >> 2;
    const int t4 = lane & 3;

    const uint32_t smb = smem_u32(smh);
    const int nk = Kd / 32;

    const uint32_t fRow = (uint32_t)((lane & 7) + ((lane >> 3) & 1) * 8);
    const uint32_t fCol = (uint32_t)(lane >> 4) * 8;
    const uint32_t aFrag = ((wm * 64 + fRow) * RPH + fCol) * 2;
    const uint32_t bFrag = ((wn * 32 + fRow) * RPH + fCol) * 2;

    int lrow[2], lc[2];
#pragma unroll
    for (int t = 0; t < 2; t++) {
        int id = tid + 256 * t;
        lrow[t] = id >> 2;
        lc[t] = (id & 3) * 8;
    }

    auto ISSUE = [&](int s) {
        const uint32_t sb = smb + (uint32_t)(s & 1) * STG * 2;
        const size_t ko = (size_t)s * 32;
#pragma unroll
        for (int t = 0; t < 2; t++) {
            const size_t goA = (size_t)(m0 + lrow[t]) * Kd + ko + lc[t];
            const size_t goB = (size_t)(n0 + lrow[t]) * Kd + ko + lc[t];
            const uint32_t so = (uint32_t)(lrow[t] * RPH + lc[t]) * 2;
            cp16(sb + AHo * 2 + so, Ah + goA);
            cp16(sb + BHo * 2 + so, Bh + goB);
            cp16(sb + ALo * 2 + so, Al + goA);
            cp16(sb + BLo * 2 + so, Bl + goB);
        }
    };

    float d[4][4][4];
#pragma unroll
    for (int i = 0; i < 4; i++)
#pragma unroll
        for (int j = 0; j < 4; j++)
#pragma unroll
            for (int q = 0; q < 4; q++) d[i][j][q] = 0.f;

    ISSUE(0); cp_commit();

    for (int s = 0; s < nk; s++) {
        cp_wait<0>();
        __syncthreads();
        if (s + 1 < nk) ISSUE(s + 1);
        cp_commit();

        const uint32_t sb = smb + (uint32_t)(s & 1) * STG * 2;
#pragma unroll
        for (int kk = 0; kk < 2; kk++) {
            const uint32_t cOff = (uint32_t)kk * 32;
            uint32_t ah[4][4], al[4][4], bh[4][2], bl[4][2];
#pragma unroll
            for (int i = 0; i < 4; i++) {
                LDSM_X4(ah[i], sb + AHo * 2 + aFrag + (uint32_t)(i * 16 * RPH * 2) + cOff);
                LDSM_X4(al[i], sb + ALo * 2 + aFrag + (uint32_t)(i * 16 * RPH * 2) + cOff);
            }
#pragma unroll
            for (int j2 = 0; j2 < 2; j2++) {
                uint32_t t[4];
                LDSM_X4(t, sb + BHo * 2 + bFrag + (uint32_t)(j2 * 16 * RPH * 2) + cOff);
                bh[j2 * 2][0] = t[0]; bh[j2 * 2 + 1][0] = t[1];
                bh[j2 * 2][1] = t[2]; bh[j2 * 2 + 1][1] = t[3];
                LDSM_X4(t, sb + BLo * 2 + bFrag + (uint32_t)(j2 * 16 * RPH * 2) + cOff);
                bl[j2 * 2][0] = t[0]; bl[j2 * 2 + 1][0] = t[1];
                bl[j2 * 2][1] = t[2]; bl[j2 * 2 + 1][1] = t[3];
            }
#pragma unroll
            for (int i = 0; i < 4; i++)
#pragma unroll
                for (int j = 0; j < 4; j++) {
                    MMA_F16(d[i][j], ah[i], bh[j]);
                    MMA_F16(d[i][j], ah[i], bl[j]);
                    MMA_F16(d[i][j], al[i], bh[j]);
                }
        }
    }

    // epilogue
#pragma unroll
    for (int i = 0; i < 4; i++) {
        int r0 = m0 + wm * 64 + i * 16 + g4;
#pragma unroll
        for (int j = 0; j < 4; j++) {
            int col = n0 + wn * 32 + j * 8 + t4 * 2;
            float2 bv = *(const float2*)(bias + col);
            float vv[4];
            vv[0] = d[i][j][0] + bv.x; vv[1] = d[i][j][1] + bv.y;
            vv[2] = d[i][j][2] + bv.x; vv[3] = d[i][j][3] + bv.y;
            if (RELU) {
#pragma unroll
                for (int q = 0; q < 4; q++) vv[q] = fmaxf(vv[q], 0.f);
            }
            size_t o0 = (size_t)r0 * Nn + col;
            size_t o1 = (size_t)(r0 + 8) * Nn + col;
            if (WSPLIT) {
                __half* C = (__half*)Cv;
                __half h0, l0, h1, l1, h2, l2, h3, l3;
                split16(vv[0], h0, l0); split16(vv[1], h1, l1);
                split16(vv[2], h2, l2); split16(vv[3], h3, l3);
                *(__half2*)(C + o0)  = __halves2half2(h0, h1);
                *(__half2*)(C + o1)  = __halves2half2(h2, h3);
                *(__half2*)(Cl + o0) = __halves2half2(l0, l1);
                *(__half2*)(Cl + o1) = __halves2half2(l2, l3);
            } else {
                float* C = (float*)Cv;
                *(float2*)(C + o0) = make_float2(vv[0], vv[1]);
                *(float2*)(C + o1) = make_float2(vv[2], vv[3]);
            }
        }
    }
}

// -------- elementwise split: x -> (fp16 hi, fp16 lo) -------------------------
__global__ __launch_bounds__(256) void split_kernel(
    const float* __restrict__ src, __half* __restrict__ dh,
    __half* __restrict__ dl, int n4)
{
    int i = blockIdx.x * blockDim.x + threadIdx.x;
    if (i >= n4) return;
    float4 v = ((const float4*)src)[i];
    __half h0, l0, h1, l1, h2, l2, h3, l3;
    split16(v.x, h0, l0); split16(v.y, h1, l1);
    split16(v.z, h2, l2); split16(v.w, h3, l3);
    ((__half2*)dh)[i * 2]     = __halves2half2(h0, h1);
    ((__half2*)dh)[i * 2 + 1] = __halves2half2(h2, h3);
    ((__half2*)dl)[i * 2]     = __halves2half2(l0, l1);
    ((__half2*)dl)[i * 2 + 1] = __halves2half2(l2, l3);
}

// ------ weight transpose. MODE 0: fp16 hi+lo; MODE 2: fp16 hi only -----------
template <int MODE>
__global__ __launch_bounds__(256) void transpose_kernel(
    const float* __restrict__ src, __half* __restrict__ dh,
    __half* __restrict__ dl, int R, int Cc)
{
    __shared__ float tile[32][33];
    size_t off = (size_t)blockIdx.z * R * Cc;
    int c0 = blockIdx.x * 32, r0 = blockIdx.y * 32;
    int tx = threadIdx.x, ty = threadIdx.y;
#pragma unroll
    for (int i = 0; i < 4; i++)
        tile[ty + i * 8][tx] = src[off + (size_t)(r0 + ty + i * 8) * Cc + c0 + tx];
    __syncthreads();
#pragma unroll
    for (int i = 0; i < 4; i++) {
        float v = tile[tx][ty + i * 8];
        size_t o = off + (size_t)(c0 + ty + i * 8) * R + r0 + tx;
        __half h = __float2half_rn(v);
        dh[o] = h;
        if (MODE == 0) dl[o] = __float2half_rn(v - __half2float(h));
    }
}

// ---------------- router head: logits + softmax + top-2 + margin flag --------
__global__ __launch_bounds__(256) void router_topk_kernel(
    const float* __restrict__ h2, const float* __restrict__ rw3,
    const float* __restrict__ rb3, int* __restrict__ eid,
    float* __restrict__ prob, int* __restrict__ list, int* __restrict__ cnt)
{
    __shared__ __align__(16) float sh[HDIM];
    __shared__ float slog[EXPN];
    const int t = blockIdx.x;

    const float4* src = (const float4*)(h2 + (size_t)t * HDIM);
    float4* dst4 = (float4*)sh;
    for (int i = threadIdx.x; i < HDIM / 4; i += 256) dst4[i] = src[i];
    __syncthreads();

    const int w = threadIdx.x >> 5;
    const int lane = threadIdx.x & 31;
    if (w < EXPN) {
        float s = 0.f;
        for (int j = lane; j < HDIM; j += 32) s += sh[j] * rw3[(size_t)j * EXPN + w];
#pragma unroll
        for (int o = 16; o > 0; o >>= 1) s += __shfl_down_sync(0xffffffffu, s, o);
        if (lane == 0) slog[w] = s + rb3[w];
    }
    __syncthreads();

    if (threadIdx.x == 0) {
        float l[EXPN], p[EXPN];
        float mx = -1e30f;
#pragma unroll
        for (int e = 0; e < EXPN; e++) { l[e] = slog[e]; mx = fmaxf(mx, l[e]); }
        float se = 0.f;
#pragma unroll
        for (int e = 0; e < EXPN; e++) { p[e] = expf(l[e] - mx); se += p[e]; }
        float inv = 1.f / se;
#pragma unroll
        for (int e = 0; e < EXPN; e++) p[e] *= inv;
        int b1 = 0;
#pragma unroll
        for (int e = 1; e < EXPN; e++) if (l[e] > l[b1]) b1 = e;
        int b2 = (b1 == 0) ? 1 : 0;
#pragma unroll
        for (int e = 0; e < EXPN; e++)
            if (e != b1 && l[e] > l[b2]) b2 = e;
        int b3 = -1;
#pragma unroll
        for (int e = 0; e < EXPN; e++)
            if (e != b1 && e != b2 && (b3 < 0 || l[e] > l[b3])) b3 = e;
        eid[t * 2 + 0] = b1; prob[t * 2 + 0] = p[b1];
        eid[t * 2 + 1] = b2; prob[t * 2 + 1] = p[b2];
        if (l[b2] - l[b3] < MARGIN) {
            int idx = atomicAdd(cnt, 1);
            if (idx < RCAP) list[idx] = t;
        }
    }
}

__global__ void reset_cnt_kernel(int* c) { *c = 0; }

// ------------- gather marginal tokens' split x into compact batch ------------
__global__ __launch_bounds__(256) void gather_kernel(
    const __half* __restrict__ xh, const __half* __restrict__ xl,
    const int* __restrict__ list, const int* __restrict__ cnt,
    __half* __restrict__ gxh, __half* __restrict__ gxl)
{
    const int i = blockIdx.x;
    const int n = min(*cnt, RCAP);
    uint2* dh = (uint2*)(gxh + (size_t)i * CDIM);
    uint2* dl = (uint2*)(gxl + (size_t)i * CDIM);
    if (i < n) {
        const int t = list[i];
        dh[threadIdx.x] = ((const uint2*)(xh + (size_t)t * CDIM))[threadIdx.x];
        dl[threadIdx.x] = ((const uint2*)(xl + (size_t)t * CDIM))[threadIdx.x];
    } else {
        uint2 z = make_uint2(0u, 0u);
        dh[threadIdx.x] = z;
        dl[threadIdx.x] = z;
    }
}

// ------------- exact top-2 fix for marginal tokens ----------------------------
__global__ __launch_bounds__(256) void fix_topk_kernel(
    const float* __restrict__ grh2, const float* __restrict__ rw3,
    const float* __restrict__ rb3, const int* __restrict__ list,
    const int* __restrict__ cnt, int* __restrict__ eid, float* __restrict__ prob)
{
    const int i = blockIdx.x;
    if (i >= min(*cnt, RCAP)) return;
    __shared__ __align__(16) float sh[HDIM];
    __shared__ float slog[EXPN];

    const float4* src = (const float4*)(grh2 + (size_t)i * HDIM);
    float4* dst4 = (float4*)sh;
    for (int k = threadIdx.x; k < HDIM / 4; k += 256) dst4[k] = src[k];
    __syncthreads();

    const int w = threadIdx.x >> 5;
    const int lane = threadIdx.x & 31;
    if (w < EXPN) {
        float s = 0.f;
        for (int j = lane; j < HDIM; j += 32) s += sh[j] * rw3[(size_t)j * EXPN + w];
#pragma unroll
        for (int o = 16; o > 0; o >>= 1) s += __shfl_down_sync(0xffffffffu, s, o);
        if (lane == 0) slog[w] = s + rb3[w];
    }
    __syncthreads();

    if (threadIdx.x == 0) {
        const int t = list[i];
        float l[EXPN], p[EXPN];
        float mx = -1e30f;
#pragma unroll
        for (int e = 0; e < EXPN; e++) { l[e] = slog[e]; mx = fmaxf(mx, l[e]); }
        float se = 0.f;
#pragma unroll
        for (int e = 0; e < EXPN; e++) { p[e] = expf(l[e] - mx); se += p[e]; }
        float inv = 1.f / se;
#pragma unroll
        for (int e = 0; e < EXPN; e++) p[e] *= inv;
        int b1 = 0;
#pragma unroll
        for (int e = 1; e < EXPN; e++) if (l[e] > l[b1]) b1 = e;
        int b2 = (b1 == 0) ? 1 : 0;
#pragma unroll
        for (int e = 0; e < EXPN; e++)
            if (e != b1 && l[e] > l[b2]) b2 = e;
        eid[t * 2 + 0] = b1; prob[t * 2 + 0] = p[b1];
        eid[t * 2 + 1] = b2; prob[t * 2 + 1] = p[b2];
    }
}

// ---- exact flattened-order per-expert ranks ---------------------------------
__global__ __launch_bounds__(1024) void positions_kernel(
    const int* __restrict__ eid, int* __restrict__ pos)
{
    __shared__ int base[EXPN];
    __shared__ int wcnt[32][EXPN];
    const int tid = threadIdx.x;
    const int lane = tid & 31;
    const int w = tid >> 5;

    if (tid < EXPN) base[tid] = 0;
    __syncthreads();

    for (int c = 0; c < NFLAT; c += 1024) {
        if (tid < 32 * EXPN) ((int*)wcnt)[tid] = 0;
        __syncthreads();

        int e = eid[c + tid];
        unsigned m = __match_any_sync(0xffffffffu, e);
        int rank = __popc(m & ((1u << lane) - 1u));
        int leader = __ffs(m) - 1;
        if (lane == leader) wcnt[w][e] = __popc(m);
        __syncthreads();

        int off = base[e] + rank;
        for (int w2 = 0; w2 < 32; w2++)
            if (w2 < w) off += wcnt[w2][e];
        pos[c + tid] = off;
        __syncthreads();

        if (tid < EXPN) {
            int s = 0;
#pragma unroll
            for (int w2 = 0; w2 < 32; w2++) s += wcnt[w2][tid];
            base[tid] += s;
        }
        __syncthreads();
    }
}

// dispatch: scatter fp16(x) rows into expert buffers
__global__ __launch_bounds__(256) void dispatch_kernel(
    const __half* __restrict__ xh, const int* __restrict__ eid,
    const int* __restrict__ pos, __half* __restrict__ disp)
{
    const int i = blockIdx.x;
    const int p = pos[i];
    if (p >= CAPN) return;
    const int e = eid[i];
    const int token = i >> 1;
    uint2* dst = (uint2*)(disp + ((size_t)e * CAPN + p) * CDIM);
    dst[threadIdx.x] = ((const uint2*)(xh + (size_t)token * CDIM))[threadIdx.x];
}

__global__ __launch_bounds__(256) void combine_kernel(
    const float* __restrict__ eo, const int* __restrict__ eid,
    const float* __restrict__ prob, const int* __restrict__ pos,
    float* __restrict__ out)
{
    const int t = blockIdx.x;
    const int e1 = eid[t * 2 + 0], e2 = eid[t * 2 + 1];
    const int p1 = pos[t * 2 + 0], p2 = pos[t * 2 + 1];
    const float w1 = prob[t * 2 + 0] * (p1 < CAPN ? 1.f : 0.f);
    const float w2 = prob[t * 2 + 1] * (p2 < CAPN ? 1.f : 0.f);
    const int g1 = min(p1, CAPN - 1), g2 = min(p2, CAPN - 1);

    const float4* r1 = (const float4*)(eo + ((size_t)e1 * CAPN + g1) * CDIM);
    const float4* r2 = (const float4*)(eo + ((size_t)e2 * CAPN + g2) * CDIM);
    float4 a = r1[threadIdx.x];
    float4 b = r2[threadIdx.x];
    float4 v;
    v.x = w1 * a.x + w2 * b.x;
    v.y = w1 * a.y + w2 * b.y;
    v.z = w1 * a.z + w2 * b.z;
    v.w = w1 * a.w + w2 * b.w;
    ((float4*)(out + (size_t)t * CDIM))[threadIdx.x] = v;
}

// ---------------- launch -----------------------------------------------------
extern "C" void kernel_launch(void* const* d_in, const int* in_sizes, int n_in,
                              void* d_out, int out_size)
{
    const float* x   = (const float*)d_in[0];
    const float* rw1 = (const float*)d_in[1];
    const float* rb1 = (const float*)d_in[2];
    const float* rw2 = (const float*)d_in[3];
    const float* rb2 = (const float*)d_in[4];
    const float* rw3 = (const float*)d_in[5];
    const float* rb3 = (const float*)d_in[6];
    const float* ew1 = (const float*)d_in[7];
    const float* eb1 = (const float*)d_in[8];
    const float* ew2 = (const float*)d_in[9];
    const float* eb2 = (const float*)d_in[10];
    float* out = (float*)d_out;
    (void)in_sizes; (void)n_in; (void)out_size;

    float *h2, *eo, *prob, *grh2;
    __half *xh16, *xl16, *h1hf, *disph, *ehh;
    __half *rw1h16, *rw1l16, *rw2h16, *rw2l16, *ew1hf, *ew2hf;
    __half *gxh, *gxl, *grh1h, *grh1l;
    int *eid, *pos, *list, *cnt;
    cudaGetSymbolAddress((void**)&xh16,   g_xh16);
    cudaGetSymbolAddress((void**)&xl16,   g_xl16);
    cudaGetSymbolAddress((void**)&h1hf,   g_h1hf);
    cudaGetSymbolAddress((void**)&h2,     g_h2);
    cudaGetSymbolAddress((void**)&disph,  g_disph);
    cudaGetSymbolAddress((void**)&ehh,    g_ehh);
    cudaGetSymbolAddress((void**)&eo,     g_eo);
    cudaGetSymbolAddress((void**)&eid,    g_eid);
    cudaGetSymbolAddress((void**)&prob,   g_prob);
    cudaGetSymbolAddress((void**)&pos,    g_pos);
    cudaGetSymbolAddress((void**)&rw1h16, g_rw1h16);
    cudaGetSymbolAddress((void**)&rw1l16, g_rw1l16);
    cudaGetSymbolAddress((void**)&rw2h16, g_rw2h16);
    cudaGetSymbolAddress((void**)&rw2l16, g_rw2l16);
    cudaGetSymbolAddress((void**)&ew1hf,  g_ew1hf);
    cudaGetSymbolAddress((void**)&ew2hf,  g_ew2hf);
    cudaGetSymbolAddress((void**)&gxh,    g_gxh);
    cudaGetSymbolAddress((void**)&gxl,    g_gxl);
    cudaGetSymbolAddress((void**)&grh1h,  g_grh1h);
    cudaGetSymbolAddress((void**)&grh1l,  g_grh1l);
    cudaGetSymbolAddress((void**)&grh2,   g_grh2);
    cudaGetSymbolAddress((void**)&list,   g_list);
    cudaGetSymbolAddress((void**)&cnt,    g_cnt);

    const int DSH = 2 * TILEH * 2 * 2;   // fp16 1x: 2 stages of (A,B)
    const int DSS = 4 * TILEH * 2 * 2;   // fp16 split: 2 stages of (AH,BH,AL,BL)
    cudaFuncSetAttribute((const void*)hmma_gemm<1,1>, cudaFuncAttributeMaxDynamicSharedMemorySize, DSH);
    cudaFuncSetAttribute((const void*)hmma_gemm<1,0>, cudaFuncAttributeMaxDynamicSharedMemorySize, DSH);
    cudaFuncSetAttribute((const void*)hmma_gemm<0,0>, cudaFuncAttributeMaxDynamicSharedMemorySize, DSH);
    cudaFuncSetAttribute((const void*)hsplit_gemm<1,1>, cudaFuncAttributeMaxDynamicSharedMemorySize, DSS);
    cudaFuncSetAttribute((const void*)hsplit_gemm<1,0>, cudaFuncAttributeMaxDynamicSharedMemorySize, DSS);

    // operand preparation (hi array == plain fp16 array, shared by fast path)
    split_kernel<<<(NTOK * CDIM / 4 + 255) / 256, 256>>>(x, xh16, xl16, NTOK * CDIM / 4);
    transpose_kernel<0><<<dim3(HDIM/32, CDIM/32, 1), dim3(32, 8)>>>(rw1, rw1h16, rw1l16, CDIM, HDIM);
    transpose_kernel<0><<<dim3(HDIM/32, HDIM/32, 1), dim3(32, 8)>>>(rw2, rw2h16, rw2l16, HDIM, HDIM);
    transpose_kernel<2><<<dim3(HDIM/32, CDIM/32, EXPN), dim3(32, 8)>>>(ew1, ew1hf, nullptr, CDIM, HDIM);
    transpose_kernel<2><<<dim3(CDIM/32, HDIM/32, EXPN), dim3(32, 8)>>>(ew2, ew2hf, nullptr, HDIM, CDIM);

    // router MLP in fp16 (decisions fixed below)
    hmma_gemm<1,1><<<dim3(HDIM/128, NTOK/128, 1), 256, DSH>>>(
        xh16, rw1h16, rb1, h1hf, CDIM, HDIM, 0, 0, 0, 0);
    hmma_gemm<1,0><<<dim3(HDIM/128, NTOK/128, 1), 256, DSH>>>(
        h1hf, rw2h16, rb2, h2, HDIM, HDIM, 0, 0, 0, 0);

    reset_cnt_kernel<<<1, 1>>>(cnt);
    router_topk_kernel<<<NTOK, 256>>>(h2, rw3, rb3, eid, prob, list, cnt);

    // exact recheck of marginal tokens: fp16 hi/lo 3-product split (22-bit class)
    gather_kernel<<<RCAP, 256>>>(xh16, xl16, list, cnt, gxh, gxl);
    hsplit_gemm<1,1><<<dim3(HDIM/128, RCAP/128, 1), 256, DSS>>>(
        gxh, gxl, rw1h16, rw1l16, rb1, grh1h, grh1l, cnt, CDIM, HDIM);
    hsplit_gemm<1,0><<<dim3(HDIM/128, RCAP/128, 1), 256, DSS>>>(
        grh1h, grh1l, rw2h16, rw2l16, rb2, grh2, nullptr, cnt, HDIM, HDIM);
    fix_topk_kernel<<<RCAP, 256>>>(grh2, rw3, rb3, list, cnt, eid, prob);

    positions_kernel<<<1, 1024>>>(eid, pos);
    dispatch_kernel<<<NFLAT, 256>>>(xh16, eid, pos, disph);

    // expert FFNs in fp16
    hmma_gemm<1,1><<<dim3(HDIM/128, CAPN/128, EXPN), 256, DSH>>>(
        disph, ew1hf, eb1, ehh, CDIM, HDIM,
        (long long)CAPN * CDIM, (long long)HDIM * CDIM, HDIM, (long long)CAPN * HDIM);
    hmma_gemm<0,0><<<dim3(CDIM/128, CAPN/128, EXPN), 256, DSH>>>(
        ehh, ew2hf, eb2, eo, HDIM, CDIM,
        (long long)CAPN * HDIM, (long long)CDIM * HDIM, CDIM, (long long)CAPN * CDIM);

    // combine
    combine_kernel<<<NTOK, 256>>>(eo, eid, prob, pos, out);
}

// round 16
// speedup vs baseline: 2.7654x; 1.0010x over previous
#include <cuda_runtime.h>
#include <cuda_fp16.h>
#include <cstdint>
#include <math.h>

// Problem constants
#define NTOK 8192
#define CDIM 1024
#define HDIM 4096
#define EXPN 8
#define KSEL 2
#define CAPN 2048
#define NFLAT (NTOK*KSEL)
#define RCAP 2048               // recheck batch capacity (rows)
#define MARGIN 0.004f           // logit-gap threshold for exact recheck (~18 sigma)

// fp16 GEMM tiling: CTA 128x128, BK=32 halves, pitch 40 halves (80B)
#define RPH 40
#define TILEH (128*RPH)         // halves per tile

// ---------------- scratch ----------------------------------------------------
__device__ __align__(16) __half g_xh16[(size_t)NTOK * CDIM];     // hi = fp16(x)
__device__ __align__(16) __half g_xl16[(size_t)NTOK * CDIM];     // lo = fp16(x-hi)
__device__ __align__(16) __half g_h1hf[(size_t)NTOK * HDIM];
__device__ __align__(16) __half g_h2h[(size_t)NTOK * HDIM];
__device__ int   g_eid[NFLAT];
__device__ float g_prob[NFLAT];
__device__ int   g_pos[NFLAT];
__device__ __align__(16) __half g_disph[(size_t)EXPN * CAPN * CDIM];
__device__ __align__(16) __half g_ehh[(size_t)EXPN * CAPN * HDIM];
__device__ __align__(16) __half g_eo16[(size_t)EXPN * CAPN * CDIM];
__device__ __align__(16) __half g_rw1h16[(size_t)HDIM * CDIM];
__device__ __align__(16) __half g_rw1l16[(size_t)HDIM * CDIM];
__device__ __align__(16) __half g_rw2h16[(size_t)HDIM * HDIM];
__device__ __align__(16) __half g_rw2l16[(size_t)HDIM * HDIM];
__device__ __align__(16) __half g_ew1hf[(size_t)EXPN * HDIM * CDIM];
__device__ __align__(16) __half g_ew2hf[(size_t)EXPN * CDIM * HDIM];
// recheck scratch
__device__ int   g_list[RCAP];
__device__ int   g_cnt;
__device__ __align__(16) __half g_gxh[(size_t)RCAP * CDIM];
__device__ __align__(16) __half g_gxl[(size_t)RCAP * CDIM];
__device__ __align__(16) __half g_grh1h[(size_t)RCAP * HDIM];
__device__ __align__(16) __half g_grh1l[(size_t)RCAP * HDIM];
__device__ float g_grh2[(size_t)RCAP * HDIM];

// ---------------- helpers ------------------------------------------------
__device__ __forceinline__ uint32_t smem_u32(const void* p) {
    uint32_t a;
    asm("{ .reg .u64 t; cvta.to.shared.u64 t, %1; cvt.u32.u64 %0, t; }" : "=r"(a) : "l"(p));
    return a;
}
__device__ __forceinline__ void cp16(uint32_t s, const void* g) {
    asm volatile("cp.async.cg.shared.global [%0], [%1], 16;" :: "r"(s), "l"(g));
}
__device__ __forceinline__ void cp_commit() {
    asm volatile("cp.async.commit_group;" ::: "memory");
}
template <int N> __device__ __forceinline__ void cp_wait() {
    asm volatile("cp.async.wait_group %0;" :: "n"(N) : "memory");
}

#define MMA_F16(d, a, b) \
    asm volatile( \
        "mma.sync.aligned.m16n8k16.row.col.f32.f16.f16.f32 " \
        "{%0,%1,%2,%3}, {%4,%5,%6,%7}, {%8,%9}, {%0,%1,%2,%3};" \
        : "+f"((d)[0]), "+f"((d)[1]), "+f"((d)[2]), "+f"((d)[3]) \
        : "r"((a)[0]), "r"((a)[1]), "r"((a)[2]), "r"((a)[3]), \
          "r"((b)[0]), "r"((b)[1]))

#define LDSM_X4(r, a) \
    asm volatile("ldmatrix.sync.aligned.m8n8.x4.shared.b16 {%0,%1,%2,%3}, [%4];" \
        : "=r"((r)[0]), "=r"((r)[1]), "=r"((r)[2]), "=r"((r)[3]) : "r"(a))

__device__ __forceinline__ void split16(float v, __half& h, __half& l) {
    h = __float2half_rn(v);
    l = __float2half_rn(v - __half2float(h));
}

// ---------------- FP16 mma.sync GEMM ------------------------------------------
// A: [M,K] row-major halves. B: [N,K] row-major halves. C = op(A@B^T + bias).
// HOUT: 0 -> fp32 C, 1 -> fp16 C. 2-stage cp.async, occ 2.
template <int RELU, int HOUT>
__global__ __launch_bounds__(256, 2)
void hmma_gemm(const __half* __restrict__ A, const __half* __restrict__ B,
               const float* __restrict__ bias, void* __restrict__ Cv,
               int Kd, int Nn,
               long long aB, long long bB, long long biasB, long long cB)
{
    extern __shared__ __half smh[];
    constexpr int AOf = 0;
    constexpr int BOf = TILEH;
    constexpr int STG = 2 * TILEH;   // halves per stage

    const int tid = threadIdx.x;
    const int z = blockIdx.z;
    A += (size_t)z * aB;
    B += (size_t)z * bB;
    bias += (size_t)z * biasB;
    const int m0 = blockIdx.y * 128;
    const int n0 = blockIdx.x * 128;

    const int warp = tid >> 5;
    const int lane = tid & 31;
    const int wm = warp >> 2;
    const int wn = warp & 3;
    const int g4 = lane >> 2;
    const int t4 = lane & 3;

    const uint32_t smb = smem_u32(smh);
    const int nk = Kd / 32;

    const uint32_t fRow = (uint32_t)((lane & 7) + ((lane >> 3) & 1) * 8);
    const uint32_t fCol = (uint32_t)(lane >> 4) * 8;
    const uint32_t aFrag = ((wm * 64 + fRow) * RPH + fCol) * 2;
    const uint32_t bFrag = ((wn * 32 + fRow) * RPH + fCol) * 2;

    int lrow[2], lc[2];
#pragma unroll
    for (int t = 0; t < 2; t++) {
        int id = tid + 256 * t;
        lrow[t] = id >> 2;
        lc[t] = (id & 3) * 8;
    }

    auto ISSUE = [&](int s) {
        const uint32_t sb = smb + (uint32_t)(s & 1) * STG * 2;
        const size_t ko = (size_t)s * 32;
#pragma unroll
        for (int t = 0; t < 2; t++) {
            const size_t go = (size_t)lrow[t] * Kd + ko + lc[t];
            const uint32_t so = (uint32_t)(lrow[t] * RPH + lc[t]) * 2;
            cp16(sb + AOf * 2 + so, A + (size_t)m0 * Kd + go);
            cp16(sb + BOf * 2 + so, B + (size_t)n0 * Kd + go);
        }
    };

    float d[4][4][4];
#pragma unroll
    for (int i = 0; i < 4; i++)
#pragma unroll
        for (int j = 0; j < 4; j++)
#pragma unroll
            for (int q = 0; q < 4; q++) d[i][j][q] = 0.f;

    ISSUE(0); cp_commit();

    for (int s = 0; s < nk; s++) {
        cp_wait<0>();
        __syncthreads();
        if (s + 1 < nk) ISSUE(s + 1);
        cp_commit();

        const uint32_t sb = smb + (uint32_t)(s & 1) * STG * 2;
#pragma unroll
        for (int kk = 0; kk < 2; kk++) {
            const uint32_t cOff = (uint32_t)kk * 32;
            uint32_t a[4][4], b[4][2];
#pragma unroll
            for (int i = 0; i < 4; i++)
                LDSM_X4(a[i], sb + AOf * 2 + aFrag + (uint32_t)(i * 16 * RPH * 2) + cOff);
#pragma unroll
            for (int j2 = 0; j2 < 2; j2++) {
                uint32_t t[4];
                LDSM_X4(t, sb + BOf * 2 + bFrag + (uint32_t)(j2 * 16 * RPH * 2) + cOff);
                b[j2 * 2][0] = t[0]; b[j2 * 2 + 1][0] = t[1];
                b[j2 * 2][1] = t[2]; b[j2 * 2 + 1][1] = t[3];
            }
#pragma unroll
            for (int i = 0; i < 4; i++)
#pragma unroll
                for (int j = 0; j < 4; j++) MMA_F16(d[i][j], a[i], b[j]);
        }
    }

    // epilogue: bias + relu
#pragma unroll
    for (int i = 0; i < 4; i++) {
        int r0 = m0 + wm * 64 + i * 16 + g4;
#pragma unroll
        for (int j = 0; j < 4; j++) {
            int col = n0 + wn * 32 + j * 8 + t4 * 2;
            float2 bv = *(const float2*)(bias + col);
            float vv[4];
            vv[0] = d[i][j][0] + bv.x; vv[1] = d[i][j][1] + bv.y;
            vv[2] = d[i][j][2] + bv.x; vv[3] = d[i][j][3] + bv.y;
            if (RELU) {
#pragma unroll
                for (int q = 0; q < 4; q++) vv[q] = fmaxf(vv[q], 0.f);
            }
            size_t o0 = (size_t)r0 * Nn + col;
            size_t o1 = (size_t)(r0 + 8) * Nn + col;
            if (HOUT) {
                __half* C = (__half*)Cv + (size_t)z * cB;
                *(__half2*)(C + o0) = __floats2half2_rn(vv[0], vv[1]);
                *(__half2*)(C + o1) = __floats2half2_rn(vv[2], vv[3]);
            } else {
                float* C = (float*)Cv + (size_t)z * cB;
                *(float2*)(C + o0) = make_float2(vv[0], vv[1]);
                *(float2*)(C + o1) = make_float2(vv[2], vv[3]);
            }
        }
    }
}

// ------- FP16 hi/lo split GEMM: 3 products (hh + hl + lh), fp32-exact class --
template <int RELU, int WSPLIT>
__global__ __launch_bounds__(256, 2)
void hsplit_gemm(const __half* __restrict__ Ah, const __half* __restrict__ Al,
                 const __half* __restrict__ Bh, const __half* __restrict__ Bl,
                 const float* __restrict__ bias, void* __restrict__ Cv,
                 __half* __restrict__ Cl, const int* __restrict__ mrows,
                 int Kd, int Nn)
{
    if (mrows && (int)(blockIdx.y * 128) >= *mrows) return;

    extern __shared__ __half smh[];
    constexpr int AHo = 0;
    constexpr int BHo = TILEH;
    constexpr int ALo = 2 * TILEH;
    constexpr int BLo = 3 * TILEH;
    constexpr int STG = 4 * TILEH;

    const int tid = threadIdx.x;
    const int m0 = blockIdx.y * 128;
    const int n0 = blockIdx.x * 128;

    const int warp = tid >> 5;
    const int lane = tid & 31;
    const int wm = warp >> 2;
    const int wn = warp & 3;
    const int g4 = lane >> 2;
    const int t4 = lane & 3;

    const uint32_t smb = smem_u32(smh);
    const int nk = Kd / 32;

    const uint32_t fRow = (uint32_t)((lane & 7) + ((lane >> 3) & 1) * 8);
    const uint32_t fCol = (uint32_t)(lane >> 4) * 8;
    const uint32_t aFrag = ((wm * 64 + fRow) * RPH + fCol) * 2;
    const uint32_t bFrag = ((wn * 32 + fRow) * RPH + fCol) * 2;

    int lrow[2], lc[2];
#pragma unroll
    for (int t = 0; t < 2; t++) {
        int id = tid + 256 * t;
        lrow[t] = id >> 2;
        lc[t] = (id & 3) * 8;
    }

    auto ISSUE = [&](int s) {
        const uint32_t sb = smb + (uint32_t)(s & 1) * STG * 2;
        const size_t ko = (size_t)s * 32;
#pragma unroll
        for (int t = 0; t < 2; t++) {
            const size_t goA = (size_t)(m0 + lrow[t]) * Kd + ko + lc[t];
            const size_t goB = (size_t)(n0 + lrow[t]) * Kd + ko + lc[t];
            const uint32_t so = (uint32_t)(lrow[t] * RPH + lc[t]) * 2;
            cp16(sb + AHo * 2 + so, Ah + goA);
            cp16(sb + BHo * 2 + so, Bh + goB);
            cp16(sb + ALo * 2 + so, Al + goA);
            cp16(sb + BLo * 2 + so, Bl + goB);
        }
    };

    float d[4][4][4];
#pragma unroll
    for (int i = 0; i < 4; i++)
#pragma unroll
        for (int j = 0; j < 4; j++)
#pragma unroll
            for (int q = 0; q < 4; q++) d[i][j][q] = 0.f;

    ISSUE(0); cp_commit();

    for (int s = 0; s < nk; s++) {
        cp_wait<0>();
        __syncthreads();
        if (s + 1 < nk) ISSUE(s + 1);
        cp_commit();

        const uint32_t sb = smb + (uint32_t)(s & 1) * STG * 2;
#pragma unroll
        for (int kk = 0; kk < 2; kk++) {
            const uint32_t cOff = (uint32_t)kk * 32;
            uint32_t ah[4][4], al[4][4], bh[4][2], bl[4][2];
#pragma unroll
            for (int i = 0; i < 4; i++) {
                LDSM_X4(ah[i], sb + AHo * 2 + aFrag + (uint32_t)(i * 16 * RPH * 2) + cOff);
                LDSM_X4(al[i], sb + ALo * 2 + aFrag + (uint32_t)(i * 16 * RPH * 2) + cOff);
            }
#pragma unroll
            for (int j2 = 0; j2 < 2; j2++) {
                uint32_t t[4];
                LDSM_X4(t, sb + BHo * 2 + bFrag + (uint32_t)(j2 * 16 * RPH * 2) + cOff);
                bh[j2 * 2][0] = t[0]; bh[j2 * 2 + 1][0] = t[1];
                bh[j2 * 2][1] = t[2]; bh[j2 * 2 + 1][1] = t[3];
                LDSM_X4(t, sb + BLo * 2 + bFrag + (uint32_t)(j2 * 16 * RPH * 2) + cOff);
                bl[j2 * 2][0] = t[0]; bl[j2 * 2 + 1][0] = t[1];
                bl[j2 * 2][1] = t[2]; bl[j2 * 2 + 1][1] = t[3];
            }
#pragma unroll
            for (int i = 0; i < 4; i++)
#pragma unroll
                for (int j = 0; j < 4; j++) {
                    MMA_F16(d[i][j], ah[i], bh[j]);
                    MMA_F16(d[i][j], ah[i], bl[j]);
                    MMA_F16(d[i][j], al[i], bh[j]);
                }
        }
    }

    // epilogue
#pragma unroll
    for (int i = 0; i < 4; i++) {
        int r0 = m0 + wm * 64 + i * 16 + g4;
#pragma unroll
        for (int j = 0; j < 4; j++) {
            int col = n0 + wn * 32 + j * 8 + t4 * 2;
            float2 bv = *(const float2*)(bias + col);
            float vv[4];
            vv[0] = d[i][j][0] + bv.x; vv[1] = d[i][j][1] + bv.y;
            vv[2] = d[i][j][2] + bv.x; vv[3] = d[i][j][3] + bv.y;
            if (RELU) {
#pragma unroll
                for (int q = 0; q < 4; q++) vv[q] = fmaxf(vv[q], 0.f);
            }
            size_t o0 = (size_t)r0 * Nn + col;
            size_t o1 = (size_t)(r0 + 8) * Nn + col;
            if (WSPLIT) {
                __half* C = (__half*)Cv;
                __half h0, l0, h1, l1, h2, l2, h3, l3;
                split16(vv[0], h0, l0); split16(vv[1], h1, l1);
                split16(vv[2], h2, l2); split16(vv[3], h3, l3);
                *(__half2*)(C + o0)  = __halves2half2(h0, h1);
                *(__half2*)(C + o1)  = __halves2half2(h2, h3);
                *(__half2*)(Cl + o0) = __halves2half2(l0, l1);
                *(__half2*)(Cl + o1) = __halves2half2(l2, l3);
            } else {
                float* C = (float*)Cv;
                *(float2*)(C + o0) = make_float2(vv[0], vv[1]);
                *(float2*)(C + o1) = make_float2(vv[2], vv[3]);
            }
        }
    }
}

// -------- elementwise split: x -> (fp16 hi, fp16 lo); also resets cnt ---------
__global__ __launch_bounds__(256) void split_kernel(
    const float* __restrict__ src, __half* __restrict__ dh,
    __half* __restrict__ dl, int* __restrict__ cnt, int n4)
{
    int i = blockIdx.x * blockDim.x + threadIdx.x;
    if (i == 0) *cnt = 0;
    if (i >= n4) return;
    float4 v = ((const float4*)src)[i];
    __half h0, l0, h1, l1, h2, l2, h3, l3;
    split16(v.x, h0, l0); split16(v.y, h1, l1);
    split16(v.z, h2, l2); split16(v.w, h3, l3);
    ((__half2*)dh)[i * 2]     = __halves2half2(h0, h1);
    ((__half2*)dh)[i * 2 + 1] = __halves2half2(h2, h3);
    ((__half2*)dl)[i * 2]     = __halves2half2(l0, l1);
    ((__half2*)dl)[i * 2 + 1] = __halves2half2(l2, l3);
}

// ------ weight transpose. MODE 0: fp16 hi+lo; MODE 2: fp16 hi only -----------
template <int MODE>
__global__ __launch_bounds__(256) void transpose_kernel(
    const float* __restrict__ src, __half* __restrict__ dh,
    __half* __restrict__ dl, int R, int Cc)
{
    __shared__ float tile[32][33];
    size_t off = (size_t)blockIdx.z * R * Cc;
    int c0 = blockIdx.x * 32, r0 = blockIdx.y * 32;
    int tx = threadIdx.x, ty = threadIdx.y;
#pragma unroll
    for (int i = 0; i < 4; i++)
        tile[ty + i * 8][tx] = src[off + (size_t)(r0 + ty + i * 8) * Cc + c0 + tx];
    __syncthreads();
#pragma unroll
    for (int i = 0; i < 4; i++) {
        float v = tile[tx][ty + i * 8];
        size_t o = off + (size_t)(c0 + ty + i * 8) * R + r0 + tx;
        __half h = __float2half_rn(v);
        dh[o] = h;
        if (MODE == 0) dl[o] = __float2half_rn(v - __half2float(h));
    }
}

// ---------------- router head (fp16 h2): logits + softmax + top-2 + flag -----
__global__ __launch_bounds__(256) void router_topk_kernel(
    const __half* __restrict__ h2, const float* __restrict__ rw3,
    const float* __restrict__ rb3, int* __restrict__ eid,
    float* __restrict__ prob, int* __restrict__ list, int* __restrict__ cnt)
{
    __shared__ __align__(16) __half sh[HDIM];
    __shared__ float slog[EXPN];
    const int t = blockIdx.x;

    const uint4* src = (const uint4*)(h2 + (size_t)t * HDIM);
    uint4* dst4 = (uint4*)sh;
    for (int i = threadIdx.x; i < HDIM / 8; i += 256) dst4[i] = src[i];
    __syncthreads();

    const int w = threadIdx.x >> 5;
    const int lane = threadIdx.x & 31;
    if (w < EXPN) {
        float s = 0.f;
        for (int j = lane; j < HDIM; j += 32)
            s += __half2float(sh[j]) * rw3[(size_t)j * EXPN + w];
#pragma unroll
        for (int o = 16; o > 0; o >>= 1) s += __shfl_down_sync(0xffffffffu, s, o);
        if (lane == 0) slog[w] = s + rb3[w];
    }
    __syncthreads();

    if (threadIdx.x == 0) {
        float l[EXPN], p[EXPN];
        float mx = -1e30f;
#pragma unroll
        for (int e = 0; e < EXPN; e++) { l[e] = slog[e]; mx = fmaxf(mx, l[e]); }
        float se = 0.f;
#pragma unroll
        for (int e = 0; e < EXPN; e++) { p[e] = expf(l[e] - mx); se += p[e]; }
        float inv = 1.f / se;
#pragma unroll
        for (int e = 0; e < EXPN; e++) p[e] *= inv;
        int b1 = 0;
#pragma unroll
        for (int e = 1; e < EXPN; e++) if (l[e] > l[b1]) b1 = e;
        int b2 = (b1 == 0) ? 1 : 0;
#pragma unroll
        for (int e = 0; e < EXPN; e++)
            if (e != b1 && l[e] > l[b2]) b2 = e;
        int b3 = -1;
#pragma unroll
        for (int e = 0; e < EXPN; e++)
            if (e != b1 && e != b2 && (b3 < 0 || l[e] > l[b3])) b3 = e;
        eid[t * 2 + 0] = b1; prob[t * 2 + 0] = p[b1];
        eid[t * 2 + 1] = b2; prob[t * 2 + 1] = p[b2];
        if (l[b2] - l[b3] < MARGIN) {
            int idx = atomicAdd(cnt, 1);
            if (idx < RCAP) list[idx] = t;
        }
    }
}

// ------------- gather marginal tokens' split x into compact batch ------------
__global__ __launch_bounds__(256) void gather_kernel(
    const __half* __restrict__ xh, const __half* __restrict__ xl,
    const int* __restrict__ list, const int* __restrict__ cnt,
    __half* __restrict__ gxh, __half* __restrict__ gxl)
{
    const int i = blockIdx.x;
    const int n = min(*cnt, RCAP);
    uint2* dh = (uint2*)(gxh + (size_t)i * CDIM);
    uint2* dl = (uint2*)(gxl + (size_t)i * CDIM);
    if (i < n) {
        const int t = list[i];
        dh[threadIdx.x] = ((const uint2*)(xh + (size_t)t * CDIM))[threadIdx.x];
        dl[threadIdx.x] = ((const uint2*)(xl + (size_t)t * CDIM))[threadIdx.x];
    } else {
        uint2 z = make_uint2(0u, 0u);
        dh[threadIdx.x] = z;
        dl[threadIdx.x] = z;
    }
}

// ------------- exact top-2 fix for marginal tokens ----------------------------
__global__ __launch_bounds__(256) void fix_topk_kernel(
    const float* __restrict__ grh2, const float* __restrict__ rw3,
    const float* __restrict__ rb3, const int* __restrict__ list,
    const int* __restrict__ cnt, int* __restrict__ eid, float* __restrict__ prob)
{
    const int i = blockIdx.x;
    if (i >= min(*cnt, RCAP)) return;
    __shared__ __align__(16) float sh[HDIM];
    __shared__ float slog[EXPN];

    const float4* src = (const float4*)(grh2 + (size_t)i * HDIM);
    float4* dst4 = (float4*)sh;
    for (int k = threadIdx.x; k < HDIM / 4; k += 256) dst4[k] = src[k];
    __syncthreads();

    const int w = threadIdx.x >> 5;
    const int lane = threadIdx.x & 31;
    if (w < EXPN) {
        float s = 0.f;
        for (int j = lane; j < HDIM; j += 32) s += sh[j] * rw3[(size_t)j * EXPN + w];
#pragma unroll
        for (int o = 16; o > 0; o >>= 1) s += __shfl_down_sync(0xffffffffu, s, o);
        if (lane == 0) slog[w] = s + rb3[w];
    }
    __syncthreads();

    if (threadIdx.x == 0) {
        const int t = list[i];
        float l[EXPN], p[EXPN];
        float mx = -1e30f;
#pragma unroll
        for (int e = 0; e < EXPN; e++) { l[e] = slog[e]; mx = fmaxf(mx, l[e]); }
        float se = 0.f;
#pragma unroll
        for (int e = 0; e < EXPN; e++) { p[e] = expf(l[e] - mx); se += p[e]; }
        float inv = 1.f / se;
#pragma unroll
        for (int e = 0; e < EXPN; e++) p[e] *= inv;
        int b1 = 0;
#pragma unroll
        for (int e = 1; e < EXPN; e++) if (l[e] > l[b1]) b1 = e;
        int b2 = (b1 == 0) ? 1 : 0;
#pragma unroll
        for (int e = 0; e < EXPN; e++)
            if (e != b1 && l[e] > l[b2]) b2 = e;
        eid[t * 2 + 0] = b1; prob[t * 2 + 0] = p[b1];
        eid[t * 2 + 1] = b2; prob[t * 2 + 1] = p[b2];
    }
}

// ---- exact flattened-order per-expert ranks ---------------------------------
__global__ __launch_bounds__(1024) void positions_kernel(
    const int* __restrict__ eid, int* __restrict__ pos)
{
    __shared__ int base[EXPN];
    __shared__ int wcnt[32][EXPN];
    const int tid = threadIdx.x;
    const int lane = tid & 31;
    const int w = tid >> 5;

    if (tid < EXPN) base[tid] = 0;
    __syncthreads();

    for (int c = 0; c < NFLAT; c += 1024) {
        if (tid < 32 * EXPN) ((int*)wcnt)[tid] = 0;
        __syncthreads();

        int e = eid[c + tid];
        unsigned m = __match_any_sync(0xffffffffu, e);
        int rank = __popc(m & ((1u << lane) - 1u));
        int leader = __ffs(m) - 1;
        if (lane == leader) wcnt[w][e] = __popc(m);
        __syncthreads();

        int off = base[e] + rank;
        for (int w2 = 0; w2 < 32; w2++)
            if (w2 < w) off += wcnt[w2][e];
        pos[c + tid] = off;
        __syncthreads();

        if (tid < EXPN) {
            int s = 0;
#pragma unroll
            for (int w2 = 0; w2 < 32; w2++) s += wcnt[w2][tid];
            base[tid] += s;
        }
        __syncthreads();
    }
}

// dispatch: scatter fp16(x) rows into expert buffers
__global__ __launch_bounds__(256) void dispatch_kernel(
    const __half* __restrict__ xh, const int* __restrict__ eid,
    const int* __restrict__ pos, __half* __restrict__ disp)
{
    const int i = blockIdx.x;
    const int p = pos[i];
    if (p >= CAPN) return;
    const int e = eid[i];
    const int token = i >> 1;
    uint2* dst = (uint2*)(disp + ((size_t)e * CAPN + p) * CDIM);
    dst[threadIdx.x] = ((const uint2*)(xh + (size_t)token * CDIM))[threadIdx.x];
}

// combine: weighted sum of two fp16 expert outputs -> fp32 out
__global__ __launch_bounds__(256) void combine_kernel(
    const __half* __restrict__ eo, const int* __restrict__ eid,
    const float* __restrict__ prob, const int* __restrict__ pos,
    float* __restrict__ out)
{
    const int t = blockIdx.x;
    const int e1 = eid[t * 2 + 0], e2 = eid[t * 2 + 1];
    const int p1 = pos[t * 2 + 0], p2 = pos[t * 2 + 1];
    const float w1 = prob[t * 2 + 0] * (p1 < CAPN ? 1.f : 0.f);
    const float w2 = prob[t * 2 + 1] * (p2 < CAPN ? 1.f : 0.f);
    const int g1 = min(p1, CAPN - 1), g2 = min(p2, CAPN - 1);

    const uint2* r1 = (const uint2*)(eo + ((size_t)e1 * CAPN + g1) * CDIM);
    const uint2* r2 = (const uint2*)(eo + ((size_t)e2 * CAPN + g2) * CDIM);
    uint2 a = r1[threadIdx.x];
    uint2 b = r2[threadIdx.x];
    float2 a0 = __half22float2(*(__half2*)&a.x);
    float2 a1 = __half22float2(*(__half2*)&a.y);
    float2 b0 = __half22float2(*(__half2*)&b.x);
    float2 b1 = __half22float2(*(__half2*)&b.y);
    float4 v;
    v.x = w1 * a0.x + w2 * b0.x;
    v.y = w1 * a0.y + w2 * b0.y;
    v.z = w1 * a1.x + w2 * b1.x;
    v.w = w1 * a1.y + w2 * b1.y;
    ((float4*)(out + (size_t)t * CDIM))[threadIdx.x] = v;
}

// ---------------- launch -----------------------------------------------------
extern "C" void kernel_launch(void* const* d_in, const int* in_sizes, int n_in,
                              void* d_out, int out_size)
{
    const float* x   = (const float*)d_in[0];
    const float* rw1 = (const float*)d_in[1];
    const float* rb1 = (const float*)d_in[2];
    const float* rw2 = (const float*)d_in[3];
    const float* rb2 = (const float*)d_in[4];
    const float* rw3 = (const float*)d_in[5];
    const float* rb3 = (const float*)d_in[6];
    const float* ew1 = (const float*)d_in[7];
    const float* eb1 = (const float*)d_in[8];
    const float* ew2 = (const float*)d_in[9];
    const float* eb2 = (const float*)d_in[10];
    float* out = (float*)d_out;
    (void)in_sizes; (void)n_in; (void)out_size;

    float *prob, *grh2;
    __half *xh16, *xl16, *h1hf, *h2h, *disph, *ehh, *eo16;
    __half *rw1h16, *rw1l16, *rw2h16, *rw2l16, *ew1hf, *ew2hf;
    __half *gxh, *gxl, *grh1h, *grh1l;
    int *eid, *pos, *list, *cnt;
    cudaGetSymbolAddress((void**)&xh16,   g_xh16);
    cudaGetSymbolAddress((void**)&xl16,   g_xl16);
    cudaGetSymbolAddress((void**)&h1hf,   g_h1hf);
    cudaGetSymbolAddress((void**)&h2h,    g_h2h);
    cudaGetSymbolAddress((void**)&disph,  g_disph);
    cudaGetSymbolAddress((void**)&ehh,    g_ehh);
    cudaGetSymbolAddress((void**)&eo16,   g_eo16);
    cudaGetSymbolAddress((void**)&eid,    g_eid);
    cudaGetSymbolAddress((void**)&prob,   g_prob);
    cudaGetSymbolAddress((void**)&pos,    g_pos);
    cudaGetSymbolAddress((void**)&rw1h16, g_rw1h16);
    cudaGetSymbolAddress((void**)&rw1l16, g_rw1l16);
    cudaGetSymbolAddress((void**)&rw2h16, g_rw2h16);
    cudaGetSymbolAddress((void**)&rw2l16, g_rw2l16);
    cudaGetSymbolAddress((void**)&ew1hf,  g_ew1hf);
    cudaGetSymbolAddress((void**)&ew2hf,  g_ew2hf);
    cudaGetSymbolAddress((void**)&gxh,    g_gxh);
    cudaGetSymbolAddress((void**)&gxl,    g_gxl);
    cudaGetSymbolAddress((void**)&grh1h,  g_grh1h);
    cudaGetSymbolAddress((void**)&grh1l,  g_grh1l);
    cudaGetSymbolAddress((void**)&grh2,   g_grh2);
    cudaGetSymbolAddress((void**)&list,   g_list);
    cudaGetSymbolAddress((void**)&cnt,    g_cnt);

    const int DSH = 2 * TILEH * 2 * 2;   // fp16 1x: 2 stages of (A,B)
    const int DSS = 4 * TILEH * 2 * 2;   // fp16 split: 2 stages of (AH,BH,AL,BL)
    cudaFuncSetAttribute((const void*)hmma_gemm<1,1>, cudaFuncAttributeMaxDynamicSharedMemorySize, DSH);
    cudaFuncSetAttribute((const void*)hmma_gemm<0,1>, cudaFuncAttributeMaxDynamicSharedMemorySize, DSH);
    cudaFuncSetAttribute((const void*)hsplit_gemm<1,1>, cudaFuncAttributeMaxDynamicSharedMemorySize, DSS);
    cudaFuncSetAttribute((const void*)hsplit_gemm<1,0>, cudaFuncAttributeMaxDynamicSharedMemorySize, DSS);

    // operand preparation (hi array == plain fp16 array, shared by fast path)
    split_kernel<<<(NTOK * CDIM / 4 + 255) / 256, 256>>>(x, xh16, xl16, cnt, NTOK * CDIM / 4);
    transpose_kernel<0><<<dim3(HDIM/32, CDIM/32, 1), dim3(32, 8)>>>(rw1, rw1h16, rw1l16, CDIM, HDIM);
    transpose_kernel<0><<<dim3(HDIM/32, HDIM/32, 1), dim3(32, 8)>>>(rw2, rw2h16, rw2l16, HDIM, HDIM);
    transpose_kernel<2><<<dim3(HDIM/32, CDIM/32, EXPN), dim3(32, 8)>>>(ew1, ew1hf, nullptr, CDIM, HDIM);
    transpose_kernel<2><<<dim3(CDIM/32, HDIM/32, EXPN), dim3(32, 8)>>>(ew2, ew2hf, nullptr, HDIM, CDIM);

    // router MLP in fp16 (decisions fixed below); h2 kept fp16
    hmma_gemm<1,1><<<dim3(HDIM/128, NTOK/128, 1), 256, DSH>>>(
        xh16, rw1h16, rb1, h1hf, CDIM, HDIM, 0, 0, 0, 0);
    hmma_gemm<1,1><<<dim3(HDIM/128, NTOK/128, 1), 256, DSH>>>(
        h1hf, rw2h16, rb2, h2h, HDIM, HDIM, 0, 0, 0, 0);

    router_topk_kernel<<<NTOK, 256>>>(h2h, rw3, rb3, eid, prob, list, cnt);

    // exact recheck of marginal tokens: fp16 hi/lo 3-product split (22-bit class)
    gather_kernel<<<RCAP, 256>>>(xh16, xl16, list, cnt, gxh, gxl);
    hsplit_gemm<1,1><<<dim3(HDIM/128, RCAP/128, 1), 256, DSS>>>(
        gxh, gxl, rw1h16, rw1l16, rb1, grh1h, grh1l, cnt, CDIM, HDIM);
    hsplit_gemm<1,0><<<dim3(HDIM/128, RCAP/128, 1), 256, DSS>>>(
        grh1h, grh1l, rw2h16, rw2l16, rb2, grh2, nullptr, cnt, HDIM, HDIM);
    fix_topk_kernel<<<RCAP, 256>>>(grh2, rw3, rb3, list, cnt, eid, prob);

    positions_kernel<<<1, 1024>>>(eid, pos);
    dispatch_kernel<<<NFLAT, 256>>>(xh16, eid, pos, disph);

    // expert FFNs in fp16 (eo kept fp16)
    hmma_gemm<1,1><<<dim3(HDIM/128, CAPN/128, EXPN), 256, DSH>>>(
        disph, ew1hf, eb1, ehh, CDIM, HDIM,
        (long long)CAPN * CDIM, (long long)HDIM * CDIM, HDIM, (long long)CAPN * HDIM);
    hmma_gemm<0,1><<<dim3(CDIM/128, CAPN/128, EXPN), 256, DSH>>>(
        ehh, ew2hf, eb2, eo16, HDIM, CDIM,
        (long long)CAPN * HDIM, (long long)CDIM * HDIM, CDIM, (long long)CAPN * CDIM);

    // combine
    combine_kernel<<<NTOK, 256>>>(eo16, eid, prob, pos, out);
}

// round 17
// speedup vs baseline: 2.8798x; 1.0414x over previous
#include <cuda_runtime.h>
#include <cuda_fp16.h>
#include <cstdint>
#include <math.h>

// Problem constants
#define NTOK 8192
#define CDIM 1024
#define HDIM 4096
#define EXPN 8
#define KSEL 2
#define CAPN 2048
#define NFLAT (NTOK*KSEL)
#define RCAP 2048               // recheck batch capacity (rows)
#define MARGIN 0.004f           // logit-gap threshold for exact recheck (~18 sigma)
#define KSP 4                   // split-K factor for recheck GEMMs

// fp16 GEMM tiling: CTA 128x128, BK=32 halves, pitch 40 halves (80B)
#define RPH 40
#define TILEH (128*RPH)         // halves per tile

// ---------------- scratch ----------------------------------------------------
__device__ __align__(16) __half g_xh16[(size_t)NTOK * CDIM];     // hi = fp16(x)
__device__ __align__(16) __half g_xl16[(size_t)NTOK * CDIM];     // lo = fp16(x-hi)
__device__ __align__(16) __half g_h1hf[(size_t)NTOK * HDIM];
__device__ __align__(16) __half g_h2h[(size_t)NTOK * HDIM];
__device__ int   g_eid[NFLAT];
__device__ float g_prob[NFLAT];
__device__ int   g_pos[NFLAT];
__device__ __align__(16) __half g_disph[(size_t)EXPN * CAPN * CDIM];
__device__ __align__(16) __half g_ehh[(size_t)EXPN * CAPN * HDIM];
__device__ __align__(16) __half g_eo16[(size_t)EXPN * CAPN * CDIM];
__device__ __align__(16) __half g_rw1h16[(size_t)HDIM * CDIM];
__device__ __align__(16) __half g_rw1l16[(size_t)HDIM * CDIM];
__device__ __align__(16) __half g_rw2h16[(size_t)HDIM * HDIM];
__device__ __align__(16) __half g_rw2l16[(size_t)HDIM * HDIM];
__device__ __align__(16) __half g_ew1hf[(size_t)EXPN * HDIM * CDIM];
__device__ __align__(16) __half g_ew2hf[(size_t)EXPN * CDIM * HDIM];
// recheck scratch
__device__ int   g_list[RCAP];
__device__ int   g_cnt;
__device__ float g_grh1f[(size_t)RCAP * HDIM];                   // split-K accum h1
__device__ __align__(16) __half g_grh1h[(size_t)RCAP * HDIM];
__device__ __align__(16) __half g_grh1l[(size_t)RCAP * HDIM];
__device__ float g_grh2[(size_t)RCAP * HDIM];                    // split-K accum h2 (pre-bias)

// ---------------- helpers ------------------------------------------------
__device__ __forceinline__ uint32_t smem_u32(const void* p) {
    uint32_t a;
    asm("{ .reg .u64 t; cvta.to.shared.u64 t, %1; cvt.u32.u64 %0, t; }" : "=r"(a) : "l"(p));
    return a;
}
__device__ __forceinline__ void cp16(uint32_t s, const void* g) {
    asm volatile("cp.async.cg.shared.global [%0], [%1], 16;" :: "r"(s), "l"(g));
}
__device__ __forceinline__ void cp_commit() {
    asm volatile("cp.async.commit_group;" ::: "memory");
}
template <int N> __device__ __forceinline__ void cp_wait() {
    asm volatile("cp.async.wait_group %0;" :: "n"(N) : "memory");
}

#define MMA_F16(d, a, b) \
    asm volatile( \
        "mma.sync.aligned.m16n8k16.row.col.f32.f16.f16.f32 " \
        "{%0,%1,%2,%3}, {%4,%5,%6,%7}, {%8,%9}, {%0,%1,%2,%3};" \
        : "+f"((d)[0]), "+f"((d)[1]), "+f"((d)[2]), "+f"((d)[3]) \
        : "r"((a)[0]), "r"((a)[1]), "r"((a)[2]), "r"((a)[3]), \
          "r"((b)[0]), "r"((b)[1]))

#define LDSM_X4(r, a) \
    asm volatile("ldmatrix.sync.aligned.m8n8.x4.shared.b16 {%0,%1,%2,%3}, [%4];" \
        : "=r"((r)[0]), "=r"((r)[1]), "=r"((r)[2]), "=r"((r)[3]) : "r"(a))

__device__ __forceinline__ void split16(float v, __half& h, __half& l) {
    h = __float2half_rn(v);
    l = __float2half_rn(v - __half2float(h));
}

// ---------------- FP16 mma.sync GEMM ------------------------------------------
// A: [M,K] row-major halves. B: [N,K] row-major halves. C = op(A@B^T + bias).
// HOUT: 0 -> fp32 C, 1 -> fp16 C. 2-stage cp.async, occ 2.
template <int RELU, int HOUT>
__global__ __launch_bounds__(256, 2)
void hmma_gemm(const __half* __restrict__ A, const __half* __restrict__ B,
               const float* __restrict__ bias, void* __restrict__ Cv,
               int Kd, int Nn,
               long long aB, long long bB, long long biasB, long long cB)
{
    extern __shared__ __half smh[];
    constexpr int AOf = 0;
    constexpr int BOf = TILEH;
    constexpr int STG = 2 * TILEH;   // halves per stage

    const int tid = threadIdx.x;
    const int z = blockIdx.z;
    A += (size_t)z * aB;
    B += (size_t)z * bB;
    bias += (size_t)z * biasB;
    const int m0 = blockIdx.y * 128;
    const int n0 = blockIdx.x * 128;

    const int warp = tid >> 5;
    const int lane = tid & 31;
    const int wm = warp >> 2;
    const int wn = warp & 3;
    const int g4 = lane >> 2;
    const int t4 = lane & 3;

    const uint32_t smb = smem_u32(smh);
    const int nk = Kd / 32;

    const uint32_t fRow = (uint32_t)((lane & 7) + ((lane >> 3) & 1) * 8);
    const uint32_t fCol = (uint32_t)(lane >> 4) * 8;
    const uint32_t aFrag = ((wm * 64 + fRow) * RPH + fCol) * 2;
    const uint32_t bFrag = ((wn * 32 + fRow) * RPH + fCol) * 2;

    int lrow[2], lc[2];
#pragma unroll
    for (int t = 0; t < 2; t++) {
        int id = tid + 256 * t;
        lrow[t] = id >> 2;
        lc[t] = (id & 3) * 8;
    }

    auto ISSUE = [&](int s) {
        const uint32_t sb = smb + (uint32_t)(s & 1) * STG * 2;
        const size_t ko = (size_t)s * 32;
#pragma unroll
        for (int t = 0; t < 2; t++) {
            const size_t go = (size_t)lrow[t] * Kd + ko + lc[t];
            const uint32_t so = (uint32_t)(lrow[t] * RPH + lc[t]) * 2;
            cp16(sb + AOf * 2 + so, A + (size_t)m0 * Kd + go);
            cp16(sb + BOf * 2 + so, B + (size_t)n0 * Kd + go);
        }
    };

    float d[4][4][4];
#pragma unroll
    for (int i = 0; i < 4; i++)
#pragma unroll
        for (int j = 0; j < 4; j++)
#pragma unroll
            for (int q = 0; q < 4; q++) d[i][j][q] = 0.f;

    ISSUE(0); cp_commit();

    for (int s = 0; s < nk; s++) {
        cp_wait<0>();
        __syncthreads();
        if (s + 1 < nk) ISSUE(s + 1);
        cp_commit();

        const uint32_t sb = smb + (uint32_t)(s & 1) * STG * 2;
#pragma unroll
        for (int kk = 0; kk < 2; kk++) {
            const uint32_t cOff = (uint32_t)kk * 32;
            uint32_t a[4][4], b[4][2];
#pragma unroll
            for (int i = 0; i < 4; i++)
                LDSM_X4(a[i], sb + AOf * 2 + aFrag + (uint32_t)(i * 16 * RPH * 2) + cOff);
#pragma unroll
            for (int j2 = 0; j2 < 2; j2++) {
                uint32_t t[4];
                LDSM_X4(t, sb + BOf * 2 + bFrag + (uint32_t)(j2 * 16 * RPH * 2) + cOff);
                b[j2 * 2][0] = t[0]; b[j2 * 2 + 1][0] = t[1];
                b[j2 * 2][1] = t[2]; b[j2 * 2 + 1][1] = t[3];
            }
#pragma unroll
            for (int i = 0; i < 4; i++)
#pragma unroll
                for (int j = 0; j < 4; j++) MMA_F16(d[i][j], a[i], b[j]);
        }
    }

    // epilogue: bias + relu
#pragma unroll
    for (int i = 0; i < 4; i++) {
        int r0 = m0 + wm * 64 + i * 16 + g4;
#pragma unroll
        for (int j = 0; j < 4; j++) {
            int col = n0 + wn * 32 + j * 8 + t4 * 2;
            float2 bv = *(const float2*)(bias + col);
            float vv[4];
            vv[0] = d[i][j][0] + bv.x; vv[1] = d[i][j][1] + bv.y;
            vv[2] = d[i][j][2] + bv.x; vv[3] = d[i][j][3] + bv.y;
            if (RELU) {
#pragma unroll
                for (int q = 0; q < 4; q++) vv[q] = fmaxf(vv[q], 0.f);
            }
            size_t o0 = (size_t)r0 * Nn + col;
            size_t o1 = (size_t)(r0 + 8) * Nn + col;
            if (HOUT) {
                __half* C = (__half*)Cv + (size_t)z * cB;
                *(__half2*)(C + o0) = __floats2half2_rn(vv[0], vv[1]);
                *(__half2*)(C + o1) = __floats2half2_rn(vv[2], vv[3]);
            } else {
                float* C = (float*)Cv + (size_t)z * cB;
                *(float2*)(C + o0) = make_float2(vv[0], vv[1]);
                *(float2*)(C + o1) = make_float2(vv[2], vv[3]);
            }
        }
    }
}

// ------- FP16 hi/lo split GEMM with split-K + atomic fp32 accumulation --------
// 3 products (hh + hl + lh) == fp32-exact class for routing decisions.
// LISTMODE 1: A rows are xh/xl rows indexed via list[]; 0: compact A rows.
// C: fp32 [RCAP, Nn], pre-zeroed; partials accumulated via atomicAdd.
template <int LISTMODE>
__global__ __launch_bounds__(256, 2)
void hsplit_splitk(const __half* __restrict__ Ah, const __half* __restrict__ Al,
                   const __half* __restrict__ Bh, const __half* __restrict__ Bl,
                   float* __restrict__ C,
                   const int* __restrict__ list, const int* __restrict__ cnt,
                   int Kd, int Nn)
{
    const int n = min(*cnt, RCAP);
    const int m0 = blockIdx.y * 128;
    if (m0 >= n) return;

    extern __shared__ __half smh[];
    constexpr int AHo = 0;
    constexpr int BHo = TILEH;
    constexpr int ALo = 2 * TILEH;
    constexpr int BLo = 3 * TILEH;
    constexpr int STG = 4 * TILEH;

    const int tid = threadIdx.x;
    const int n0 = blockIdx.x * 128;
    const int nk = Kd / (KSP * 32);
    const size_t kbase = (size_t)blockIdx.z * nk * 32;

    const int warp = tid >> 5;
    const int lane = tid & 31;
    const int wm = warp >> 2;
    const int wn = warp & 3;
    const int g4 = lane >> 2;
    const int t4 = lane & 3;

    const uint32_t smb = smem_u32(smh);

    const uint32_t fRow = (uint32_t)((lane & 7) + ((lane >> 3) & 1) * 8);
    const uint32_t fCol = (uint32_t)(lane >> 4) * 8;
    const uint32_t aFrag = ((wm * 64 + fRow) * RPH + fCol) * 2;
    const uint32_t bFrag = ((wn * 32 + fRow) * RPH + fCol) * 2;

    int lrow[2], lc[2], arow[2];
#pragma unroll
    for (int t = 0; t < 2; t++) {
        int id = tid + 256 * t;
        lrow[t] = id >> 2;
        lc[t] = (id & 3) * 8;
        int r = m0 + lrow[t];
        if (LISTMODE) arow[t] = list[(r < n) ? r : (n - 1)];
        else          arow[t] = r;
    }

    auto ISSUE = [&](int s) {
        const uint32_t sb = smb + (uint32_t)(s & 1) * STG * 2;
        const size_t ko = kbase + (size_t)s * 32;
#pragma unroll
        for (int t = 0; t < 2; t++) {
            const size_t goA = (size_t)arow[t] * Kd + ko + lc[t];
            const size_t goB = (size_t)(n0 + lrow[t]) * Kd + ko + lc[t];
            const uint32_t so = (uint32_t)(lrow[t] * RPH + lc[t]) * 2;
            cp16(sb + AHo * 2 + so, Ah + goA);
            cp16(sb + BHo * 2 + so, Bh + goB);
            cp16(sb + ALo * 2 + so, Al + goA);
            cp16(sb + BLo * 2 + so, Bl + goB);
        }
    };

    float d[4][4][4];
#pragma unroll
    for (int i = 0; i < 4; i++)
#pragma unroll
        for (int j = 0; j < 4; j++)
#pragma unroll
            for (int q = 0; q < 4; q++) d[i][j][q] = 0.f;

    ISSUE(0); cp_commit();

    for (int s = 0; s < nk; s++) {
        cp_wait<0>();
        __syncthreads();
        if (s + 1 < nk) ISSUE(s + 1);
        cp_commit();

        const uint32_t sb = smb + (uint32_t)(s & 1) * STG * 2;
#pragma unroll
        for (int kk = 0; kk < 2; kk++) {
            const uint32_t cOff = (uint32_t)kk * 32;
            uint32_t ah[4][4], al[4][4], bh[4][2], bl[4][2];
#pragma unroll
            for (int i = 0; i < 4; i++) {
                LDSM_X4(ah[i], sb + AHo * 2 + aFrag + (uint32_t)(i * 16 * RPH * 2) + cOff);
                LDSM_X4(al[i], sb + ALo * 2 + aFrag + (uint32_t)(i * 16 * RPH * 2) + cOff);
            }
#pragma unroll
            for (int j2 = 0; j2 < 2; j2++) {
                uint32_t t[4];
                LDSM_X4(t, sb + BHo * 2 + bFrag + (uint32_t)(j2 * 16 * RPH * 2) + cOff);
                bh[j2 * 2][0] = t[0]; bh[j2 * 2 + 1][0] = t[1];
                bh[j2 * 2][1] = t[2]; bh[j2 * 2 + 1][1] = t[3];
                LDSM_X4(t, sb + BLo * 2 + bFrag + (uint32_t)(j2 * 16 * RPH * 2) + cOff);
                bl[j2 * 2][0] = t[0]; bl[j2 * 2 + 1][0] = t[1];
                bl[j2 * 2][1] = t[2]; bl[j2 * 2 + 1][1] = t[3];
            }
#pragma unroll
            for (int i = 0; i < 4; i++)
#pragma unroll
                for (int j = 0; j < 4; j++) {
                    MMA_F16(d[i][j], ah[i], bh[j]);
                    MMA_F16(d[i][j], ah[i], bl[j]);
                    MMA_F16(d[i][j], al[i], bh[j]);
                }
        }
    }

    // epilogue: atomic accumulate partials (no bias/relu here)
#pragma unroll
    for (int i = 0; i < 4; i++) {
        int r0 = m0 + wm * 64 + i * 16 + g4;
#pragma unroll
        for (int j = 0; j < 4; j++) {
            int col = n0 + wn * 32 + j * 8 + t4 * 2;
            atomicAdd(&C[(size_t)r0 * Nn + col],       d[i][j][0]);
            atomicAdd(&C[(size_t)r0 * Nn + col + 1],   d[i][j][1]);
            atomicAdd(&C[(size_t)(r0 + 8) * Nn + col],     d[i][j][2]);
            atomicAdd(&C[(size_t)(r0 + 8) * Nn + col + 1], d[i][j][3]);
        }
    }
}

// ---- h1 fixup: bias + relu + fp16 hi/lo split (recheck rows only) -----------
__global__ __launch_bounds__(256) void h1fix_kernel(
    const float* __restrict__ src, const float* __restrict__ rb1,
    const int* __restrict__ cnt, __half* __restrict__ dh, __half* __restrict__ dl)
{
    const int i = blockIdx.x;
    if (i >= min(*cnt, RCAP)) return;
    for (int c = threadIdx.x * 4; c < HDIM; c += 1024) {
        float4 v = *(const float4*)(src + (size_t)i * HDIM + c);
        float4 b = *(const float4*)(rb1 + c);
        float r0 = fmaxf(v.x + b.x, 0.f);
        float r1 = fmaxf(v.y + b.y, 0.f);
        float r2 = fmaxf(v.z + b.z, 0.f);
        float r3 = fmaxf(v.w + b.w, 0.f);
        __half h0, l0, h1, l1, h2, l2, h3, l3;
        split16(r0, h0, l0); split16(r1, h1, l1);
        split16(r2, h2, l2); split16(r3, h3, l3);
        size_t o = (size_t)i * HDIM + c;
        *(__half2*)(dh + o)     = __halves2half2(h0, h1);
        *(__half2*)(dh + o + 2) = __halves2half2(h2, h3);
        *(__half2*)(dl + o)     = __halves2half2(l0, l1);
        *(__half2*)(dl + o + 2) = __halves2half2(l2, l3);
    }
}

// ---- zero fp32 buffer --------------------------------------------------------
__global__ void zero4_kernel(float4* __restrict__ p, int n4)
{
    int i = blockIdx.x * blockDim.x + threadIdx.x;
    if (i < n4) p[i] = make_float4(0.f, 0.f, 0.f, 0.f);
}

// -------- elementwise split: x -> (fp16 hi, fp16 lo); also resets cnt ---------
__global__ __launch_bounds__(256) void split_kernel(
    const float* __restrict__ src, __half* __restrict__ dh,
    __half* __restrict__ dl, int* __restrict__ cnt, int n4)
{
    int i = blockIdx.x * blockDim.x + threadIdx.x;
    if (i == 0) *cnt = 0;
    if (i >= n4) return;
    float4 v = ((const float4*)src)[i];
    __half h0, l0, h1, l1, h2, l2, h3, l3;
    split16(v.x, h0, l0); split16(v.y, h1, l1);
    split16(v.z, h2, l2); split16(v.w, h3, l3);
    ((__half2*)dh)[i * 2]     = __halves2half2(h0, h1);
    ((__half2*)dh)[i * 2 + 1] = __halves2half2(h2, h3);
    ((__half2*)dl)[i * 2]     = __halves2half2(l0, l1);
    ((__half2*)dl)[i * 2 + 1] = __halves2half2(l2, l3);
}

// ------ weight transpose. MODE 0: fp16 hi+lo; MODE 2: fp16 hi only -----------
template <int MODE>
__global__ __launch_bounds__(256) void transpose_kernel(
    const float* __restrict__ src, __half* __restrict__ dh,
    __half* __restrict__ dl, int R, int Cc)
{
    __shared__ float tile[32][33];
    size_t off = (size_t)blockIdx.z * R * Cc;
    int c0 = blockIdx.x * 32, r0 = blockIdx.y * 32;
    int tx = threadIdx.x, ty = threadIdx.y;
#pragma unroll
    for (int i = 0; i < 4; i++)
        tile[ty + i * 8][tx] = src[off + (size_t)(r0 + ty + i * 8) * Cc + c0 + tx];
    __syncthreads();
#pragma unroll
    for (int i = 0; i < 4; i++) {
        float v = tile[tx][ty + i * 8];
        size_t o = off + (size_t)(c0 + ty + i * 8) * R + r0 + tx;
        __half h = __float2half_rn(v);
        dh[o] = h;
        if (MODE == 0) dl[o] = __float2half_rn(v - __half2float(h));
    }
}

// ---------------- router head (fp16 h2): logits + softmax + top-2 + flag -----
__global__ __launch_bounds__(256) void router_topk_kernel(
    const __half* __restrict__ h2, const float* __restrict__ rw3,
    const float* __restrict__ rb3, int* __restrict__ eid,
    float* __restrict__ prob, int* __restrict__ list, int* __restrict__ cnt)
{
    __shared__ __align__(16) __half sh[HDIM];
    __shared__ float slog[EXPN];
    const int t = blockIdx.x;

    const uint4* src = (const uint4*)(h2 + (size_t)t * HDIM);
    uint4* dst4 = (uint4*)sh;
    for (int i = threadIdx.x; i < HDIM / 8; i += 256) dst4[i] = src[i];
    __syncthreads();

    const int w = threadIdx.x >> 5;
    const int lane = threadIdx.x & 31;
    if (w < EXPN) {
        float s = 0.f;
        for (int j = lane; j < HDIM; j += 32)
            s += __half2float(sh[j]) * rw3[(size_t)j * EXPN + w];
#pragma unroll
        for (int o = 16; o > 0; o >>= 1) s += __shfl_down_sync(0xffffffffu, s, o);
        if (lane == 0) slog[w] = s + rb3[w];
    }
    __syncthreads();

    if (threadIdx.x == 0) {
        float l[EXPN], p[EXPN];
        float mx = -1e30f;
#pragma unroll
        for (int e = 0; e < EXPN; e++) { l[e] = slog[e]; mx = fmaxf(mx, l[e]); }
        float se = 0.f;
#pragma unroll
        for (int e = 0; e < EXPN; e++) { p[e] = expf(l[e] - mx); se += p[e]; }
        float inv = 1.f / se;
#pragma unroll
        for (int e = 0; e < EXPN; e++) p[e] *= inv;
        int b1 = 0;
#pragma unroll
        for (int e = 1; e < EXPN; e++) if (l[e] > l[b1]) b1 = e;
        int b2 = (b1 == 0) ? 1 : 0;
#pragma unroll
        for (int e = 0; e < EXPN; e++)
            if (e != b1 && l[e] > l[b2]) b2 = e;
        int b3 = -1;
#pragma unroll
        for (int e = 0; e < EXPN; e++)
            if (e != b1 && e != b2 && (b3 < 0 || l[e] > l[b3])) b3 = e;
        eid[t * 2 + 0] = b1; prob[t * 2 + 0] = p[b1];
        eid[t * 2 + 1] = b2; prob[t * 2 + 1] = p[b2];
        if (l[b2] - l[b3] < MARGIN) {
            int idx = atomicAdd(cnt, 1);
            if (idx < RCAP) list[idx] = t;
        }
    }
}

// ------------- exact top-2 fix for marginal tokens (h2 = relu(acc + rb2)) -----
__global__ __launch_bounds__(256) void fix_topk_kernel(
    const float* __restrict__ grh2, const float* __restrict__ rb2,
    const float* __restrict__ rw3, const float* __restrict__ rb3,
    const int* __restrict__ list, const int* __restrict__ cnt,
    int* __restrict__ eid, float* __restrict__ prob)
{
    const int i = blockIdx.x;
    if (i >= min(*cnt, RCAP)) return;
    __shared__ __align__(16) float sh[HDIM];
    __shared__ float slog[EXPN];

    for (int k = threadIdx.x; k < HDIM / 4; k += 256) {
        float4 v = ((const float4*)(grh2 + (size_t)i * HDIM))[k];
        float4 b = ((const float4*)rb2)[k];
        float4 r;
        r.x = fmaxf(v.x + b.x, 0.f);
        r.y = fmaxf(v.y + b.y, 0.f);
        r.z = fmaxf(v.z + b.z, 0.f);
        r.w = fmaxf(v.w + b.w, 0.f);
        ((float4*)sh)[k] = r;
    }
    __syncthreads();

    const int w = threadIdx.x >> 5;
    const int lane = threadIdx.x & 31;
    if (w < EXPN) {
        float s = 0.f;
        for (int j = lane; j < HDIM; j += 32) s += sh[j] * rw3[(size_t)j * EXPN + w];
#pragma unroll
        for (int o = 16; o > 0; o >>= 1) s += __shfl_down_sync(0xffffffffu, s, o);
        if (lane == 0) slog[w] = s + rb3[w];
    }
    __syncthreads();

    if (threadIdx.x == 0) {
        const int t = list[i];
        float l[EXPN], p[EXPN];
        float mx = -1e30f;
#pragma unroll
        for (int e = 0; e < EXPN; e++) { l[e] = slog[e]; mx = fmaxf(mx, l[e]); }
        float se = 0.f;
#pragma unroll
        for (int e = 0; e < EXPN; e++) { p[e] = expf(l[e] - mx); se += p[e]; }
        float inv = 1.f / se;
#pragma unroll
        for (int e = 0; e < EXPN; e++) p[e] *= inv;
        int b1 = 0;
#pragma unroll
        for (int e = 1; e < EXPN; e++) if (l[e] > l[b1]) b1 = e;
        int b2 = (b1 == 0) ? 1 : 0;
#pragma unroll
        for (int e = 0; e < EXPN; e++)
            if (e != b1 && l[e] > l[b2]) b2 = e;
        eid[t * 2 + 0] = b1; prob[t * 2 + 0] = p[b1];
        eid[t * 2 + 1] = b2; prob[t * 2 + 1] = p[b2];
    }
}

// ---- exact flattened-order per-expert ranks ---------------------------------
__global__ __launch_bounds__(1024) void positions_kernel(
    const int* __restrict__ eid, int* __restrict__ pos)
{
    __shared__ int base[EXPN];
    __shared__ int wcnt[32][EXPN];
    const int tid = threadIdx.x;
    const int lane = tid & 31;
    const int w = tid >> 5;

    if (tid < EXPN) base[tid] = 0;
    __syncthreads();

    for (int c = 0; c < NFLAT; c += 1024) {
        if (tid < 32 * EXPN) ((int*)wcnt)[tid] = 0;
        __syncthreads();

        int e = eid[c + tid];
        unsigned m = __match_any_sync(0xffffffffu, e);
        int rank = __popc(m & ((1u << lane) - 1u));
        int leader = __ffs(m) - 1;
        if (lane == leader) wcnt[w][e] = __popc(m);
        __syncthreads();

        int off = base[e] + rank;
        for (int w2 = 0; w2 < 32; w2++)
            if (w2 < w) off += wcnt[w2][e];
        pos[c + tid] = off;
        __syncthreads();

        if (tid < EXPN) {
            int s = 0;
#pragma unroll
            for (int w2 = 0; w2 < 32; w2++) s += wcnt[w2][tid];
            base[tid] += s;
        }
        __syncthreads();
    }
}

// dispatch: scatter fp16(x) rows into expert buffers
__global__ __launch_bounds__(256) void dispatch_kernel(
    const __half* __restrict__ xh, const int* __restrict__ eid,
    const int* __restrict__ pos, __half* __restrict__ disp)
{
    const int i = blockIdx.x;
    const int p = pos[i];
    if (p >= CAPN) return;
    const int e = eid[i];
    const int token = i >> 1;
    uint2* dst = (uint2*)(disp + ((size_t)e * CAPN + p) * CDIM);
    dst[threadIdx.x] = ((const uint2*)(xh + (size_t)token * CDIM))[threadIdx.x];
}

// combine: weighted sum of two fp16 expert outputs -> fp32 out
__global__ __launch_bounds__(256) void combine_kernel(
    const __half* __restrict__ eo, const int* __restrict__ eid,
    const float* __restrict__ prob, const int* __restrict__ pos,
    float* __restrict__ out)
{
    const int t = blockIdx.x;
    const int e1 = eid[t * 2 + 0], e2 = eid[t * 2 + 1];
    const int p1 = pos[t * 2 + 0], p2 = pos[t * 2 + 1];
    const float w1 = prob[t * 2 + 0] * (p1 < CAPN ? 1.f : 0.f);
    const float w2 = prob[t * 2 + 1] * (p2 < CAPN ? 1.f : 0.f);
    const int g1 = min(p1, CAPN - 1), g2 = min(p2, CAPN - 1);

    const uint2* r1 = (const uint2*)(eo + ((size_t)e1 * CAPN + g1) * CDIM);
    const uint2* r2 = (const uint2*)(eo + ((size_t)e2 * CAPN + g2) * CDIM);
    uint2 a = r1[threadIdx.x];
    uint2 b = r2[threadIdx.x];
    float2 a0 = __half22float2(*(__half2*)&a.x);
    float2 a1 = __half22float2(*(__half2*)&a.y);
    float2 b0 = __half22float2(*(__half2*)&b.x);
    float2 b1 = __half22float2(*(__half2*)&b.y);
    float4 v;
    v.x = w1 * a0.x + w2 * b0.x;
    v.y = w1 * a0.y + w2 * b0.y;
    v.z = w1 * a1.x + w2 * b1.x;
    v.w = w1 * a1.y + w2 * b1.y;
    ((float4*)(out + (size_t)t * CDIM))[threadIdx.x] = v;
}

// ---------------- launch -----------------------------------------------------
extern "C" void kernel_launch(void* const* d_in, const int* in_sizes, int n_in,
                              void* d_out, int out_size)
{
    const float* x   = (const float*)d_in[0];
    const float* rw1 = (const float*)d_in[1];
    const float* rb1 = (const float*)d_in[2];
    const float* rw2 = (const float*)d_in[3];
    const float* rb2 = (const float*)d_in[4];
    const float* rw3 = (const float*)d_in[5];
    const float* rb3 = (const float*)d_in[6];
    const float* ew1 = (const float*)d_in[7];
    const float* eb1 = (const float*)d_in[8];
    const float* ew2 = (const float*)d_in[9];
    const float* eb2 = (const float*)d_in[10];
    float* out = (float*)d_out;
    (void)in_sizes; (void)n_in; (void)out_size;

    float *prob, *grh1f, *grh2;
    __half *xh16, *xl16, *h1hf, *h2h, *disph, *ehh, *eo16;
    __half *rw1h16, *rw1l16, *rw2h16, *rw2l16, *ew1hf, *ew2hf;
    __half *grh1h, *grh1l;
    int *eid, *pos, *list, *cnt;
    cudaGetSymbolAddress((void**)&xh16,   g_xh16);
    cudaGetSymbolAddress((void**)&xl16,   g_xl16);
    cudaGetSymbolAddress((void**)&h1hf,   g_h1hf);
    cudaGetSymbolAddress((void**)&h2h,    g_h2h);
    cudaGetSymbolAddress((void**)&disph,  g_disph);
    cudaGetSymbolAddress((void**)&ehh,    g_ehh);
    cudaGetSymbolAddress((void**)&eo16,   g_eo16);
    cudaGetSymbolAddress((void**)&eid,    g_eid);
    cudaGetSymbolAddress((void**)&prob,   g_prob);
    cudaGetSymbolAddress((void**)&pos,    g_pos);
    cudaGetSymbolAddress((void**)&rw1h16, g_rw1h16);
    cudaGetSymbolAddress((void**)&rw1l16, g_rw1l16);
    cudaGetSymbolAddress((void**)&rw2h16, g_rw2h16);
    cudaGetSymbolAddress((void**)&rw2l16, g_rw2l16);
    cudaGetSymbolAddress((void**)&ew1hf,  g_ew1hf);
    cudaGetSymbolAddress((void**)&ew2hf,  g_ew2hf);
    cudaGetSymbolAddress((void**)&grh1f,  g_grh1f);
    cudaGetSymbolAddress((void**)&grh1h,  g_grh1h);
    cudaGetSymbolAddress((void**)&grh1l,  g_grh1l);
    cudaGetSymbolAddress((void**)&grh2,   g_grh2);
    cudaGetSymbolAddress((void**)&list,   g_list);
    cudaGetSymbolAddress((void**)&cnt,    g_cnt);

    const int DSH = 2 * TILEH * 2 * 2;   // fp16 1x: 2 stages of (A,B)
    const int DSS = 4 * TILEH * 2 * 2;   // fp16 split: 2 stages of (AH,BH,AL,BL)
    cudaFuncSetAttribute((const void*)hmma_gemm<1,1>, cudaFuncAttributeMaxDynamicSharedMemorySize, DSH);
    cudaFuncSetAttribute((const void*)hmma_gemm<0,1>, cudaFuncAttributeMaxDynamicSharedMemorySize, DSH);
    cudaFuncSetAttribute((const void*)hsplit_splitk<1>, cudaFuncAttributeMaxDynamicSharedMemorySize, DSS);
    cudaFuncSetAttribute((const void*)hsplit_splitk<0>, cudaFuncAttributeMaxDynamicSharedMemorySize, DSS);

    // operand preparation (hi array == plain fp16 array, shared by fast path)
    split_kernel<<<(NTOK * CDIM / 4 + 255) / 256, 256>>>(x, xh16, xl16, cnt, NTOK * CDIM / 4);
    {
        int n4 = RCAP * HDIM / 4;
        zero4_kernel<<<(n4 + 255) / 256, 256>>>((float4*)grh1f, n4);
        zero4_kernel<<<(n4 + 255) / 256, 256>>>((float4*)grh2,  n4);
    }
    transpose_kernel<0><<<dim3(HDIM/32, CDIM/32, 1), dim3(32, 8)>>>(rw1, rw1h16, rw1l16, CDIM, HDIM);
    transpose_kernel<0><<<dim3(HDIM/32, HDIM/32, 1), dim3(32, 8)>>>(rw2, rw2h16, rw2l16, HDIM, HDIM);
    transpose_kernel<2><<<dim3(HDIM/32, CDIM/32, EXPN), dim3(32, 8)>>>(ew1, ew1hf, nullptr, CDIM, HDIM);
    transpose_kernel<2><<<dim3(CDIM/32, HDIM/32, EXPN), dim3(32, 8)>>>(ew2, ew2hf, nullptr, HDIM, CDIM);

    // router MLP in fp16 (decisions fixed below); h2 kept fp16
    hmma_gemm<1,1><<<dim3(HDIM/128, NTOK/128, 1), 256, DSH>>>(
        xh16, rw1h16, rb1, h1hf, CDIM, HDIM, 0, 0, 0, 0);
    hmma_gemm<1,1><<<dim3(HDIM/128, NTOK/128, 1), 256, DSH>>>(
        h1hf, rw2h16, rb2, h2h, HDIM, HDIM, 0, 0, 0, 0);

    router_topk_kernel<<<NTOK, 256>>>(h2h, rw3, rb3, eid, prob, list, cnt);

    // exact recheck of marginal tokens: fp16 hi/lo 3-product split, split-K
    hsplit_splitk<1><<<dim3(HDIM/128, RCAP/128, KSP), 256, DSS>>>(
        xh16, xl16, rw1h16, rw1l16, grh1f, list, cnt, CDIM, HDIM);
    h1fix_kernel<<<RCAP, 256>>>(grh1f, rb1, cnt, grh1h, grh1l);
    hsplit_splitk<0><<<dim3(HDIM/128, RCAP/128, KSP), 256, DSS>>>(
        grh1h, grh1l, rw2h16, rw2l16, grh2, nullptr, cnt, HDIM, HDIM);
    fix_topk_kernel<<<RCAP, 256>>>(grh2, rb2, rw3, rb3, list, cnt, eid, prob);

    positions_kernel<<<1, 1024>>>(eid, pos);
    dispatch_kernel<<<NFLAT, 256>>>(xh16, eid, pos, disph);

    // expert FFNs in fp16 (eo kept fp16)
    hmma_gemm<1,1><<<dim3(HDIM/128, CAPN/128, EXPN), 256, DSH>>>(
        disph, ew1hf, eb1, ehh, CDIM, HDIM,
        (long long)CAPN * CDIM, (long long)HDIM * CDIM, HDIM, (long long)CAPN * HDIM);
    hmma_gemm<0,1><<<dim3(CDIM/128, CAPN/128, EXPN), 256, DSH>>>(
        ehh, ew2hf, eb2, eo16, HDIM, CDIM,
        (long long)CAPN * HDIM, (long long)CDIM * HDIM, CDIM, (long long)CAPN * CDIM);

    // combine
    combine_kernel<<<NTOK, 256>>>(eo16, eid, prob, pos, out);
}